// round 5
// baseline (speedup 1.0000x reference)
#include <cuda_runtime.h>
#include <cuda_bf16.h>
#include <math.h>
#include <stdint.h>

// ---------------- problem constants ----------------
constexpr int B_ = 2, T_ = 1024, D_ = 768, H_ = 12, L_ = 4, E_ = 8, DFF_ = 3072, V_ = 32000;
constexpr int HEAD_ = D_ / H_;       // 64
constexpr int D3_ = 3 * D_;          // 2304
constexpr int M_ = B_ * T_;          // 2048 tokens

// ---------------- scratch (static device, allocation-free) ----------------
__device__ __align__(128) float g_x[(size_t)M_ * D_];
__device__ __align__(128) float g_h[(size_t)M_ * D_];
__device__ __align__(128) float g_attn[(size_t)M_ * D_];
__device__ __align__(128) float g_qkv[(size_t)M_ * D3_];
__device__ __align__(128) float g_scores[(size_t)B_ * H_ * T_ * T_];   // ~100 MB
__device__ __align__(128) float g_hid[(size_t)M_ * E_ * DFF_];         // ~201 MB
__device__ __align__(128) float g_mp[(size_t)M_ * E_];

// ---------------- packed f32x2 FMA (Blackwell FFMA2) ----------------
// Each lane is an independent IEEE fp32 fma -> per-element arithmetic is
// IDENTICAL to scalar fmaf; we only fuse two elements per instruction.
__device__ __forceinline__ float2 ffma2(float2 a, float2 b, float2 c) {
    unsigned long long au, bu, cu, du;
    au = *reinterpret_cast<unsigned long long*>(&a);
    bu = *reinterpret_cast<unsigned long long*>(&b);
    cu = *reinterpret_cast<unsigned long long*>(&c);
    asm("fma.rn.f32x2 %0, %1, %2, %3;" : "=l"(du) : "l"(au), "l"(bu), "l"(cu));
    return *reinterpret_cast<float2*>(&du);
}

// ---------------- reductions ----------------
__device__ __forceinline__ float bsum(float v, float* sred) {
#pragma unroll
    for (int o = 16; o; o >>= 1) v += __shfl_xor_sync(0xffffffffu, v, o);
    if ((threadIdx.x & 31) == 0) sred[threadIdx.x >> 5] = v;
    __syncthreads();
    float r = 0.f;
#pragma unroll
    for (int i = 0; i < 8; i++) r += sred[i];
    __syncthreads();
    return r;
}
__device__ __forceinline__ float bmax(float v, float* sred) {
#pragma unroll
    for (int o = 16; o; o >>= 1) v = fmaxf(v, __shfl_xor_sync(0xffffffffu, v, o));
    if ((threadIdx.x & 31) == 0) sred[threadIdx.x >> 5] = v;
    __syncthreads();
    float r = -3.402823e38f;
#pragma unroll
    for (int i = 0; i < 8; i++) r = fmaxf(r, sred[i]);
    __syncthreads();
    return r;
}

// ---------------- generic tiled GEMM (f32x2 FFMA2 core; bit-identical math to R1)
// C[m,n] (op)= epilogue( sum_k A[m*lda+k] * B(n,k) )
// BNT=true : B(n,k) = Bw[(k/KB)*expStride + n*ldb + (k%KB)]
// BNT=false: B(n,k) = Bw[k*ldb + n]
// MODE 0: C = alpha*acc   MODE 1: C = scale[m*E + n/DFF]*relu(acc)   MODE 2: C += acc
template <int MODE, bool BNT>
__global__ void __launch_bounds__(256)
gemm_tile(const float* __restrict__ A, const float* __restrict__ Bw,
          float* __restrict__ C, const float* __restrict__ scale,
          int M, int N, int K, int lda, int ldb, int ldc,
          long expStride, int KB, int ZH,
          long sAb, long sAh, long sBb, long sBh, long sCb, long sCh,
          float alpha, int causalSkip, int causalK)
{
    constexpr int BM = 128, BN = 128, BK = 16;
    if (ZH > 0) {
        int z = blockIdx.z;
        int zb = z / ZH, zh = z - zb * ZH;
        A  += zb * sAb + zh * sAh;
        Bw += zb * sBb + zh * sBh;
        C  += zb * sCb + zh * sCh;
    }
    const int n0 = blockIdx.x * BN;
    const int m0 = blockIdx.y * BM;
    if (causalSkip && n0 > m0) return;
    const int kend = causalK ? min(K, m0 + BM) : K;

    __shared__ float  As[BK][BM];
    __shared__ float2 Bs2[BK][BN];        // duplicated lanes {v,v}

    const int tid  = threadIdx.x;
    const int trow = (tid >> 4) << 3;     // m within tile
    const int tcol = (tid & 15) << 3;     // n within tile

    float2 acc2[4][8];                    // rows trow+2ip, trow+2ip+1 ; col tcol+j
#pragma unroll
    for (int ip = 0; ip < 4; ip++)
#pragma unroll
        for (int j = 0; j < 8; j++) acc2[ip][j] = make_float2(0.f, 0.f);

    for (int k0 = 0; k0 < kend; k0 += BK) {
        // ---- A tile (BMxBK), transpose into As[k][m]
#pragma unroll
        for (int it = 0; it < 2; it++) {
            int idx = tid + it * 256;
            int r = idx >> 2;
            int c4 = (idx & 3) << 2;
            float4 v = *(const float4*)(A + (long)(m0 + r) * lda + k0 + c4);
            As[c4 + 0][r] = v.x; As[c4 + 1][r] = v.y;
            As[c4 + 2][r] = v.z; As[c4 + 3][r] = v.w;
        }
        // ---- B tile (duplicated lanes)
        if (BNT) {
            int e = k0 / KB;
            const float* Bb = Bw + (long)e * expStride + (k0 - e * KB);
#pragma unroll
            for (int it = 0; it < 2; it++) {
                int idx = tid + it * 256;
                int r = idx >> 2;
                int c4 = (idx & 3) << 2;
                float4 v = make_float4(0.f, 0.f, 0.f, 0.f);
                if (n0 + r < N) v = *(const float4*)(Bb + (long)(n0 + r) * ldb + c4);
                Bs2[c4 + 0][r] = make_float2(v.x, v.x);
                Bs2[c4 + 1][r] = make_float2(v.y, v.y);
                Bs2[c4 + 2][r] = make_float2(v.z, v.z);
                Bs2[c4 + 3][r] = make_float2(v.w, v.w);
            }
        } else {
#pragma unroll
            for (int it = 0; it < 2; it++) {
                int idx = tid + it * 256;
                int r = idx >> 5;            // k
                int c4 = (idx & 31) << 2;    // n
                float4 v = make_float4(0.f, 0.f, 0.f, 0.f);
                if (n0 + c4 + 3 < N) v = *(const float4*)(Bw + (long)(k0 + r) * ldb + n0 + c4);
                Bs2[r][c4 + 0] = make_float2(v.x, v.x);
                Bs2[r][c4 + 1] = make_float2(v.y, v.y);
                Bs2[r][c4 + 2] = make_float2(v.z, v.z);
                Bs2[r][c4 + 3] = make_float2(v.w, v.w);
            }
        }
        __syncthreads();
#pragma unroll
        for (int kk = 0; kk < BK; kk++) {
            float2 a2[4], b2[8];
#pragma unroll
            for (int ip = 0; ip < 4; ip++) a2[ip] = *(const float2*)&As[kk][trow + 2 * ip];
#pragma unroll
            for (int j = 0; j < 8; j++) b2[j] = Bs2[kk][tcol + j];
#pragma unroll
            for (int ip = 0; ip < 4; ip++)
#pragma unroll
                for (int j = 0; j < 8; j++)
                    acc2[ip][j] = ffma2(a2[ip], b2[j], acc2[ip][j]);
        }
        __syncthreads();
    }

#pragma unroll
    for (int ip = 0; ip < 4; ip++) {
#pragma unroll
        for (int sub = 0; sub < 2; sub++) {
            int m = m0 + trow + 2 * ip + sub;
            if (m >= M) continue;
#pragma unroll
            for (int j = 0; j < 8; j++) {
                int n = n0 + tcol + j;
                if (n >= N) continue;
                long ci = (long)m * ldc + n;
                float v = sub ? acc2[ip][j].y : acc2[ip][j].x;
                if (MODE == 0)      C[ci] = alpha * v;
                else if (MODE == 1) C[ci] = scale[(long)m * E_ + (n / DFF_)] * fmaxf(v, 0.f);
                else                C[ci] += v;
            }
        }
    }
}

// ---------------- embedding + LN0 ----------------
__global__ void embed_ln_kernel(const int* __restrict__ tokens,
                                const float* __restrict__ wte, const float* __restrict__ wpe,
                                const float* __restrict__ g, const float* __restrict__ b,
                                float* __restrict__ y)
{
    __shared__ float sred[8];
    long row = blockIdx.x;                  // b*T + t
    int t = (int)(row % T_);
    int tok = tokens[row];
    const float* we = wte + (long)tok * D_;
    const float* pe = wpe + (long)t * D_;
    float* yr = y + row * D_;
    int tid = threadIdx.x;
    float v[3], s = 0.f;
#pragma unroll
    for (int i = 0; i < 3; i++) { int c = tid + i * 256; v[i] = we[c] + pe[c]; s += v[i]; }
    s = bsum(s, sred);
    float mu = s * (1.f / D_);
    float q = 0.f;
#pragma unroll
    for (int i = 0; i < 3; i++) { float d = v[i] - mu; q += d * d; }
    q = bsum(q, sred);
    float rstd = rsqrtf(q * (1.f / D_) + 1e-5f);
#pragma unroll
    for (int i = 0; i < 3; i++) { int c = tid + i * 256; yr[c] = (v[i] - mu) * rstd * g[c] + b[c]; }
}

// ---------------- LayerNorm ----------------
__global__ void ln_kernel(const float* __restrict__ x, float* __restrict__ y,
                          const float* __restrict__ g, const float* __restrict__ b)
{
    __shared__ float sred[8];
    long row = blockIdx.x;
    const float* xr = x + row * D_;
    float* yr = y + row * D_;
    int tid = threadIdx.x;
    float v[3], s = 0.f;
#pragma unroll
    for (int i = 0; i < 3; i++) { v[i] = xr[tid + i * 256]; s += v[i]; }
    s = bsum(s, sred);
    float mu = s * (1.f / D_);
    float q = 0.f;
#pragma unroll
    for (int i = 0; i < 3; i++) { float d = v[i] - mu; q += d * d; }
    q = bsum(q, sred);
    float rstd = rsqrtf(q * (1.f / D_) + 1e-5f);
#pragma unroll
    for (int i = 0; i < 3; i++) { int c = tid + i * 256; yr[c] = (v[i] - mu) * rstd * g[c] + b[c]; }
}

// ---------------- causal softmax (in place on scores rows) ----------------
__global__ void softmax_kernel(float* __restrict__ sc)
{
    __shared__ float sred[8];
    long row = blockIdx.x;                   // z*T + i
    int i = (int)(row & (T_ - 1));
    float* r = sc + row * (long)T_;
    int tid = threadIdx.x;
    int n = i + 1;
    float rv[4];
    float mx = -3.402823e38f;
#pragma unroll
    for (int p = 0; p < 4; p++) { int j = tid + p * 256; if (j < n) { rv[p] = r[j]; mx = fmaxf(mx, rv[p]); } }
    mx = bmax(mx, sred);
    float s = 0.f;
#pragma unroll
    for (int p = 0; p < 4; p++) { int j = tid + p * 256; if (j < n) { rv[p] = __expf(rv[p] - mx); s += rv[p]; } }
    s = bsum(s, sred);
    float inv = 1.f / s;
    int zend = ((i >> 7) + 1) << 7;          // zero only up to tile boundary (PV truncates K there)
#pragma unroll
    for (int p = 0; p < 4; p++) {
        int j = tid + p * 256;
        if (j < n) r[j] = rv[p] * inv;
        else if (j < zend) r[j] = 0.f;
    }
}

// ---------------- router: scores, softmax, top-2, renorm ----------------
__global__ void router_kernel(const float* __restrict__ h, const float* __restrict__ rw,
                              float* __restrict__ mp)
{
    __shared__ float sc[E_];
    long tok = blockIdx.x;
    int tid = threadIdx.x;
    int w = tid >> 5, lane = tid & 31;
    const float* hr = h + tok * D_;
    const float* we = rw + (long)w * D_;     // 8 warps -> 8 experts
    float s = 0.f;
    for (int k = lane; k < D_; k += 32) s += hr[k] * we[k];
#pragma unroll
    for (int o = 16; o; o >>= 1) s += __shfl_xor_sync(0xffffffffu, s, o);
    if (lane == 0) sc[w] = s;
    __syncthreads();
    if (tid == 0) {
        float mx = sc[0];
#pragma unroll
        for (int e = 1; e < E_; e++) mx = fmaxf(mx, sc[e]);
        float p[E_], sum = 0.f;
#pragma unroll
        for (int e = 0; e < E_; e++) { p[e] = __expf(sc[e] - mx); sum += p[e]; }
        int i1 = 0;
#pragma unroll
        for (int e = 1; e < E_; e++) if (sc[e] > sc[i1]) i1 = e;
        int i2 = -1;
#pragma unroll
        for (int e = 0; e < E_; e++) if (e != i1 && (i2 < 0 || sc[e] > sc[i2])) i2 = e;
        float p1 = p[i1] / sum, p2 = p[i2] / sum;
        float inv = 1.f / (p1 + p2 + 1e-8f);
#pragma unroll
        for (int e = 0; e < E_; e++) mp[tok * E_ + e] = 0.f;
        mp[tok * E_ + i1] = p1 * inv;
        mp[tok * E_ + i2] = p2 * inv;
    }
}

// ---------------- host side ----------------
static float* sym(const void* s) { void* p = nullptr; cudaGetSymbolAddress(&p, s); return (float*)p; }

template <int MODE>
static void gemm_nt(const float* A, const float* Bw, float* C, const float* scale,
                    int M, int N, int K, int lda, int ldb, int ldc,
                    long expStride, int KB, float alpha = 1.f)
{
    dim3 grid((N + 127) / 128, (M + 127) / 128, 1);
    gemm_tile<MODE, true><<<grid, 256>>>(A, Bw, C, scale, M, N, K, lda, ldb, ldc,
                                         expStride, KB, 0, 0, 0, 0, 0, 0, 0,
                                         alpha, 0, 0);
}

extern "C" void kernel_launch(void* const* d_in, const int* in_sizes, int n_in,
                              void* d_out, int out_size)
{
    const int*   tokens  = (const int*)d_in[0];
    const float* wte     = (const float*)d_in[1];
    const float* wpe     = (const float*)d_in[2];
    const float* n0g     = (const float*)d_in[3];
    const float* n0b     = (const float*)d_in[4];
    const float* n1g     = (const float*)d_in[5];
    const float* n1b     = (const float*)d_in[6];
    const float* n2g     = (const float*)d_in[7];
    const float* n2b     = (const float*)d_in[8];
    const float* qkvw    = (const float*)d_in[9];
    const float* projw   = (const float*)d_in[10];
    const float* routerw = (const float*)d_in[11];
    const float* fc1     = (const float*)d_in[12];
    const float* fc2     = (const float*)d_in[13];
    const float* lmw     = (const float*)d_in[14];
    float* out = (float*)d_out;

    float* x   = sym(g_x);
    float* h   = sym(g_h);
    float* at  = sym(g_attn);
    float* qkv = sym(g_qkv);
    float* scs = sym(g_scores);
    float* hid = sym(g_hid);
    float* mp  = sym(g_mp);

    // embed + LN0
    embed_ln_kernel<<<M_, 256>>>(tokens, wte, wpe, n0g, n0b, x);

    for (int l = 0; l < L_; l++) {
        // LN1
        ln_kernel<<<M_, 256>>>(x, h, n1g + l * D_, n1b + l * D_);
        // QKV
        gemm_nt<0>(h, qkvw + (long)l * D3_ * D_, qkv, nullptr,
                   M_, D3_, D_, D_, D_, D3_, 0, D_);
        // scores = (Q K^T) / 8, batched over z=b*H+h, causal tile-skip
        {
            dim3 grid(T_ / 128, T_ / 128, B_ * H_);
            gemm_tile<0, true><<<grid, 256>>>(
                qkv, qkv + D_, scs, nullptr,
                T_, T_, HEAD_, D3_, D3_, T_,
                0, HEAD_, H_,
                (long)T_ * D3_, HEAD_, (long)T_ * D3_, HEAD_,
                (long)H_ * T_ * T_, (long)T_ * T_,
                0.125f, 1, 0);
        }
        // causal softmax
        softmax_kernel<<<B_ * H_ * T_, 256>>>(scs);
        // PV: out[b,h,i,:] = P V  (K truncated at causal tile boundary)
        {
            dim3 grid(1, T_ / 128, B_ * H_);
            gemm_tile<0, false><<<grid, 256>>>(
                scs, qkv + 2 * D_, at, nullptr,
                T_, HEAD_, T_, T_, D3_, D_,
                0, T_, H_,
                (long)H_ * T_ * T_, (long)T_ * T_, (long)T_ * D3_, HEAD_,
                (long)T_ * D_, HEAD_,
                1.f, 0, 1);
        }
        // x += attn @ proj^T
        gemm_nt<2>(at, projw + (long)l * D_ * D_, x, nullptr,
                   M_, D_, D_, D_, D_, D_, 0, D_);
        // LN2
        ln_kernel<<<M_, 256>>>(x, h, n2g + l * D_, n2b + l * D_);
        // router -> mp[token, e]
        router_kernel<<<M_, 256>>>(h, routerw + (long)l * E_ * D_, mp);
        // fc1 (all experts fused, N = 8*3072), epilogue: mp * relu(.)
        gemm_nt<1>(h, fc1 + (long)l * E_ * DFF_ * D_, hid, mp,
                   M_, E_ * DFF_, D_, D_, D_, E_ * DFF_, 0, D_);
        // x += fc2 (all experts fused via expert-strided K)
        gemm_nt<2>(hid, fc2 + (long)l * E_ * D_ * DFF_, x, nullptr,
                   M_, D_, E_ * DFF_, E_ * DFF_, DFF_, D_,
                   (long)D_ * DFF_, DFF_);
    }
    // logits
    gemm_nt<0>(x, lmw, out, nullptr, M_, V_, D_, D_, D_, V_, 0, D_);
}

// round 6
// speedup vs baseline: 2.6004x; 2.6004x over previous
#include <cuda_runtime.h>
#include <cuda_bf16.h>
#include <math.h>
#include <stdint.h>

// ---------------- problem constants ----------------
constexpr int B_ = 2, T_ = 1024, D_ = 768, H_ = 12, L_ = 4, E_ = 8, DFF_ = 3072, V_ = 32000;
constexpr int HEAD_ = D_ / H_;       // 64
constexpr int D3_ = 3 * D_;          // 2304
constexpr int M_ = B_ * T_;          // 2048 tokens

// ---------------- scratch (static device, allocation-free) ----------------
__device__ __align__(128) float g_x[(size_t)M_ * D_];
__device__ __align__(128) float g_h[(size_t)M_ * D_];
__device__ __align__(128) float g_attn[(size_t)M_ * D_];
__device__ __align__(128) float g_qkv[(size_t)M_ * D3_];
__device__ __align__(128) float g_scores[(size_t)B_ * H_ * T_ * T_];   // ~100 MB
__device__ __align__(128) float g_hid[(size_t)M_ * E_ * DFF_];         // ~201 MB
__device__ __align__(128) float g_mp[(size_t)M_ * E_];

// ---------------- packed f32x2 FMA (Blackwell FFMA2) ----------------
// Each lane is an independent IEEE fp32 fma -> per-element arithmetic is
// IDENTICAL to scalar fmaf; we only fuse two independent elements (M-pairs)
// per instruction. Per-element k-accumulation order is unchanged, so the
// results are bit-identical to the scalar R1 kernel.
__device__ __forceinline__ float2 ffma2(float2 a, float2 b, float2 c) {
    unsigned long long au, bu, cu, du;
    au = *reinterpret_cast<unsigned long long*>(&a);
    bu = *reinterpret_cast<unsigned long long*>(&b);
    cu = *reinterpret_cast<unsigned long long*>(&c);
    asm("fma.rn.f32x2 %0, %1, %2, %3;" : "=l"(du) : "l"(au), "l"(bu), "l"(cu));
    return *reinterpret_cast<float2*>(&du);
}

// ---------------- reductions ----------------
__device__ __forceinline__ float bsum(float v, float* sred) {
#pragma unroll
    for (int o = 16; o; o >>= 1) v += __shfl_xor_sync(0xffffffffu, v, o);
    if ((threadIdx.x & 31) == 0) sred[threadIdx.x >> 5] = v;
    __syncthreads();
    float r = 0.f;
#pragma unroll
    for (int i = 0; i < 8; i++) r += sred[i];
    __syncthreads();
    return r;
}
__device__ __forceinline__ float bmax(float v, float* sred) {
#pragma unroll
    for (int o = 16; o; o >>= 1) v = fmaxf(v, __shfl_xor_sync(0xffffffffu, v, o));
    if ((threadIdx.x & 31) == 0) sred[threadIdx.x >> 5] = v;
    __syncthreads();
    float r = -3.402823e38f;
#pragma unroll
    for (int i = 0; i < 8; i++) r = fmaxf(r, sred[i]);
    __syncthreads();
    return r;
}

// ---------------- generic tiled GEMM (FFMA2 core; bit-identical math to R1)
// C[m,n] (op)= epilogue( sum_k A[m*lda+k] * B(n,k) )
// BNT=true : B(n,k) = Bw[(k/KB)*expStride + n*ldb + (k%KB)]
// BNT=false: B(n,k) = Bw[k*ldb + n]
// MODE 0: C = alpha*acc   MODE 1: C = scale[m*E + n/DFF]*relu(acc)   MODE 2: C += acc
template <int MODE, bool BNT>
__global__ void __launch_bounds__(256, 2)
gemm_tile(const float* __restrict__ A, const float* __restrict__ Bw,
          float* __restrict__ C, const float* __restrict__ scale,
          int M, int N, int K, int lda, int ldb, int ldc,
          long expStride, int KB, int ZH,
          long sAb, long sAh, long sBb, long sBh, long sCb, long sCh,
          float alpha, int causalSkip, int causalK)
{
    constexpr int BM = 128, BN = 128, BK = 16;
    if (ZH > 0) {
        int z = blockIdx.z;
        int zb = z / ZH, zh = z - zb * ZH;
        A  += zb * sAb + zh * sAh;
        Bw += zb * sBb + zh * sBh;
        C  += zb * sCb + zh * sCh;
    }
    const int n0 = blockIdx.x * BN;
    const int m0 = blockIdx.y * BM;
    if (causalSkip && n0 > m0) return;
    const int kend = causalK ? min(K, m0 + BM) : K;

    __shared__ float As[BK][BM];
    __shared__ float Bs[BK][BN];

    const int tid  = threadIdx.x;
    const int trow = (tid >> 4) << 3;     // m within tile
    const int tcol = (tid & 15) << 3;     // n within tile

    float2 acc2[4][8];                    // rows (trow+2ip, trow+2ip+1) ; col tcol+j
#pragma unroll
    for (int ip = 0; ip < 4; ip++)
#pragma unroll
        for (int j = 0; j < 8; j++) acc2[ip][j] = make_float2(0.f, 0.f);

    for (int k0 = 0; k0 < kend; k0 += BK) {
        // ---- A tile (BMxBK), transpose into As[k][m]
#pragma unroll
        for (int it = 0; it < 2; it++) {
            int idx = tid + it * 256;
            int r = idx >> 2;
            int c4 = (idx & 3) << 2;
            float4 v = *(const float4*)(A + (long)(m0 + r) * lda + k0 + c4);
            As[c4 + 0][r] = v.x; As[c4 + 1][r] = v.y;
            As[c4 + 2][r] = v.z; As[c4 + 3][r] = v.w;
        }
        // ---- B tile
        if (BNT) {
            int e = k0 / KB;
            const float* Bb = Bw + (long)e * expStride + (k0 - e * KB);
#pragma unroll
            for (int it = 0; it < 2; it++) {
                int idx = tid + it * 256;
                int r = idx >> 2;
                int c4 = (idx & 3) << 2;
                float4 v = make_float4(0.f, 0.f, 0.f, 0.f);
                if (n0 + r < N) v = *(const float4*)(Bb + (long)(n0 + r) * ldb + c4);
                Bs[c4 + 0][r] = v.x; Bs[c4 + 1][r] = v.y;
                Bs[c4 + 2][r] = v.z; Bs[c4 + 3][r] = v.w;
            }
        } else {
#pragma unroll
            for (int it = 0; it < 2; it++) {
                int idx = tid + it * 256;
                int r = idx >> 5;            // k
                int c4 = (idx & 31) << 2;    // n
                float4 v = make_float4(0.f, 0.f, 0.f, 0.f);
                if (n0 + c4 + 3 < N) v = *(const float4*)(Bw + (long)(k0 + r) * ldb + n0 + c4);
                *(float4*)&Bs[r][c4] = v;
            }
        }
        __syncthreads();
#pragma unroll
        for (int kk = 0; kk < BK; kk++) {
            float2 a2[4];
#pragma unroll
            for (int ip = 0; ip < 4; ip++) a2[ip] = *(const float2*)&As[kk][trow + 2 * ip];
            float4 b0 = *(const float4*)&Bs[kk][tcol];
            float4 b1 = *(const float4*)&Bs[kk][tcol + 4];
            float bs[8] = {b0.x, b0.y, b0.z, b0.w, b1.x, b1.y, b1.z, b1.w};
#pragma unroll
            for (int j = 0; j < 8; j++) {
                float2 bd = make_float2(bs[j], bs[j]);   // dup via ALU movs (off the fma pipe)
#pragma unroll
                for (int ip = 0; ip < 4; ip++)
                    acc2[ip][j] = ffma2(a2[ip], bd, acc2[ip][j]);
            }
        }
        __syncthreads();
    }

#pragma unroll
    for (int ip = 0; ip < 4; ip++) {
#pragma unroll
        for (int sub = 0; sub < 2; sub++) {
            int m = m0 + trow + 2 * ip + sub;
            if (m >= M) continue;
#pragma unroll
            for (int j = 0; j < 8; j++) {
                int n = n0 + tcol + j;
                if (n >= N) continue;
                long ci = (long)m * ldc + n;
                float v = sub ? acc2[ip][j].y : acc2[ip][j].x;
                if (MODE == 0)      C[ci] = alpha * v;
                else if (MODE == 1) C[ci] = scale[(long)m * E_ + (n / DFF_)] * fmaxf(v, 0.f);
                else                C[ci] += v;
            }
        }
    }
}

// ---------------- embedding + LN0 ----------------
__global__ void embed_ln_kernel(const int* __restrict__ tokens,
                                const float* __restrict__ wte, const float* __restrict__ wpe,
                                const float* __restrict__ g, const float* __restrict__ b,
                                float* __restrict__ y)
{
    __shared__ float sred[8];
    long row = blockIdx.x;                  // b*T + t
    int t = (int)(row % T_);
    int tok = tokens[row];
    const float* we = wte + (long)tok * D_;
    const float* pe = wpe + (long)t * D_;
    float* yr = y + row * D_;
    int tid = threadIdx.x;
    float v[3], s = 0.f;
#pragma unroll
    for (int i = 0; i < 3; i++) { int c = tid + i * 256; v[i] = we[c] + pe[c]; s += v[i]; }
    s = bsum(s, sred);
    float mu = s * (1.f / D_);
    float q = 0.f;
#pragma unroll
    for (int i = 0; i < 3; i++) { float d = v[i] - mu; q += d * d; }
    q = bsum(q, sred);
    float rstd = rsqrtf(q * (1.f / D_) + 1e-5f);
#pragma unroll
    for (int i = 0; i < 3; i++) { int c = tid + i * 256; yr[c] = (v[i] - mu) * rstd * g[c] + b[c]; }
}

// ---------------- LayerNorm ----------------
__global__ void ln_kernel(const float* __restrict__ x, float* __restrict__ y,
                          const float* __restrict__ g, const float* __restrict__ b)
{
    __shared__ float sred[8];
    long row = blockIdx.x;
    const float* xr = x + row * D_;
    float* yr = y + row * D_;
    int tid = threadIdx.x;
    float v[3], s = 0.f;
#pragma unroll
    for (int i = 0; i < 3; i++) { v[i] = xr[tid + i * 256]; s += v[i]; }
    s = bsum(s, sred);
    float mu = s * (1.f / D_);
    float q = 0.f;
#pragma unroll
    for (int i = 0; i < 3; i++) { float d = v[i] - mu; q += d * d; }
    q = bsum(q, sred);
    float rstd = rsqrtf(q * (1.f / D_) + 1e-5f);
#pragma unroll
    for (int i = 0; i < 3; i++) { int c = tid + i * 256; yr[c] = (v[i] - mu) * rstd * g[c] + b[c]; }
}

// ---------------- causal softmax (in place on scores rows) ----------------
__global__ void softmax_kernel(float* __restrict__ sc)
{
    __shared__ float sred[8];
    long row = blockIdx.x;                   // z*T + i
    int i = (int)(row & (T_ - 1));
    float* r = sc + row * (long)T_;
    int tid = threadIdx.x;
    int n = i + 1;
    float rv[4];
    float mx = -3.402823e38f;
#pragma unroll
    for (int p = 0; p < 4; p++) { int j = tid + p * 256; if (j < n) { rv[p] = r[j]; mx = fmaxf(mx, rv[p]); } }
    mx = bmax(mx, sred);
    float s = 0.f;
#pragma unroll
    for (int p = 0; p < 4; p++) { int j = tid + p * 256; if (j < n) { rv[p] = __expf(rv[p] - mx); s += rv[p]; } }
    s = bsum(s, sred);
    float inv = 1.f / s;
    int zend = ((i >> 7) + 1) << 7;          // zero only up to tile boundary (PV truncates K there)
#pragma unroll
    for (int p = 0; p < 4; p++) {
        int j = tid + p * 256;
        if (j < n) r[j] = rv[p] * inv;
        else if (j < zend) r[j] = 0.f;
    }
}

// ---------------- router: scores, softmax, top-2, renorm ----------------
__global__ void router_kernel(const float* __restrict__ h, const float* __restrict__ rw,
                              float* __restrict__ mp)
{
    __shared__ float sc[E_];
    long tok = blockIdx.x;
    int tid = threadIdx.x;
    int w = tid >> 5, lane = tid & 31;
    const float* hr = h + tok * D_;
    const float* we = rw + (long)w * D_;     // 8 warps -> 8 experts
    float s = 0.f;
    for (int k = lane; k < D_; k += 32) s += hr[k] * we[k];
#pragma unroll
    for (int o = 16; o; o >>= 1) s += __shfl_xor_sync(0xffffffffu, s, o);
    if (lane == 0) sc[w] = s;
    __syncthreads();
    if (tid == 0) {
        float mx = sc[0];
#pragma unroll
        for (int e = 1; e < E_; e++) mx = fmaxf(mx, sc[e]);
        float p[E_], sum = 0.f;
#pragma unroll
        for (int e = 0; e < E_; e++) { p[e] = __expf(sc[e] - mx); sum += p[e]; }
        int i1 = 0;
#pragma unroll
        for (int e = 1; e < E_; e++) if (sc[e] > sc[i1]) i1 = e;
        int i2 = -1;
#pragma unroll
        for (int e = 0; e < E_; e++) if (e != i1 && (i2 < 0 || sc[e] > sc[i2])) i2 = e;
        float p1 = p[i1] / sum, p2 = p[i2] / sum;
        float inv = 1.f / (p1 + p2 + 1e-8f);
#pragma unroll
        for (int e = 0; e < E_; e++) mp[tok * E_ + e] = 0.f;
        mp[tok * E_ + i1] = p1 * inv;
        mp[tok * E_ + i2] = p2 * inv;
    }
}

// ---------------- host side ----------------
static float* sym(const void* s) { void* p = nullptr; cudaGetSymbolAddress(&p, s); return (float*)p; }

template <int MODE>
static void gemm_nt(const float* A, const float* Bw, float* C, const float* scale,
                    int M, int N, int K, int lda, int ldb, int ldc,
                    long expStride, int KB, float alpha = 1.f)
{
    dim3 grid((N + 127) / 128, (M + 127) / 128, 1);
    gemm_tile<MODE, true><<<grid, 256>>>(A, Bw, C, scale, M, N, K, lda, ldb, ldc,
                                         expStride, KB, 0, 0, 0, 0, 0, 0, 0,
                                         alpha, 0, 0);
}

extern "C" void kernel_launch(void* const* d_in, const int* in_sizes, int n_in,
                              void* d_out, int out_size)
{
    const int*   tokens  = (const int*)d_in[0];
    const float* wte     = (const float*)d_in[1];
    const float* wpe     = (const float*)d_in[2];
    const float* n0g     = (const float*)d_in[3];
    const float* n0b     = (const float*)d_in[4];
    const float* n1g     = (const float*)d_in[5];
    const float* n1b     = (const float*)d_in[6];
    const float* n2g     = (const float*)d_in[7];
    const float* n2b     = (const float*)d_in[8];
    const float* qkvw    = (const float*)d_in[9];
    const float* projw   = (const float*)d_in[10];
    const float* routerw = (const float*)d_in[11];
    const float* fc1     = (const float*)d_in[12];
    const float* fc2     = (const float*)d_in[13];
    const float* lmw     = (const float*)d_in[14];
    float* out = (float*)d_out;

    float* x   = sym(g_x);
    float* h   = sym(g_h);
    float* at  = sym(g_attn);
    float* qkv = sym(g_qkv);
    float* scs = sym(g_scores);
    float* hid = sym(g_hid);
    float* mp  = sym(g_mp);

    // embed + LN0
    embed_ln_kernel<<<M_, 256>>>(tokens, wte, wpe, n0g, n0b, x);

    for (int l = 0; l < L_; l++) {
        // LN1
        ln_kernel<<<M_, 256>>>(x, h, n1g + l * D_, n1b + l * D_);
        // QKV
        gemm_nt<0>(h, qkvw + (long)l * D3_ * D_, qkv, nullptr,
                   M_, D3_, D_, D_, D_, D3_, 0, D_);
        // scores = (Q K^T) / 8, batched over z=b*H+h, causal tile-skip
        {
            dim3 grid(T_ / 128, T_ / 128, B_ * H_);
            gemm_tile<0, true><<<grid, 256>>>(
                qkv, qkv + D_, scs, nullptr,
                T_, T_, HEAD_, D3_, D3_, T_,
                0, HEAD_, H_,
                (long)T_ * D3_, HEAD_, (long)T_ * D3_, HEAD_,
                (long)H_ * T_ * T_, (long)T_ * T_,
                0.125f, 1, 0);
        }
        // causal softmax
        softmax_kernel<<<B_ * H_ * T_, 256>>>(scs);
        // PV: out[b,h,i,:] = P V  (K truncated at causal tile boundary)
        {
            dim3 grid(1, T_ / 128, B_ * H_);
            gemm_tile<0, false><<<grid, 256>>>(
                scs, qkv + 2 * D_, at, nullptr,
                T_, HEAD_, T_, T_, D3_, D_,
                0, T_, H_,
                (long)H_ * T_ * T_, (long)T_ * T_, (long)T_ * D3_, HEAD_,
                (long)T_ * D_, HEAD_,
                1.f, 0, 1);
        }
        // x += attn @ proj^T
        gemm_nt<2>(at, projw + (long)l * D_ * D_, x, nullptr,
                   M_, D_, D_, D_, D_, D_, 0, D_);
        // LN2
        ln_kernel<<<M_, 256>>>(x, h, n2g + l * D_, n2b + l * D_);
        // router -> mp[token, e]
        router_kernel<<<M_, 256>>>(h, routerw + (long)l * E_ * D_, mp);
        // fc1 (all experts fused, N = 8*3072), epilogue: mp * relu(.)
        gemm_nt<1>(h, fc1 + (long)l * E_ * DFF_ * D_, hid, mp,
                   M_, E_ * DFF_, D_, D_, D_, E_ * DFF_, 0, D_);
        // x += fc2 (all experts fused via expert-strided K)
        gemm_nt<2>(hid, fc2 + (long)l * E_ * D_ * DFF_, x, nullptr,
                   M_, D_, E_ * DFF_, E_ * DFF_, DFF_, D_,
                   (long)D_ * DFF_, DFF_);
    }
    // logits
    gemm_nt<0>(x, lmw, out, nullptr, M_, V_, D_, D_, D_, V_, 0, D_);
}

// round 7
// speedup vs baseline: 4.5960x; 1.7674x over previous
#include <cuda_runtime.h>
#include <cuda_bf16.h>
#include <math.h>
#include <stdint.h>

// ---------------- problem constants ----------------
constexpr int B_ = 2, T_ = 1024, D_ = 768, H_ = 12, L_ = 4, E_ = 8, DFF_ = 3072, V_ = 32000;
constexpr int HEAD_ = D_ / H_;       // 64
constexpr int D3_ = 3 * D_;          // 2304
constexpr int M_ = B_ * T_;          // 2048 tokens
constexpr int NPAIR = 28;            // C(8,2)
constexpr int D2FF = 2 * DFF_;       // 6144

// ---------------- scratch (static device, allocation-free) ----------------
__device__ __align__(128) float g_x[(size_t)M_ * D_];
__device__ __align__(128) float g_h[(size_t)M_ * D_];
__device__ __align__(128) float g_attn[(size_t)M_ * D_];
__device__ __align__(128) float g_qkv[(size_t)M_ * D3_];
__device__ __align__(128) float g_scores[(size_t)B_ * H_ * T_ * T_];   // ~100 MB
__device__ __align__(128) float g_hidc[(size_t)M_ * D2FF];             // compact [rows, 6144]
__device__ __align__(128) float g_mp[(size_t)M_ * E_];
__device__ int g_cnt[NPAIR], g_baseo[NPAIR], g_pos[NPAIR];
__device__ int g_pairid[M_], g_idx[M_];

// pair tables: p -> (e1 < e2)
__constant__ int c_pe1[NPAIR] = {0,0,0,0,0,0,0, 1,1,1,1,1,1, 2,2,2,2,2, 3,3,3,3, 4,4,4, 5,5, 6};
__constant__ int c_pe2[NPAIR] = {1,2,3,4,5,6,7, 2,3,4,5,6,7, 3,4,5,6,7, 4,5,6,7, 5,6,7, 6,7, 7};

// ---------------- packed f32x2 FMA ----------------
// Each lane is an independent IEEE fp32 fma -> per-element arithmetic identical
// to scalar fmaf; results bit-identical to the scalar kernel.
__device__ __forceinline__ float2 ffma2(float2 a, float2 b, float2 c) {
    unsigned long long au, bu, cu, du;
    au = *reinterpret_cast<unsigned long long*>(&a);
    bu = *reinterpret_cast<unsigned long long*>(&b);
    cu = *reinterpret_cast<unsigned long long*>(&c);
    asm("fma.rn.f32x2 %0, %1, %2, %3;" : "=l"(du) : "l"(au), "l"(bu), "l"(cu));
    return *reinterpret_cast<float2*>(&du);
}

// ---------------- reductions ----------------
__device__ __forceinline__ float bsum(float v, float* sred) {
#pragma unroll
    for (int o = 16; o; o >>= 1) v += __shfl_xor_sync(0xffffffffu, v, o);
    if ((threadIdx.x & 31) == 0) sred[threadIdx.x >> 5] = v;
    __syncthreads();
    float r = 0.f;
#pragma unroll
    for (int i = 0; i < 8; i++) r += sred[i];
    __syncthreads();
    return r;
}
__device__ __forceinline__ float bmax(float v, float* sred) {
#pragma unroll
    for (int o = 16; o; o >>= 1) v = fmaxf(v, __shfl_xor_sync(0xffffffffu, v, o));
    if ((threadIdx.x & 31) == 0) sred[threadIdx.x >> 5] = v;
    __syncthreads();
    float r = -3.402823e38f;
#pragma unroll
    for (int i = 0; i < 8; i++) r = fmaxf(r, sred[i]);
    __syncthreads();
    return r;
}

// ---------------- inner-product macro body (FFMA2) ----------------
#define GEMM_ACC_DECL                                   \
    float2 acc2[4][8];                                  \
    _Pragma("unroll")                                   \
    for (int ip = 0; ip < 4; ip++)                      \
        _Pragma("unroll")                               \
        for (int j = 0; j < 8; j++) acc2[ip][j] = make_float2(0.f, 0.f);

#define GEMM_INNER(As, Bs, trow, tcol)                                        \
    _Pragma("unroll")                                                          \
    for (int kk = 0; kk < 16; kk++) {                                          \
        float2 a2[4];                                                          \
        _Pragma("unroll")                                                      \
        for (int ip = 0; ip < 4; ip++) a2[ip] = *(const float2*)&As[kk][(trow) + 2 * ip]; \
        float4 b0 = *(const float4*)&Bs[kk][(tcol)];                           \
        float4 b1 = *(const float4*)&Bs[kk][(tcol) + 4];                       \
        float bsv[8] = {b0.x, b0.y, b0.z, b0.w, b1.x, b1.y, b1.z, b1.w};       \
        _Pragma("unroll")                                                      \
        for (int j = 0; j < 8; j++) {                                          \
            float2 bd = make_float2(bsv[j], bsv[j]);                           \
            _Pragma("unroll")                                                  \
            for (int ip = 0; ip < 4; ip++)                                     \
                acc2[ip][j] = ffma2(a2[ip], bd, acc2[ip][j]);                  \
        }                                                                      \
    }

// ---------------- generic tiled GEMM (dense; FFMA2 core) ----------------
// MODE 0: C = alpha*acc     MODE 2: C += acc
template <int MODE, bool BNT>
__global__ void __launch_bounds__(256, 2)
gemm_tile(const float* __restrict__ A, const float* __restrict__ Bw,
          float* __restrict__ C, const float* __restrict__ scale,
          int M, int N, int K, int lda, int ldb, int ldc,
          long expStride, int KB, int ZH,
          long sAb, long sAh, long sBb, long sBh, long sCb, long sCh,
          float alpha, int causalSkip, int causalK)
{
    constexpr int BM = 128, BN = 128, BK = 16;
    if (ZH > 0) {
        int z = blockIdx.z;
        int zb = z / ZH, zh = z - zb * ZH;
        A  += zb * sAb + zh * sAh;
        Bw += zb * sBb + zh * sBh;
        C  += zb * sCb + zh * sCh;
    }
    const int n0 = blockIdx.x * BN;
    const int m0 = blockIdx.y * BM;
    if (causalSkip && n0 > m0) return;
    const int kend = causalK ? min(K, m0 + BM) : K;

    __shared__ float As[BK][BM];
    __shared__ float Bs[BK][BN];

    const int tid  = threadIdx.x;
    const int trow = (tid >> 4) << 3;
    const int tcol = (tid & 15) << 3;

    GEMM_ACC_DECL

    for (int k0 = 0; k0 < kend; k0 += BK) {
#pragma unroll
        for (int it = 0; it < 2; it++) {
            int idx = tid + it * 256;
            int r = idx >> 2;
            int c4 = (idx & 3) << 2;
            float4 v = *(const float4*)(A + (long)(m0 + r) * lda + k0 + c4);
            As[c4 + 0][r] = v.x; As[c4 + 1][r] = v.y;
            As[c4 + 2][r] = v.z; As[c4 + 3][r] = v.w;
        }
        if (BNT) {
            int e = k0 / KB;
            const float* Bb = Bw + (long)e * expStride + (k0 - e * KB);
#pragma unroll
            for (int it = 0; it < 2; it++) {
                int idx = tid + it * 256;
                int r = idx >> 2;
                int c4 = (idx & 3) << 2;
                float4 v = make_float4(0.f, 0.f, 0.f, 0.f);
                if (n0 + r < N) v = *(const float4*)(Bb + (long)(n0 + r) * ldb + c4);
                Bs[c4 + 0][r] = v.x; Bs[c4 + 1][r] = v.y;
                Bs[c4 + 2][r] = v.z; Bs[c4 + 3][r] = v.w;
            }
        } else {
#pragma unroll
            for (int it = 0; it < 2; it++) {
                int idx = tid + it * 256;
                int r = idx >> 5;
                int c4 = (idx & 31) << 2;
                float4 v = make_float4(0.f, 0.f, 0.f, 0.f);
                if (n0 + c4 + 3 < N) v = *(const float4*)(Bw + (long)(k0 + r) * ldb + n0 + c4);
                *(float4*)&Bs[r][c4] = v;
            }
        }
        __syncthreads();
        GEMM_INNER(As, Bs, trow, tcol)
        __syncthreads();
    }

#pragma unroll
    for (int ip = 0; ip < 4; ip++) {
#pragma unroll
        for (int sub = 0; sub < 2; sub++) {
            int m = m0 + trow + 2 * ip + sub;
            if (m >= M) continue;
#pragma unroll
            for (int j = 0; j < 8; j++) {
                int n = n0 + tcol + j;
                if (n >= N) continue;
                long ci = (long)m * ldc + n;
                float v = sub ? acc2[ip][j].y : acc2[ip][j].x;
                if (MODE == 0)      C[ci] = alpha * v;
                else                C[ci] += v;
            }
        }
    }
}

// ---------------- grouped fc1: hidc[bg+m, 0:3072|3072:6144] = mp*relu(h[tok] @ W_e^T)
__global__ void __launch_bounds__(256, 2)
fc1_group(const float* __restrict__ h, const float* __restrict__ w1,
          float* __restrict__ hidc, const float* __restrict__ mp,
          const int* __restrict__ idxv, const int* __restrict__ baseo,
          const int* __restrict__ cnt)
{
    const int g  = blockIdx.z;
    const int cg = cnt[g];
    const int m0 = blockIdx.y * 128;
    if (m0 >= cg) return;
    const int bg = baseo[g];
    const int n0 = blockIdx.x * 128;                 // 0..6143
    const int e  = (n0 < DFF_) ? c_pe1[g] : c_pe2[g];
    const int nw = n0 - (n0 < DFF_ ? 0 : DFF_);      // col base within expert
    const float* Bw = w1 + (size_t)e * DFF_ * D_;    // [DFF, D] row-major

    __shared__ float As[16][128];
    __shared__ float Bs[16][128];
    __shared__ int   sidx[128];

    const int tid = threadIdx.x;
    if (tid < 128) {
        int rr = m0 + tid; if (rr >= cg) rr = cg - 1;
        sidx[tid] = idxv[bg + rr];
    }
    __syncthreads();

    const int trow = (tid >> 4) << 3;
    const int tcol = (tid & 15) << 3;

    GEMM_ACC_DECL

    for (int k0 = 0; k0 < D_; k0 += 16) {
#pragma unroll
        for (int it = 0; it < 2; it++) {
            int idx = tid + it * 256;
            int r = idx >> 2;
            int c4 = (idx & 3) << 2;
            float4 v = *(const float4*)(h + (size_t)sidx[r] * D_ + k0 + c4);
            As[c4 + 0][r] = v.x; As[c4 + 1][r] = v.y;
            As[c4 + 2][r] = v.z; As[c4 + 3][r] = v.w;
        }
#pragma unroll
        for (int it = 0; it < 2; it++) {
            int idx = tid + it * 256;
            int r = idx >> 2;
            int c4 = (idx & 3) << 2;
            float4 v = *(const float4*)(Bw + (size_t)(nw + r) * D_ + k0 + c4);
            Bs[c4 + 0][r] = v.x; Bs[c4 + 1][r] = v.y;
            Bs[c4 + 2][r] = v.z; Bs[c4 + 3][r] = v.w;
        }
        __syncthreads();
        GEMM_INNER(As, Bs, trow, tcol)
        __syncthreads();
    }

#pragma unroll
    for (int ip = 0; ip < 4; ip++) {
#pragma unroll
        for (int sub = 0; sub < 2; sub++) {
            int ml = trow + 2 * ip + sub;
            int mg = m0 + ml;
            if (mg >= cg) continue;
            int tok = sidx[ml];
            float sc = mp[(size_t)tok * E_ + e];
#pragma unroll
            for (int j = 0; j < 8; j++) {
                float v = sub ? acc2[ip][j].y : acc2[ip][j].x;
                hidc[(size_t)(bg + mg) * D2FF + n0 + tcol + j] = sc * fmaxf(v, 0.f);
            }
        }
    }
}

// ---------------- grouped fc2: x[tok] += hidc_row @ [W_e1 ; W_e2]^T  (K=6144)
__global__ void __launch_bounds__(256, 2)
fc2_group(const float* __restrict__ hidc, const float* __restrict__ w2,
          float* __restrict__ x, const int* __restrict__ idxv,
          const int* __restrict__ baseo, const int* __restrict__ cnt)
{
    const int g  = blockIdx.z;
    const int cg = cnt[g];
    const int m0 = blockIdx.y * 128;
    if (m0 >= cg) return;
    const int bg = baseo[g];
    const int n0 = blockIdx.x * 128;                 // 0..767
    const int e1 = c_pe1[g], e2 = c_pe2[g];

    __shared__ float As[16][128];
    __shared__ float Bs[16][128];
    __shared__ int   sidx[128];

    const int tid = threadIdx.x;
    if (tid < 128) {
        int rr = m0 + tid; if (rr >= cg) rr = cg - 1;
        sidx[tid] = idxv[bg + rr];
    }
    __syncthreads();

    const int trow = (tid >> 4) << 3;
    const int tcol = (tid & 15) << 3;

    GEMM_ACC_DECL

    for (int k0 = 0; k0 < D2FF; k0 += 16) {
        int eb = k0 / DFF_;
        const float* Bw = w2 + (size_t)(eb ? e2 : e1) * D_ * DFF_ + (k0 - eb * DFF_);
#pragma unroll
        for (int it = 0; it < 2; it++) {
            int idx = tid + it * 256;
            int r = idx >> 2;
            int c4 = (idx & 3) << 2;
            int rr = m0 + r; if (rr >= cg) rr = cg - 1;
            float4 v = *(const float4*)(hidc + (size_t)(bg + rr) * D2FF + k0 + c4);
            As[c4 + 0][r] = v.x; As[c4 + 1][r] = v.y;
            As[c4 + 2][r] = v.z; As[c4 + 3][r] = v.w;
        }
#pragma unroll
        for (int it = 0; it < 2; it++) {
            int idx = tid + it * 256;
            int r = idx >> 2;
            int c4 = (idx & 3) << 2;
            float4 v = *(const float4*)(Bw + (size_t)(n0 + r) * DFF_ + c4);
            Bs[c4 + 0][r] = v.x; Bs[c4 + 1][r] = v.y;
            Bs[c4 + 2][r] = v.z; Bs[c4 + 3][r] = v.w;
        }
        __syncthreads();
        GEMM_INNER(As, Bs, trow, tcol)
        __syncthreads();
    }

#pragma unroll
    for (int ip = 0; ip < 4; ip++) {
#pragma unroll
        for (int sub = 0; sub < 2; sub++) {
            int ml = trow + 2 * ip + sub;
            int mg = m0 + ml;
            if (mg >= cg) continue;
            int tok = sidx[ml];
#pragma unroll
            for (int j = 0; j < 8; j++) {
                float v = sub ? acc2[ip][j].y : acc2[ip][j].x;
                x[(size_t)tok * D_ + n0 + tcol + j] += v;
            }
        }
    }
}

// ---------------- embedding + LN0 ----------------
__global__ void embed_ln_kernel(const int* __restrict__ tokens,
                                const float* __restrict__ wte, const float* __restrict__ wpe,
                                const float* __restrict__ g, const float* __restrict__ b,
                                float* __restrict__ y)
{
    __shared__ float sred[8];
    long row = blockIdx.x;
    int t = (int)(row % T_);
    int tok = tokens[row];
    const float* we = wte + (long)tok * D_;
    const float* pe = wpe + (long)t * D_;
    float* yr = y + row * D_;
    int tid = threadIdx.x;
    float v[3], s = 0.f;
#pragma unroll
    for (int i = 0; i < 3; i++) { int c = tid + i * 256; v[i] = we[c] + pe[c]; s += v[i]; }
    s = bsum(s, sred);
    float mu = s * (1.f / D_);
    float q = 0.f;
#pragma unroll
    for (int i = 0; i < 3; i++) { float d = v[i] - mu; q += d * d; }
    q = bsum(q, sred);
    float rstd = rsqrtf(q * (1.f / D_) + 1e-5f);
#pragma unroll
    for (int i = 0; i < 3; i++) { int c = tid + i * 256; yr[c] = (v[i] - mu) * rstd * g[c] + b[c]; }
}

// ---------------- LayerNorm ----------------
__global__ void ln_kernel(const float* __restrict__ x, float* __restrict__ y,
                          const float* __restrict__ g, const float* __restrict__ b)
{
    __shared__ float sred[8];
    long row = blockIdx.x;
    const float* xr = x + row * D_;
    float* yr = y + row * D_;
    int tid = threadIdx.x;
    float v[3], s = 0.f;
#pragma unroll
    for (int i = 0; i < 3; i++) { v[i] = xr[tid + i * 256]; s += v[i]; }
    s = bsum(s, sred);
    float mu = s * (1.f / D_);
    float q = 0.f;
#pragma unroll
    for (int i = 0; i < 3; i++) { float d = v[i] - mu; q += d * d; }
    q = bsum(q, sred);
    float rstd = rsqrtf(q * (1.f / D_) + 1e-5f);
#pragma unroll
    for (int i = 0; i < 3; i++) { int c = tid + i * 256; yr[c] = (v[i] - mu) * rstd * g[c] + b[c]; }
}

// ---------------- causal softmax ----------------
__global__ void softmax_kernel(float* __restrict__ sc)
{
    __shared__ float sred[8];
    long row = blockIdx.x;
    int i = (int)(row & (T_ - 1));
    float* r = sc + row * (long)T_;
    int tid = threadIdx.x;
    int n = i + 1;
    float rv[4];
    float mx = -3.402823e38f;
#pragma unroll
    for (int p = 0; p < 4; p++) { int j = tid + p * 256; if (j < n) { rv[p] = r[j]; mx = fmaxf(mx, rv[p]); } }
    mx = bmax(mx, sred);
    float s = 0.f;
#pragma unroll
    for (int p = 0; p < 4; p++) { int j = tid + p * 256; if (j < n) { rv[p] = __expf(rv[p] - mx); s += rv[p]; } }
    s = bsum(s, sred);
    float inv = 1.f / s;
    int zend = ((i >> 7) + 1) << 7;
#pragma unroll
    for (int p = 0; p < 4; p++) {
        int j = tid + p * 256;
        if (j < n) r[j] = rv[p] * inv;
        else if (j < zend) r[j] = 0.f;
    }
}

// ---------------- router + pair binning ----------------
__global__ void zero_cnt_kernel(int* cnt) { if (threadIdx.x < NPAIR) cnt[threadIdx.x] = 0; }

__global__ void router_kernel(const float* __restrict__ h, const float* __restrict__ rw,
                              float* __restrict__ mp, int* __restrict__ pairid,
                              int* __restrict__ cnt)
{
    __shared__ float sc[E_];
    long tok = blockIdx.x;
    int tid = threadIdx.x;
    int w = tid >> 5, lane = tid & 31;
    const float* hr = h + tok * D_;
    const float* we = rw + (long)w * D_;
    float s = 0.f;
    for (int k = lane; k < D_; k += 32) s += hr[k] * we[k];
#pragma unroll
    for (int o = 16; o; o >>= 1) s += __shfl_xor_sync(0xffffffffu, s, o);
    if (lane == 0) sc[w] = s;
    __syncthreads();
    if (tid == 0) {
        float mx = sc[0];
#pragma unroll
        for (int e = 1; e < E_; e++) mx = fmaxf(mx, sc[e]);
        float p[E_], sum = 0.f;
#pragma unroll
        for (int e = 0; e < E_; e++) { p[e] = __expf(sc[e] - mx); sum += p[e]; }
        int i1 = 0;
#pragma unroll
        for (int e = 1; e < E_; e++) if (sc[e] > sc[i1]) i1 = e;
        int i2 = -1;
#pragma unroll
        for (int e = 0; e < E_; e++) if (e != i1 && (i2 < 0 || sc[e] > sc[i2])) i2 = e;
        float p1 = p[i1] / sum, p2 = p[i2] / sum;
        float inv = 1.f / (p1 + p2 + 1e-8f);
#pragma unroll
        for (int e = 0; e < E_; e++) mp[tok * E_ + e] = 0.f;
        mp[tok * E_ + i1] = p1 * inv;
        mp[tok * E_ + i2] = p2 * inv;
        int a = i1 < i2 ? i1 : i2;
        int bx = i1 < i2 ? i2 : i1;
        int pid = a * E_ - a * (a + 1) / 2 + (bx - a - 1);
        pairid[tok] = pid;
        atomicAdd(&cnt[pid], 1);
    }
}

__global__ void prefix_kernel(const int* __restrict__ cnt, int* __restrict__ baseo,
                              int* __restrict__ pos)
{
    if (threadIdx.x == 0) {
        int s = 0;
        for (int p = 0; p < NPAIR; p++) { baseo[p] = s; pos[p] = s; s += cnt[p]; }
    }
}

__global__ void scatter_kernel(const int* __restrict__ pairid, int* __restrict__ pos,
                               int* __restrict__ idxv)
{
    int t = blockIdx.x * 256 + threadIdx.x;
    if (t < M_) {
        int p = pairid[t];
        int slot = atomicAdd(&pos[p], 1);
        idxv[slot] = t;
    }
}

// ---------------- host side ----------------
template <class T>
static T* sym(const void* s) { void* p = nullptr; cudaGetSymbolAddress(&p, s); return (T*)p; }

template <int MODE>
static void gemm_nt(const float* A, const float* Bw, float* C,
                    int M, int N, int K, int lda, int ldb, int ldc, float alpha = 1.f)
{
    dim3 grid((N + 127) / 128, (M + 127) / 128, 1);
    gemm_tile<MODE, true><<<grid, 256>>>(A, Bw, C, nullptr, M, N, K, lda, ldb, ldc,
                                         0, K, 0, 0, 0, 0, 0, 0, 0, alpha, 0, 0);
}

extern "C" void kernel_launch(void* const* d_in, const int* in_sizes, int n_in,
                              void* d_out, int out_size)
{
    const int*   tokens  = (const int*)d_in[0];
    const float* wte     = (const float*)d_in[1];
    const float* wpe     = (const float*)d_in[2];
    const float* n0g     = (const float*)d_in[3];
    const float* n0b     = (const float*)d_in[4];
    const float* n1g     = (const float*)d_in[5];
    const float* n1b     = (const float*)d_in[6];
    const float* n2g     = (const float*)d_in[7];
    const float* n2b     = (const float*)d_in[8];
    const float* qkvw    = (const float*)d_in[9];
    const float* projw   = (const float*)d_in[10];
    const float* routerw = (const float*)d_in[11];
    const float* fc1     = (const float*)d_in[12];
    const float* fc2     = (const float*)d_in[13];
    const float* lmw     = (const float*)d_in[14];
    float* out = (float*)d_out;

    float* x    = sym<float>(g_x);
    float* h    = sym<float>(g_h);
    float* at   = sym<float>(g_attn);
    float* qkv  = sym<float>(g_qkv);
    float* scs  = sym<float>(g_scores);
    float* hidc = sym<float>(g_hidc);
    float* mp   = sym<float>(g_mp);
    int* cnt    = sym<int>(g_cnt);
    int* baseo  = sym<int>(g_baseo);
    int* pos    = sym<int>(g_pos);
    int* pairid = sym<int>(g_pairid);
    int* idxv   = sym<int>(g_idx);

    // embed + LN0
    embed_ln_kernel<<<M_, 256>>>(tokens, wte, wpe, n0g, n0b, x);

    for (int l = 0; l < L_; l++) {
        // LN1
        ln_kernel<<<M_, 256>>>(x, h, n1g + l * D_, n1b + l * D_);
        // QKV
        gemm_nt<0>(h, qkvw + (long)l * D3_ * D_, qkv, M_, D3_, D_, D_, D_, D3_);
        // scores = (Q K^T)/8, causal tile-skip
        {
            dim3 grid(T_ / 128, T_ / 128, B_ * H_);
            gemm_tile<0, true><<<grid, 256>>>(
                qkv, qkv + D_, scs, nullptr,
                T_, T_, HEAD_, D3_, D3_, T_,
                0, HEAD_, H_,
                (long)T_ * D3_, HEAD_, (long)T_ * D3_, HEAD_,
                (long)H_ * T_ * T_, (long)T_ * T_,
                0.125f, 1, 0);
        }
        softmax_kernel<<<B_ * H_ * T_, 256>>>(scs);
        // PV (K truncated at causal tile boundary)
        {
            dim3 grid(1, T_ / 128, B_ * H_);
            gemm_tile<0, false><<<grid, 256>>>(
                scs, qkv + 2 * D_, at, nullptr,
                T_, HEAD_, T_, T_, D3_, D_,
                0, T_, H_,
                (long)H_ * T_ * T_, (long)T_ * T_, (long)T_ * D3_, HEAD_,
                (long)T_ * D_, HEAD_,
                1.f, 0, 1);
        }
        // x += attn @ proj^T
        gemm_nt<2>(at, projw + (long)l * D_ * D_, x, M_, D_, D_, D_, D_, D_);
        // LN2
        ln_kernel<<<M_, 256>>>(x, h, n2g + l * D_, n2b + l * D_);
        // router + pair binning
        zero_cnt_kernel<<<1, 32>>>(cnt);
        router_kernel<<<M_, 256>>>(h, routerw + (long)l * E_ * D_, mp, pairid, cnt);
        prefix_kernel<<<1, 32>>>(cnt, baseo, pos);
        scatter_kernel<<<M_ / 256, 256>>>(pairid, pos, idxv);
        // grouped fc1: only the 2 selected experts per token
        {
            dim3 grid(D2FF / 128, M_ / 128, NPAIR);
            fc1_group<<<grid, 256>>>(h, fc1 + (size_t)l * E_ * DFF_ * D_, hidc, mp,
                                     idxv, baseo, cnt);
        }
        // grouped fc2: x[tok] += hidc @ [W_e1;W_e2]^T
        {
            dim3 grid(D_ / 128, M_ / 128, NPAIR);
            fc2_group<<<grid, 256>>>(hidc, fc2 + (size_t)l * E_ * D_ * DFF_, x,
                                     idxv, baseo, cnt);
        }
    }
    // logits
    gemm_nt<0>(x, lmw, out, M_, V_, D_, D_, D_, V_);
}

// round 8
// speedup vs baseline: 5.5660x; 1.2110x over previous
#include <cuda_runtime.h>
#include <cuda_bf16.h>
#include <math.h>
#include <stdint.h>

typedef __nv_bfloat16 bf;

// ---------------- problem constants ----------------
constexpr int B_ = 2, T_ = 1024, D_ = 768, H_ = 12, L_ = 4, E_ = 8, DFF_ = 3072, V_ = 32000;
constexpr int HEAD_ = D_ / H_;       // 64
constexpr int D3_ = 3 * D_;          // 2304
constexpr int M_ = B_ * T_;          // 2048 tokens
constexpr int NPAIR = 28;            // C(8,2)
constexpr int D2FF = 2 * DFF_;       // 6144
constexpr int NSEG = 96;             // >= 28 + 2048/32 = 92 worst case

// ---------------- scratch (static device, allocation-free) ----------------
__device__ __align__(128) float g_x[(size_t)M_ * D_];
__device__ __align__(128) float g_h[(size_t)M_ * D_];
__device__ __align__(128) float g_attn[(size_t)M_ * D_];
__device__ __align__(128) float g_qkv[(size_t)M_ * D3_];
__device__ __align__(128) float g_scores[(size_t)B_ * H_ * T_ * T_];
__device__ __align__(128) float g_hidc[(size_t)M_ * D2FF];
__device__ __align__(128) float g_mp[(size_t)M_ * E_];
__device__ int g_cnt[NPAIR], g_baseo[NPAIR], g_pos[NPAIR];
__device__ int g_pairid[M_], g_idx[M_];
__device__ int g_segp[NSEG], g_segrow[NSEG], g_segcnt[NSEG];

// bf16 planes for tensor-core lm_head (router-safe: nothing downstream but logits)
__device__ __align__(128) bf g_xp_h[(size_t)M_ * D_], g_xp_m[(size_t)M_ * D_], g_xp_l[(size_t)M_ * D_];
__device__ __align__(128) bf w_lm_h[(size_t)V_ * D_], w_lm_m[(size_t)V_ * D_], w_lm_l[(size_t)V_ * D_];

// pair tables: p -> (e1 < e2)
__constant__ int c_pe1[NPAIR] = {0,0,0,0,0,0,0, 1,1,1,1,1,1, 2,2,2,2,2, 3,3,3,3, 4,4,4, 5,5, 6};
__constant__ int c_pe2[NPAIR] = {1,2,3,4,5,6,7, 2,3,4,5,6,7, 3,4,5,6,7, 4,5,6,7, 5,6,7, 6,7, 7};

// ---------------- packed f32x2 FMA ----------------
__device__ __forceinline__ float2 ffma2(float2 a, float2 b, float2 c) {
    unsigned long long au, bu, cu, du;
    au = *reinterpret_cast<unsigned long long*>(&a);
    bu = *reinterpret_cast<unsigned long long*>(&b);
    cu = *reinterpret_cast<unsigned long long*>(&c);
    asm("fma.rn.f32x2 %0, %1, %2, %3;" : "=l"(du) : "l"(au), "l"(bu), "l"(cu));
    return *reinterpret_cast<float2*>(&du);
}

// ---------------- reductions ----------------
__device__ __forceinline__ float bsum(float v, float* sred) {
#pragma unroll
    for (int o = 16; o; o >>= 1) v += __shfl_xor_sync(0xffffffffu, v, o);
    if ((threadIdx.x & 31) == 0) sred[threadIdx.x >> 5] = v;
    __syncthreads();
    float r = 0.f;
#pragma unroll
    for (int i = 0; i < 8; i++) r += sred[i];
    __syncthreads();
    return r;
}
__device__ __forceinline__ float bmax(float v, float* sred) {
#pragma unroll
    for (int o = 16; o; o >>= 1) v = fmaxf(v, __shfl_xor_sync(0xffffffffu, v, o));
    if ((threadIdx.x & 31) == 0) sred[threadIdx.x >> 5] = v;
    __syncthreads();
    float r = -3.402823e38f;
#pragma unroll
    for (int i = 0; i < 8; i++) r = fmaxf(r, sred[i]);
    __syncthreads();
    return r;
}

// ---------------- inner-product macro body (FFMA2; bit-exact per-element chain)
#define GEMM_ACC_DECL                                   \
    float2 acc2[4][8];                                  \
    _Pragma("unroll")                                   \
    for (int ip = 0; ip < 4; ip++)                      \
        _Pragma("unroll")                               \
        for (int j = 0; j < 8; j++) acc2[ip][j] = make_float2(0.f, 0.f);

#define GEMM_INNER(As, Bs, trow, tcol)                                        \
    _Pragma("unroll")                                                          \
    for (int kk = 0; kk < 16; kk++) {                                          \
        float2 a2[4];                                                          \
        _Pragma("unroll")                                                      \
        for (int ip = 0; ip < 4; ip++) a2[ip] = *(const float2*)&As[kk][(trow) + 2 * ip]; \
        float4 b0 = *(const float4*)&Bs[kk][(tcol)];                           \
        float4 b1 = *(const float4*)&Bs[kk][(tcol) + 4];                       \
        float bsv[8] = {b0.x, b0.y, b0.z, b0.w, b1.x, b1.y, b1.z, b1.w};       \
        _Pragma("unroll")                                                      \
        for (int j = 0; j < 8; j++) {                                          \
            float2 bd = make_float2(bsv[j], bsv[j]);                           \
            _Pragma("unroll")                                                  \
            for (int ip = 0; ip < 4; ip++)                                     \
                acc2[ip][j] = ffma2(a2[ip], bd, acc2[ip][j]);                  \
        }                                                                      \
    }

// ---------------- generic tiled GEMM (dense; attention/QKV/proj) ----------------
// MODE 0: C = alpha*acc     MODE 2: C += acc
template <int MODE, bool BNT>
__global__ void __launch_bounds__(256, 2)
gemm_tile(const float* __restrict__ A, const float* __restrict__ Bw,
          float* __restrict__ C,
          int M, int N, int K, int lda, int ldb, int ldc, int ZH,
          long sAb, long sAh, long sBb, long sBh, long sCb, long sCh,
          float alpha, int causalSkip, int causalK)
{
    constexpr int BM = 128, BN = 128, BK = 16;
    if (ZH > 0) {
        int z = blockIdx.z;
        int zb = z / ZH, zh = z - zb * ZH;
        A  += zb * sAb + zh * sAh;
        Bw += zb * sBb + zh * sBh;
        C  += zb * sCb + zh * sCh;
    }
    const int n0 = blockIdx.x * BN;
    const int m0 = blockIdx.y * BM;
    if (causalSkip && n0 > m0) return;
    const int kend = causalK ? min(K, m0 + BM) : K;

    __shared__ float As[BK][BM];
    __shared__ float Bs[BK][BN];

    const int tid  = threadIdx.x;
    const int trow = (tid >> 4) << 3;
    const int tcol = (tid & 15) << 3;

    GEMM_ACC_DECL

    for (int k0 = 0; k0 < kend; k0 += BK) {
#pragma unroll
        for (int it = 0; it < 2; it++) {
            int idx = tid + it * 256;
            int r = idx >> 2;
            int c4 = (idx & 3) << 2;
            float4 v = *(const float4*)(A + (long)(m0 + r) * lda + k0 + c4);
            As[c4 + 0][r] = v.x; As[c4 + 1][r] = v.y;
            As[c4 + 2][r] = v.z; As[c4 + 3][r] = v.w;
        }
        if (BNT) {
#pragma unroll
            for (int it = 0; it < 2; it++) {
                int idx = tid + it * 256;
                int r = idx >> 2;
                int c4 = (idx & 3) << 2;
                float4 v = make_float4(0.f, 0.f, 0.f, 0.f);
                if (n0 + r < N) v = *(const float4*)(Bw + (long)(n0 + r) * ldb + k0 + c4);
                Bs[c4 + 0][r] = v.x; Bs[c4 + 1][r] = v.y;
                Bs[c4 + 2][r] = v.z; Bs[c4 + 3][r] = v.w;
            }
        } else {
#pragma unroll
            for (int it = 0; it < 2; it++) {
                int idx = tid + it * 256;
                int r = idx >> 5;
                int c4 = (idx & 31) << 2;
                float4 v = make_float4(0.f, 0.f, 0.f, 0.f);
                if (n0 + c4 + 3 < N) v = *(const float4*)(Bw + (long)(k0 + r) * ldb + n0 + c4);
                *(float4*)&Bs[r][c4] = v;
            }
        }
        __syncthreads();
        GEMM_INNER(As, Bs, trow, tcol)
        __syncthreads();
    }

#pragma unroll
    for (int ip = 0; ip < 4; ip++) {
#pragma unroll
        for (int sub = 0; sub < 2; sub++) {
            int m = m0 + trow + 2 * ip + sub;
            if (m >= M) continue;
#pragma unroll
            for (int j = 0; j < 8; j++) {
                int n = n0 + tcol + j;
                if (n >= N) continue;
                long ci = (long)m * ldc + n;
                float v = sub ? acc2[ip][j].y : acc2[ip][j].x;
                if (MODE == 0) C[ci] = alpha * v;
                else           C[ci] += v;
            }
        }
    }
}

// ---------------- segmented fc1: quantum-32 padding, 4 segments per block ----
// For segment s (pair p): hidc[crow, n0..n0+127] = mp * relu(h[tok] @ W_e^T)
__global__ void __launch_bounds__(256, 2)
fc1_seg(const float* __restrict__ h, const float* __restrict__ w1,
        float* __restrict__ hidc, const float* __restrict__ mp,
        const int* __restrict__ idxv, const int* __restrict__ segp,
        const int* __restrict__ segrow, const int* __restrict__ segcnt)
{
    const int q  = blockIdx.y;           // segment quad
    const int n0 = blockIdx.x * 128;     // 0..6143 (pair column space)
    const int tid = threadIdx.x;

    if (segcnt[q*4+0] + segcnt[q*4+1] + segcnt[q*4+2] + segcnt[q*4+3] == 0) return;

    __shared__ float As[16][128];
    __shared__ float Bs[4][16][128];
    __shared__ int sidx[128];
    __shared__ int s_cnt[4], s_row[4], s_e[4];

    if (tid < 128) {
        int sg = q*4 + (tid >> 5);
        int c = segcnt[sg];
        int off = tid & 31;
        if (off >= c) off = (c > 0) ? c - 1 : 0;
        sidx[tid] = idxv[segrow[sg] + off];
    }
    if (tid < 4) {
        int sg = q*4 + tid;
        int p = segp[sg];
        s_cnt[tid] = segcnt[sg];
        s_row[tid] = segrow[sg];
        s_e[tid] = (n0 < DFF_) ? c_pe1[p] : c_pe2[p];
    }
    __syncthreads();

    const int trow = (tid >> 4) << 3;
    const int tcol = (tid & 15) << 3;
    const int nw = (n0 < DFF_) ? n0 : n0 - DFF_;
    const int myseg = trow >> 5;

    GEMM_ACC_DECL

    for (int k0 = 0; k0 < D_; k0 += 16) {
#pragma unroll
        for (int it = 0; it < 2; it++) {
            int idx = tid + it * 256;
            int r = idx >> 2, c4 = (idx & 3) << 2;
            float4 v = *(const float4*)(h + (size_t)sidx[r] * D_ + k0 + c4);
            As[c4 + 0][r] = v.x; As[c4 + 1][r] = v.y;
            As[c4 + 2][r] = v.z; As[c4 + 3][r] = v.w;
        }
#pragma unroll
        for (int t = 0; t < 4; t++) {
            const float* Bw = w1 + (size_t)s_e[t] * DFF_ * D_ + (size_t)nw * D_;
#pragma unroll
            for (int it = 0; it < 2; it++) {
                int idx = tid + it * 256;
                int r = idx >> 2, c4 = (idx & 3) << 2;
                float4 v = *(const float4*)(Bw + (size_t)r * D_ + k0 + c4);
                Bs[t][c4 + 0][r] = v.x; Bs[t][c4 + 1][r] = v.y;
                Bs[t][c4 + 2][r] = v.z; Bs[t][c4 + 3][r] = v.w;
            }
        }
        __syncthreads();
        GEMM_INNER(As, Bs[myseg], trow, tcol)
        __syncthreads();
    }

#pragma unroll
    for (int ip = 0; ip < 4; ip++) {
#pragma unroll
        for (int sub = 0; sub < 2; sub++) {
            int ml = trow + 2 * ip + sub;
            int seg = ml >> 5, off = ml & 31;
            if (off >= s_cnt[seg]) continue;
            int tok = sidx[ml];
            int crow = s_row[seg] + off;
            float sc = mp[(size_t)tok * E_ + s_e[seg]];
#pragma unroll
            for (int j = 0; j < 8; j++) {
                float v = sub ? acc2[ip][j].y : acc2[ip][j].x;
                hidc[(size_t)crow * D2FF + n0 + tcol + j] = sc * fmaxf(v, 0.f);
            }
        }
    }
}

// ---------------- segmented fc2: x[tok] += hidc_row @ [W_e1;W_e2]^T (K=6144)
__global__ void __launch_bounds__(256, 2)
fc2_seg(const float* __restrict__ hidc, const float* __restrict__ w2,
        float* __restrict__ x, const int* __restrict__ idxv,
        const int* __restrict__ segp, const int* __restrict__ segrow,
        const int* __restrict__ segcnt)
{
    const int q  = blockIdx.y;
    const int n0 = blockIdx.x * 128;     // 0..767
    const int tid = threadIdx.x;

    if (segcnt[q*4+0] + segcnt[q*4+1] + segcnt[q*4+2] + segcnt[q*4+3] == 0) return;

    __shared__ float As[16][128];
    __shared__ float Bs[4][16][128];
    __shared__ int sidx[128];
    __shared__ int scrow[128];
    __shared__ int s_cnt[4], s_row[4], s_p[4];

    if (tid < 128) {
        int sg = q*4 + (tid >> 5);
        int c = segcnt[sg];
        int off = tid & 31;
        if (off >= c) off = (c > 0) ? c - 1 : 0;
        int cr = segrow[sg] + off;
        scrow[tid] = cr;
        sidx[tid] = idxv[cr];
    }
    if (tid < 4) {
        int sg = q*4 + tid;
        s_cnt[tid] = segcnt[sg];
        s_row[tid] = segrow[sg];
        s_p[tid] = segp[sg];
    }
    __syncthreads();

    const int trow = (tid >> 4) << 3;
    const int tcol = (tid & 15) << 3;
    const int myseg = trow >> 5;

    GEMM_ACC_DECL

    for (int k0 = 0; k0 < D2FF; k0 += 16) {
        const int eb = (k0 >= DFF_);
        const int kk0 = k0 - (eb ? DFF_ : 0);
#pragma unroll
        for (int it = 0; it < 2; it++) {
            int idx = tid + it * 256;
            int r = idx >> 2, c4 = (idx & 3) << 2;
            float4 v = *(const float4*)(hidc + (size_t)scrow[r] * D2FF + k0 + c4);
            As[c4 + 0][r] = v.x; As[c4 + 1][r] = v.y;
            As[c4 + 2][r] = v.z; As[c4 + 3][r] = v.w;
        }
#pragma unroll
        for (int t = 0; t < 4; t++) {
            int e = eb ? c_pe2[s_p[t]] : c_pe1[s_p[t]];
            const float* Bw = w2 + (size_t)e * D_ * DFF_ + (size_t)n0 * DFF_ + kk0;
#pragma unroll
            for (int it = 0; it < 2; it++) {
                int idx = tid + it * 256;
                int r = idx >> 2, c4 = (idx & 3) << 2;
                float4 v = *(const float4*)(Bw + (size_t)r * DFF_ + c4);
                Bs[t][c4 + 0][r] = v.x; Bs[t][c4 + 1][r] = v.y;
                Bs[t][c4 + 2][r] = v.z; Bs[t][c4 + 3][r] = v.w;
            }
        }
        __syncthreads();
        GEMM_INNER(As, Bs[myseg], trow, tcol)
        __syncthreads();
    }

#pragma unroll
    for (int ip = 0; ip < 4; ip++) {
#pragma unroll
        for (int sub = 0; sub < 2; sub++) {
            int ml = trow + 2 * ip + sub;
            int seg = ml >> 5, off = ml & 31;
            if (off >= s_cnt[seg]) continue;
            int tok = sidx[ml];
#pragma unroll
            for (int j = 0; j < 8; j++) {
                float v = sub ? acc2[ip][j].y : acc2[ip][j].x;
                x[(size_t)tok * D_ + n0 + tcol + j] += v;
            }
        }
    }
}

// ================= tensor-core lm_head (router-safe) =================
__device__ __forceinline__ uint32_t smem_u32(const void* p) {
    uint32_t a;
    asm("{ .reg .u64 t; cvta.to.shared.u64 t, %1; cvt.u32.u64 %0, t; }" : "=r"(a) : "l"(p));
    return a;
}
__device__ __forceinline__ void cpa16(uint32_t dst, const void* src) {
    asm volatile("cp.async.cg.shared.global [%0], [%1], 16;" :: "r"(dst), "l"(src) : "memory");
}
__device__ __forceinline__ void cpa_commit() { asm volatile("cp.async.commit_group;" ::: "memory"); }
template <int N> __device__ __forceinline__ void cpa_wait() {
    asm volatile("cp.async.wait_group %0;" :: "n"(N) : "memory");
}
#define LDSM4(R, addr) \
    asm volatile("ldmatrix.sync.aligned.m8n8.x4.shared.b16 {%0,%1,%2,%3}, [%4];" \
        : "=r"((R)[0]), "=r"((R)[1]), "=r"((R)[2]), "=r"((R)[3]) : "r"(addr))
__device__ __forceinline__ void mma16816(float* c, const uint32_t* a, uint32_t b0, uint32_t b1) {
    asm volatile("mma.sync.aligned.m16n8k16.row.col.f32.bf16.bf16.f32 "
                 "{%0,%1,%2,%3}, {%4,%5,%6,%7}, {%8,%9}, {%0,%1,%2,%3};"
                 : "+f"(c[0]), "+f"(c[1]), "+f"(c[2]), "+f"(c[3])
                 : "r"(a[0]), "r"(a[1]), "r"(a[2]), "r"(a[3]), "r"(b0), "r"(b1));
}
__device__ __forceinline__ void split3(float v, bf& h, bf& m, bf& l) {
    h = __float2bfloat16(v);
    float r = v - __bfloat162float(h);
    m = __float2bfloat16(r);
    l = __float2bfloat16(r - __bfloat162float(m));
}

constexpr int ROWB = 80;                         // 32 bf16 + 16B pad
constexpr int A_BYTES = 128 * ROWB;              // 10240
constexpr int STAGE_BYTES = A_BYTES * 2;         // 20480
constexpr int TNST = 3;
constexpr int TC_SMEM = TNST * STAGE_BYTES;      // 61440

// C[2048, 32000] = 3-pass (hh + hm + mh) bf16 emulation of x @ lm^T.  K=768.
__global__ void __launch_bounds__(256)
tc_lmhead(const bf* __restrict__ Ah, const bf* __restrict__ Am, const bf* __restrict__ Al,
          const bf* __restrict__ Bh, const bf* __restrict__ Bm, const bf* __restrict__ Bl,
          float* __restrict__ Cf)
{
    extern __shared__ __align__(128) char smem[];
    const uint32_t sbase = smem_u32(smem);
    const int tid  = threadIdx.x;
    const int lane = tid & 31;
    const int wid  = tid >> 5;
    const int wm   = wid & 1;
    const int wn   = wid >> 1;
    const int m0 = blockIdx.y * 128;
    const int n0 = blockIdx.x * 128;

    constexpr int KC = D_ / 32;      // 24 chunks per pass
    constexpr int C3 = 3 * KC;       // 72

    const int lr = tid >> 2;
    const int lq = (tid & 3) << 4;

    auto load_chunk = [&](int c, int s) {
        int p = c / KC;
        int kabs = (c - p * KC) << 5;
        const bf* Ap = (p == 1) ? Am : Ah;        // pass0: hh, pass1: h*m, pass2: m*h
        const bf* Bp = (p == 1) ? Bm : Bh;
        if (p == 1) Ap = Ah;                      // (0,0),(0,1),(1,0)
        if (p == 2) { Ap = Am; Bp = Bh; }
        uint32_t sA = sbase + (uint32_t)s * STAGE_BYTES;
        uint32_t sB = sA + A_BYTES;
#pragma unroll
        for (int i = 0; i < 2; i++) {
            int r = lr + (i << 6);
            cpa16(sA + r * ROWB + lq, Ap + (size_t)(m0 + r) * D_ + kabs + (lq >> 1));
        }
#pragma unroll
        for (int i = 0; i < 2; i++) {
            int r = lr + (i << 6);
            cpa16(sB + r * ROWB + lq, Bp + (size_t)(n0 + r) * D_ + kabs + (lq >> 1));
        }
        cpa_commit();
    };

    float acc[4][4][4];
#pragma unroll
    for (int i = 0; i < 4; i++)
#pragma unroll
        for (int j = 0; j < 4; j++)
#pragma unroll
            for (int qq = 0; qq < 4; qq++) acc[i][j][qq] = 0.f;

    const int arow = (lane & 7) + ((lane >> 3) & 1) * 8;
    const int akh  = (lane >> 4) & 1;
    const int brow = (lane & 7) + ((lane >> 4) & 1) * 8;
    const int bkh  = (lane >> 3) & 1;

    load_chunk(0, 0);
    load_chunk(1, 1);

    for (int c = 0; c < C3; ++c) {
        int s = c % TNST;
        if (c + 1 < C3) cpa_wait<1>(); else cpa_wait<0>();
        __syncthreads();
        if (c + 2 < C3) load_chunk(c + 2, (c + 2) % TNST);

        uint32_t sA = sbase + (uint32_t)s * STAGE_BYTES;
        uint32_t sB = sA + A_BYTES;
        uint32_t aAddr = sA + (wm * 64 + arow) * ROWB + akh * 16;
        uint32_t bAddr = sB + (wn * 32 + brow) * ROWB + bkh * 16;

#pragma unroll
        for (int kc = 0; kc < 2; kc++) {
            uint32_t af[4][4], bfm[2][4];
#pragma unroll
            for (int ms = 0; ms < 4; ms++) LDSM4(af[ms], aAddr + ms * (16 * ROWB) + kc * 32);
#pragma unroll
            for (int np = 0; np < 2; np++) LDSM4(bfm[np], bAddr + np * (16 * ROWB) + kc * 32);
#pragma unroll
            for (int i = 0; i < 4; i++)
#pragma unroll
                for (int j = 0; j < 4; j++)
                    mma16816(acc[i][j], af[i], bfm[j >> 1][(j & 1) * 2], bfm[j >> 1][(j & 1) * 2 + 1]);
        }
    }

    const int tg  = lane >> 2;
    const int tc2 = (lane & 3) << 1;
#pragma unroll
    for (int i = 0; i < 4; i++) {
        int r0 = m0 + wm * 64 + i * 16 + tg;
        int r1 = r0 + 8;
#pragma unroll
        for (int j = 0; j < 4; j++) {
            int cb = n0 + wn * 32 + j * 8 + tc2;
            float* a4 = acc[i][j];
            *(float2*)(Cf + (size_t)r0 * V_ + cb) = make_float2(a4[0], a4[1]);
            *(float2*)(Cf + (size_t)r1 * V_ + cb) = make_float2(a4[2], a4[3]);
        }
    }
}

// ---------------- fp32 -> 3x bf16 planes ----------------
__global__ void cvt_split3(const float* __restrict__ x, bf* __restrict__ hi,
                           bf* __restrict__ mi, bf* __restrict__ lo, size_t n4)
{
    size_t i = (size_t)blockIdx.x * blockDim.x + threadIdx.x;
    size_t stride = (size_t)gridDim.x * blockDim.x;
    for (; i < n4; i += stride) {
        float4 v = ((const float4*)x)[i];
        bf h[4], m[4], l[4];
        split3(v.x, h[0], m[0], l[0]); split3(v.y, h[1], m[1], l[1]);
        split3(v.z, h[2], m[2], l[2]); split3(v.w, h[3], m[3], l[3]);
        ((__nv_bfloat162*)hi)[i * 2 + 0] = __halves2bfloat162(h[0], h[1]);
        ((__nv_bfloat162*)hi)[i * 2 + 1] = __halves2bfloat162(h[2], h[3]);
        ((__nv_bfloat162*)mi)[i * 2 + 0] = __halves2bfloat162(m[0], m[1]);
        ((__nv_bfloat162*)mi)[i * 2 + 1] = __halves2bfloat162(m[2], m[3]);
        ((__nv_bfloat162*)lo)[i * 2 + 0] = __halves2bfloat162(l[0], l[1]);
        ((__nv_bfloat162*)lo)[i * 2 + 1] = __halves2bfloat162(l[2], l[3]);
    }
}

// ---------------- embedding + LN0 ----------------
__global__ void embed_ln_kernel(const int* __restrict__ tokens,
                                const float* __restrict__ wte, const float* __restrict__ wpe,
                                const float* __restrict__ g, const float* __restrict__ b,
                                float* __restrict__ y)
{
    __shared__ float sred[8];
    long row = blockIdx.x;
    int t = (int)(row % T_);
    int tok = tokens[row];
    const float* we = wte + (long)tok * D_;
    const float* pe = wpe + (long)t * D_;
    float* yr = y + row * D_;
    int tid = threadIdx.x;
    float v[3], s = 0.f;
#pragma unroll
    for (int i = 0; i < 3; i++) { int c = tid + i * 256; v[i] = we[c] + pe[c]; s += v[i]; }
    s = bsum(s, sred);
    float mu = s * (1.f / D_);
    float q = 0.f;
#pragma unroll
    for (int i = 0; i < 3; i++) { float d = v[i] - mu; q += d * d; }
    q = bsum(q, sred);
    float rstd = rsqrtf(q * (1.f / D_) + 1e-5f);
#pragma unroll
    for (int i = 0; i < 3; i++) { int c = tid + i * 256; yr[c] = (v[i] - mu) * rstd * g[c] + b[c]; }
}

// ---------------- LayerNorm ----------------
__global__ void ln_kernel(const float* __restrict__ x, float* __restrict__ y,
                          const float* __restrict__ g, const float* __restrict__ b)
{
    __shared__ float sred[8];
    long row = blockIdx.x;
    const float* xr = x + row * D_;
    float* yr = y + row * D_;
    int tid = threadIdx.x;
    float v[3], s = 0.f;
#pragma unroll
    for (int i = 0; i < 3; i++) { v[i] = xr[tid + i * 256]; s += v[i]; }
    s = bsum(s, sred);
    float mu = s * (1.f / D_);
    float q = 0.f;
#pragma unroll
    for (int i = 0; i < 3; i++) { float d = v[i] - mu; q += d * d; }
    q = bsum(q, sred);
    float rstd = rsqrtf(q * (1.f / D_) + 1e-5f);
#pragma unroll
    for (int i = 0; i < 3; i++) { int c = tid + i * 256; yr[c] = (v[i] - mu) * rstd * g[c] + b[c]; }
}

// ---------------- causal softmax ----------------
__global__ void softmax_kernel(float* __restrict__ sc)
{
    __shared__ float sred[8];
    long row = blockIdx.x;
    int i = (int)(row & (T_ - 1));
    float* r = sc + row * (long)T_;
    int tid = threadIdx.x;
    int n = i + 1;
    float rv[4];
    float mx = -3.402823e38f;
#pragma unroll
    for (int p = 0; p < 4; p++) { int j = tid + p * 256; if (j < n) { rv[p] = r[j]; mx = fmaxf(mx, rv[p]); } }
    mx = bmax(mx, sred);
    float s = 0.f;
#pragma unroll
    for (int p = 0; p < 4; p++) { int j = tid + p * 256; if (j < n) { rv[p] = __expf(rv[p] - mx); s += rv[p]; } }
    s = bsum(s, sred);
    float inv = 1.f / s;
    int zend = ((i >> 7) + 1) << 7;
#pragma unroll
    for (int p = 0; p < 4; p++) {
        int j = tid + p * 256;
        if (j < n) r[j] = rv[p] * inv;
        else if (j < zend) r[j] = 0.f;
    }
}

// ---------------- router + pair binning + segments ----------------
__global__ void zero_cnt_kernel(int* cnt) { if (threadIdx.x < NPAIR) cnt[threadIdx.x] = 0; }

__global__ void router_kernel(const float* __restrict__ h, const float* __restrict__ rw,
                              float* __restrict__ mp, int* __restrict__ pairid,
                              int* __restrict__ cnt)
{
    __shared__ float sc[E_];
    long tok = blockIdx.x;
    int tid = threadIdx.x;
    int w = tid >> 5, lane = tid & 31;
    const float* hr = h + tok * D_;
    const float* we = rw + (long)w * D_;
    float s = 0.f;
    for (int k = lane; k < D_; k += 32) s += hr[k] * we[k];
#pragma unroll
    for (int o = 16; o; o >>= 1) s += __shfl_xor_sync(0xffffffffu, s, o);
    if (lane == 0) sc[w] = s;
    __syncthreads();
    if (tid == 0) {
        float mx = sc[0];
#pragma unroll
        for (int e = 1; e < E_; e++) mx = fmaxf(mx, sc[e]);
        float p[E_], sum = 0.f;
#pragma unroll
        for (int e = 0; e < E_; e++) { p[e] = __expf(sc[e] - mx); sum += p[e]; }
        int i1 = 0;
#pragma unroll
        for (int e = 1; e < E_; e++) if (sc[e] > sc[i1]) i1 = e;
        int i2 = -1;
#pragma unroll
        for (int e = 0; e < E_; e++) if (e != i1 && (i2 < 0 || sc[e] > sc[i2])) i2 = e;
        float p1 = p[i1] / sum, p2 = p[i2] / sum;
        float inv = 1.f / (p1 + p2 + 1e-8f);
#pragma unroll
        for (int e = 0; e < E_; e++) mp[tok * E_ + e] = 0.f;
        mp[tok * E_ + i1] = p1 * inv;
        mp[tok * E_ + i2] = p2 * inv;
        int a = i1 < i2 ? i1 : i2;
        int bx = i1 < i2 ? i2 : i1;
        int pid = a * E_ - a * (a + 1) / 2 + (bx - a - 1);
        pairid[tok] = pid;
        atomicAdd(&cnt[pid], 1);
    }
}

__global__ void prefix_kernel(const int* __restrict__ cnt, int* __restrict__ baseo,
                              int* __restrict__ pos, int* __restrict__ segp,
                              int* __restrict__ segrow, int* __restrict__ segcnt)
{
    if (threadIdx.x == 0) {
        int s = 0;
        for (int p = 0; p < NPAIR; p++) { baseo[p] = s; pos[p] = s; s += cnt[p]; }
        int ns = 0;
        for (int p = 0; p < NPAIR; p++) {
            int c = cnt[p];
            for (int o = 0; o < c; o += 32) {
                segp[ns] = p; segrow[ns] = baseo[p] + o;
                segcnt[ns] = (c - o < 32) ? (c - o) : 32;
                ns++;
            }
        }
        for (; ns < NSEG; ns++) { segp[ns] = 0; segrow[ns] = 0; segcnt[ns] = 0; }
    }
}

__global__ void scatter_kernel(const int* __restrict__ pairid, int* __restrict__ pos,
                               int* __restrict__ idxv)
{
    int t = blockIdx.x * 256 + threadIdx.x;
    if (t < M_) {
        int p = pairid[t];
        int slot = atomicAdd(&pos[p], 1);
        idxv[slot] = t;
    }
}

// ---------------- host side ----------------
template <class T>
static T* sym(const void* s) { void* p = nullptr; cudaGetSymbolAddress(&p, s); return (T*)p; }

template <int MODE>
static void gemm_nt(const float* A, const float* Bw, float* C,
                    int M, int N, int K, int lda, int ldb, int ldc, float alpha = 1.f)
{
    dim3 grid((N + 127) / 128, (M + 127) / 128, 1);
    gemm_tile<MODE, true><<<grid, 256>>>(A, Bw, C, M, N, K, lda, ldb, ldc,
                                         0, 0, 0, 0, 0, 0, 0, alpha, 0, 0);
}

extern "C" void kernel_launch(void* const* d_in, const int* in_sizes, int n_in,
                              void* d_out, int out_size)
{
    const int*   tokens  = (const int*)d_in[0];
    const float* wte     = (const float*)d_in[1];
    const float* wpe     = (const float*)d_in[2];
    const float* n0g     = (const float*)d_in[3];
    const float* n0b     = (const float*)d_in[4];
    const float* n1g     = (const float*)d_in[5];
    const float* n1b     = (const float*)d_in[6];
    const float* n2g     = (const float*)d_in[7];
    const float* n2b     = (const float*)d_in[8];
    const float* qkvw    = (const float*)d_in[9];
    const float* projw   = (const float*)d_in[10];
    const float* routerw = (const float*)d_in[11];
    const float* fc1     = (const float*)d_in[12];
    const float* fc2     = (const float*)d_in[13];
    const float* lmw     = (const float*)d_in[14];
    float* out = (float*)d_out;

    float* x    = sym<float>(g_x);
    float* h    = sym<float>(g_h);
    float* at   = sym<float>(g_attn);
    float* qkv  = sym<float>(g_qkv);
    float* scs  = sym<float>(g_scores);
    float* hidc = sym<float>(g_hidc);
    float* mp   = sym<float>(g_mp);
    int* cnt    = sym<int>(g_cnt);
    int* baseo  = sym<int>(g_baseo);
    int* pos    = sym<int>(g_pos);
    int* pairid = sym<int>(g_pairid);
    int* idxv   = sym<int>(g_idx);
    int* segp   = sym<int>(g_segp);
    int* segrow = sym<int>(g_segrow);
    int* segcnt = sym<int>(g_segcnt);
    bf* xp_h = sym<bf>(g_xp_h); bf* xp_m = sym<bf>(g_xp_m); bf* xp_l = sym<bf>(g_xp_l);
    bf* lm_h = sym<bf>(w_lm_h); bf* lm_m = sym<bf>(w_lm_m); bf* lm_l = sym<bf>(w_lm_l);

    cudaFuncSetAttribute(tc_lmhead, cudaFuncAttributeMaxDynamicSharedMemorySize, TC_SMEM);

    // lm_head weight planes (once per launch)
    cvt_split3<<<2048, 256>>>(lmw, lm_h, lm_m, lm_l, (size_t)V_ * D_ / 4);

    // embed + LN0
    embed_ln_kernel<<<M_, 256>>>(tokens, wte, wpe, n0g, n0b, x);

    for (int l = 0; l < L_; l++) {
        ln_kernel<<<M_, 256>>>(x, h, n1g + l * D_, n1b + l * D_);
        // QKV
        gemm_nt<0>(h, qkvw + (long)l * D3_ * D_, qkv, M_, D3_, D_, D_, D_, D3_);
        // scores = (Q K^T)/8, causal tile-skip
        {
            dim3 grid(T_ / 128, T_ / 128, B_ * H_);
            gemm_tile<0, true><<<grid, 256>>>(
                qkv, qkv + D_, scs,
                T_, T_, HEAD_, D3_, D3_, T_, H_,
                (long)T_ * D3_, HEAD_, (long)T_ * D3_, HEAD_,
                (long)H_ * T_ * T_, (long)T_ * T_,
                0.125f, 1, 0);
        }
        softmax_kernel<<<B_ * H_ * T_, 256>>>(scs);
        // PV (K truncated at causal tile boundary)
        {
            dim3 grid(1, T_ / 128, B_ * H_);
            gemm_tile<0, false><<<grid, 256>>>(
                scs, qkv + 2 * D_, at,
                T_, HEAD_, T_, T_, D3_, D_, H_,
                (long)H_ * T_ * T_, (long)T_ * T_, (long)T_ * D3_, HEAD_,
                (long)T_ * D_, HEAD_,
                1.f, 0, 1);
        }
        // x += attn @ proj^T
        gemm_nt<2>(at, projw + (long)l * D_ * D_, x, M_, D_, D_, D_, D_, D_);
        // LN2
        ln_kernel<<<M_, 256>>>(x, h, n2g + l * D_, n2b + l * D_);
        // router + binning + segment build
        zero_cnt_kernel<<<1, 32>>>(cnt);
        router_kernel<<<M_, 256>>>(h, routerw + (long)l * E_ * D_, mp, pairid, cnt);
        prefix_kernel<<<1, 32>>>(cnt, baseo, pos, segp, segrow, segcnt);
        scatter_kernel<<<M_ / 256, 256>>>(pairid, pos, idxv);
        // segmented fc1 (quantum-32)
        {
            dim3 grid(D2FF / 128, NSEG / 4);
            fc1_seg<<<grid, 256>>>(h, fc1 + (size_t)l * E_ * DFF_ * D_, hidc, mp,
                                   idxv, segp, segrow, segcnt);
        }
        // segmented fc2
        {
            dim3 grid(D_ / 128, NSEG / 4);
            fc2_seg<<<grid, 256>>>(hidc, fc2 + (size_t)l * E_ * D_ * DFF_, x,
                                   idxv, segp, segrow, segcnt);
        }
    }
    // lm_head via tensor cores (3-pass bf16 emulation; router-safe)
    cvt_split3<<<512, 256>>>(x, xp_h, xp_m, xp_l, (size_t)M_ * D_ / 4);
    tc_lmhead<<<dim3(V_ / 128, M_ / 128), 256, TC_SMEM>>>(
        xp_h, xp_m, xp_l, lm_h, lm_m, lm_l, out);
}

// round 10
// speedup vs baseline: 7.4420x; 1.3370x over previous
#include <cuda_runtime.h>
#include <cuda_bf16.h>
#include <math.h>
#include <stdint.h>

typedef __nv_bfloat16 bf;

// ---------------- problem constants ----------------
constexpr int B_ = 2, T_ = 1024, D_ = 768, H_ = 12, L_ = 4, E_ = 8, DFF_ = 3072, V_ = 32000;
constexpr int HEAD_ = D_ / H_;       // 64
constexpr int D3_ = 3 * D_;          // 2304
constexpr int M_ = B_ * T_;          // 2048
constexpr int NPAIR = 28;
constexpr int D2FF = 2 * DFF_;       // 6144
constexpr int NSEG = 96;
constexpr int NSLOT = NSEG * 32;     // 3072

// ---------------- scratch (static device, allocation-free) ----------------
__device__ __align__(128) float g_x[M_ * D_];
__device__ __align__(128) float g_h[M_ * D_];
__device__ __align__(128) float g_hT[D_ * M_];
__device__ __align__(128) float g_atT[D_ * M_];
__device__ __align__(128) float g_qkv[M_ * D3_];
__device__ __align__(128) float g_scores[(size_t)B_ * H_ * T_ * T_];
__device__ __align__(128) float g_hcT[(size_t)D_ * NSLOT];
__device__ __align__(128) float g_hidcT[(size_t)D2FF * NSLOT];
__device__ __align__(128) float g_mp[M_ * E_];
__device__ int g_cnt[NPAIR], g_baseo[NPAIR], g_pos[NPAIR];
__device__ int g_pairid[M_], g_idx[M_];
__device__ int g_segp[NSEG], g_segrow[NSEG], g_segcnt[NSEG], g_slottok[NSLOT];

// transposed weights ([K][N] per layer/expert)
__device__ __align__(128) float w_qkvT[(size_t)L_ * D_ * D3_];
__device__ __align__(128) float w_prT[(size_t)L_ * D_ * D_];
__device__ __align__(128) float w_f1T[(size_t)L_ * E_ * D_ * DFF_];
__device__ __align__(128) float w_f2T[(size_t)L_ * E_ * DFF_ * D_];

// bf16 planes for tensor-core lm_head
__device__ __align__(128) bf g_xp_h[M_ * D_], g_xp_m[M_ * D_], g_xp_l[M_ * D_];
__device__ __align__(128) bf w_lm_h[(size_t)V_ * D_], w_lm_m[(size_t)V_ * D_], w_lm_l[(size_t)V_ * D_];

__constant__ int c_pe1[NPAIR] = {0,0,0,0,0,0,0, 1,1,1,1,1,1, 2,2,2,2,2, 3,3,3,3, 4,4,4, 5,5, 6};
__constant__ int c_pe2[NPAIR] = {1,2,3,4,5,6,7, 2,3,4,5,6,7, 3,4,5,6,7, 4,5,6,7, 5,6,7, 6,7, 7};

// ---------------- packed f32x2 FMA (bit-exact lanes) ----------------
__device__ __forceinline__ float2 ffma2(float2 a, float2 b, float2 c) {
    unsigned long long au, bu, cu, du;
    au = *reinterpret_cast<unsigned long long*>(&a);
    bu = *reinterpret_cast<unsigned long long*>(&b);
    cu = *reinterpret_cast<unsigned long long*>(&c);
    asm("fma.rn.f32x2 %0, %1, %2, %3;" : "=l"(du) : "l"(au), "l"(bu), "l"(cu));
    return *reinterpret_cast<float2*>(&du);
}

// ---------------- PTX helpers ----------------
__device__ __forceinline__ uint32_t smem_u32(const void* p) {
    uint32_t a;
    asm("{ .reg .u64 t; cvta.to.shared.u64 t, %1; cvt.u32.u64 %0, t; }" : "=r"(a) : "l"(p));
    return a;
}
__device__ __forceinline__ void cpa16(uint32_t dst, const void* src) {
    asm volatile("cp.async.cg.shared.global [%0], [%1], 16;" :: "r"(dst), "l"(src) : "memory");
}
__device__ __forceinline__ void cpa_commit() { asm volatile("cp.async.commit_group;" ::: "memory"); }
template <int N> __device__ __forceinline__ void cpa_wait() {
    asm volatile("cp.async.wait_group %0;" :: "n"(N) : "memory");
}

// ---------------- reductions ----------------
__device__ __forceinline__ float bsum(float v, float* sred) {
#pragma unroll
    for (int o = 16; o; o >>= 1) v += __shfl_xor_sync(0xffffffffu, v, o);
    if ((threadIdx.x & 31) == 0) sred[threadIdx.x >> 5] = v;
    __syncthreads();
    float r = 0.f;
#pragma unroll
    for (int i = 0; i < 8; i++) r += sred[i];
    __syncthreads();
    return r;
}
__device__ __forceinline__ float bmax(float v, float* sred) {
#pragma unroll
    for (int o = 16; o; o >>= 1) v = fmaxf(v, __shfl_xor_sync(0xffffffffu, v, o));
    if ((threadIdx.x & 31) == 0) sred[threadIdx.x >> 5] = v;
    __syncthreads();
    float r = -3.402823e38f;
#pragma unroll
    for (int i = 0; i < 8; i++) r = fmaxf(r, sred[i]);
    __syncthreads();
    return r;
}

// ---------------- FFMA2 accumulator + inner bodies ----------------
#define GEMM_ACC_DECL                                   \
    float2 acc2[4][8];                                  \
    _Pragma("unroll")                                   \
    for (int ip = 0; ip < 4; ip++)                      \
        _Pragma("unroll")                               \
        for (int j = 0; j < 8; j++) acc2[ip][j] = make_float2(0.f, 0.f);

#define GEMM_INNER(As, Bs, trow, tcol)                                        \
    _Pragma("unroll")                                                          \
    for (int kk = 0; kk < 16; kk++) {                                          \
        float2 a2[4];                                                          \
        _Pragma("unroll")                                                      \
        for (int ip = 0; ip < 4; ip++) a2[ip] = *(const float2*)&As[kk][(trow) + 2 * ip]; \
        float4 b0 = *(const float4*)&Bs[kk][(tcol)];                           \
        float4 b1 = *(const float4*)&Bs[kk][(tcol) + 4];                       \
        float bsv[8] = {b0.x, b0.y, b0.z, b0.w, b1.x, b1.y, b1.z, b1.w};       \
        _Pragma("unroll")                                                      \
        for (int j = 0; j < 8; j++) {                                          \
            float2 bd = make_float2(bsv[j], bsv[j]);                           \
            _Pragma("unroll")                                                  \
            for (int ip = 0; ip < 4; ip++)                                     \
                acc2[ip][j] = ffma2(a2[ip], bd, acc2[ip][j]);                  \
        }                                                                      \
    }

#define PIPE_INNER(sm, aOff, bOff, trow, tcol)                                 \
    _Pragma("unroll")                                                          \
    for (int kk = 0; kk < 16; kk++) {                                          \
        float2 a2[4];                                                          \
        _Pragma("unroll")                                                      \
        for (int ip = 0; ip < 4; ip++)                                         \
            a2[ip] = *(const float2*)&sm[(aOff) + kk * 128 + (trow) + 2 * ip]; \
        float4 b0 = *(const float4*)&sm[(bOff) + kk * 128 + (tcol)];           \
        float4 b1 = *(const float4*)&sm[(bOff) + kk * 128 + (tcol) + 4];       \
        float bsv[8] = {b0.x, b0.y, b0.z, b0.w, b1.x, b1.y, b1.z, b1.w};       \
        _Pragma("unroll")                                                      \
        for (int j = 0; j < 8; j++) {                                          \
            float2 bd = make_float2(bsv[j], bsv[j]);                           \
            _Pragma("unroll")                                                  \
            for (int ip = 0; ip < 4; ip++)                                     \
                acc2[ip][j] = ffma2(a2[ip], bd, acc2[ip][j]);                  \
        }                                                                      \
    }

// ---------------- pipelined dense GEMM: C = A@B^T via transposed operands ----
// AT [K][M] (row stride ldat), BT [K][N] (row stride ldbt). 3-stage cp.async.
// MODE 0: C = acc     MODE 2: C += acc      (all dims multiples of 128/16)
template <int MODE>
__global__ void __launch_bounds__(256, 2)
gemm_pipe(const float* __restrict__ AT, const float* __restrict__ BT,
          float* __restrict__ C, int M, int N, int K, int ldat, int ldbt, int ldc)
{
    extern __shared__ float sm[];            // 3 stages x (2048 A + 2048 B) floats
    const int tid = threadIdx.x;
    const int m0 = blockIdx.y << 7, n0 = blockIdx.x << 7;
    const int NT = K >> 4;
    const int trow = (tid >> 4) << 3, tcol = (tid & 15) << 3;
    const bool isA = tid < 128;
    const int lrow = (tid & 127) >> 3;       // k-row within tile 0..15
    const int c0 = (tid & 7) << 2;           // base float col (0..28)

    GEMM_ACC_DECL

    auto issue = [&](int t) {
        int s = t % 3;
        uint32_t base = smem_u32(&sm[s * 4096 + (isA ? 0 : 2048) + lrow * 128]);
        const float* src = isA ? (AT + (size_t)(t * 16 + lrow) * ldat + m0)
                               : (BT + (size_t)(t * 16 + lrow) * ldbt + n0);
#pragma unroll
        for (int i = 0; i < 4; i++) {
            int col = c0 + i * 32;
            cpa16(base + col * 4, src + col);
        }
        cpa_commit();
    };

    issue(0); issue(1);
    for (int t = 0; t < NT; t++) {
        if (t + 1 < NT) cpa_wait<1>(); else cpa_wait<0>();
        __syncthreads();
        if (t + 2 < NT) issue(t + 2);
        int sb = (t % 3) * 4096;
        PIPE_INNER(sm, sb, sb + 2048, trow, tcol)
    }

#pragma unroll
    for (int ip = 0; ip < 4; ip++) {
#pragma unroll
        for (int sub = 0; sub < 2; sub++) {
            int m = m0 + trow + 2 * ip + sub;
#pragma unroll
            for (int j = 0; j < 8; j++) {
                int n = n0 + tcol + j;
                long ci = (long)m * ldc + n;
                float v = sub ? acc2[ip][j].y : acc2[ip][j].x;
                if (MODE == 0) C[ci] = v;
                else           C[ci] += v;
            }
        }
    }
}

// ---------------- pipelined segmented fc1 (quantum-32 slots) -----------------
// hidcT[n][slot] = mp * relu( h[slottok] . w1_e[:, n] ), n in pair col space 0..6143
__global__ void __launch_bounds__(256, 2)
fc1_pipe(const float* __restrict__ hcT, const float* __restrict__ w1T,
         float* __restrict__ hidcT, const float* __restrict__ mp,
         const int* __restrict__ slottok, const int* __restrict__ segp,
         const int* __restrict__ segcnt)
{
    extern __shared__ float sm[];            // 2 stages x (2048 A + 4*2048 B)
    const int q  = blockIdx.y;
    const int n0 = blockIdx.x << 7;
    const int tid = threadIdx.x;
    if (segcnt[q*4+0] + segcnt[q*4+1] + segcnt[q*4+2] + segcnt[q*4+3] == 0) return;

    __shared__ int s_e[4];
    __shared__ int s_tok[128];
    if (tid < 128) s_tok[tid] = slottok[q * 128 + tid];
    if (tid < 4) {
        int p = segp[q * 4 + tid];
        s_e[tid] = (n0 < DFF_) ? c_pe1[p] : c_pe2[p];
    }
    __syncthreads();

    const int nw = (n0 < DFF_) ? n0 : n0 - DFF_;
    const int trow = (tid >> 4) << 3, tcol = (tid & 15) << 3;
    const int myseg = trow >> 5;

    GEMM_ACC_DECL

    // stage = 512 A-float4 + 4*512 B-float4 = 2560 float4
    auto issue = [&](int t) {
        int s = t & 1;
        int k0 = t << 4;
#pragma unroll
        for (int c = tid; c < 2560; c += 256) {
            uint32_t dst; const float* src;
            if (c < 512) {
                int row = c >> 5, col = (c & 31) << 2;
                dst = smem_u32(&sm[s * 10240 + row * 128 + col]);
                src = hcT + (size_t)(k0 + row) * NSLOT + q * 128 + col;
            } else {
                int bt = (c - 512) >> 9, cc = (c - 512) & 511;
                int row = cc >> 5, col = (cc & 31) << 2;
                dst = smem_u32(&sm[s * 10240 + 2048 + bt * 2048 + row * 128 + col]);
                src = w1T + ((size_t)s_e[bt] * D_ + k0 + row) * DFF_ + nw + col;
            }
            cpa16(dst, src);
        }
        cpa_commit();
    };

    issue(0);
    const int NT = D_ >> 4;   // 48
    for (int t = 0; t < NT; t++) {
        cpa_wait<0>();
        __syncthreads();
        if (t + 1 < NT) issue(t + 1);
        int sb = (t & 1) * 10240;
        PIPE_INNER(sm, sb, sb + 2048 + myseg * 2048, trow, tcol)
    }

#pragma unroll
    for (int ip = 0; ip < 4; ip++) {
        int ml0 = trow + 2 * ip;
        int e = s_e[ml0 >> 5];
        float sc0 = mp[(size_t)s_tok[ml0] * E_ + e];
        float sc1 = mp[(size_t)s_tok[ml0 + 1] * E_ + e];
#pragma unroll
        for (int j = 0; j < 8; j++) {
            float2 v = acc2[ip][j];
            float2 o = make_float2(sc0 * fmaxf(v.x, 0.f), sc1 * fmaxf(v.y, 0.f));
            *(float2*)&hidcT[(size_t)(n0 + tcol + j) * NSLOT + q * 128 + ml0] = o;
        }
    }
}

// ---------------- pipelined segmented fc2: x[tok] += hid . [W_e1;W_e2] -------
__global__ void __launch_bounds__(256, 2)
fc2_pipe(const float* __restrict__ hidcT, const float* __restrict__ w2T,
         float* __restrict__ x, const int* __restrict__ slottok,
         const int* __restrict__ segp, const int* __restrict__ segcnt)
{
    extern __shared__ float sm[];
    const int q  = blockIdx.y;
    const int n0 = blockIdx.x << 7;
    const int tid = threadIdx.x;
    if (segcnt[q*4+0] + segcnt[q*4+1] + segcnt[q*4+2] + segcnt[q*4+3] == 0) return;

    __shared__ int s_e1[4], s_e2[4], s_cnt[4];
    __shared__ int s_tok[128];
    if (tid < 128) s_tok[tid] = slottok[q * 128 + tid];
    if (tid < 4) {
        int p = segp[q * 4 + tid];
        s_e1[tid] = c_pe1[p];
        s_e2[tid] = c_pe2[p];
        s_cnt[tid] = segcnt[q * 4 + tid];
    }
    __syncthreads();

    const int trow = (tid >> 4) << 3, tcol = (tid & 15) << 3;
    const int myseg = trow >> 5;

    GEMM_ACC_DECL

    auto issue = [&](int t) {
        int s = t & 1;
        int k0 = t << 4;
        int eb = (k0 >= DFF_);
        int kb = k0 - (eb ? DFF_ : 0);
#pragma unroll
        for (int c = tid; c < 2560; c += 256) {
            uint32_t dst; const float* src;
            if (c < 512) {
                int row = c >> 5, col = (c & 31) << 2;
                dst = smem_u32(&sm[s * 10240 + row * 128 + col]);
                src = hidcT + (size_t)(k0 + row) * NSLOT + q * 128 + col;
            } else {
                int bt = (c - 512) >> 9, cc = (c - 512) & 511;
                int row = cc >> 5, col = (cc & 31) << 2;
                int e = eb ? s_e2[bt] : s_e1[bt];
                dst = smem_u32(&sm[s * 10240 + 2048 + bt * 2048 + row * 128 + col]);
                src = w2T + ((size_t)e * DFF_ + kb + row) * D_ + n0 + col;
            }
            cpa16(dst, src);
        }
        cpa_commit();
    };

    issue(0);
    const int NT = D2FF >> 4;  // 384
    for (int t = 0; t < NT; t++) {
        cpa_wait<0>();
        __syncthreads();
        if (t + 1 < NT) issue(t + 1);
        int sb = (t & 1) * 10240;
        PIPE_INNER(sm, sb, sb + 2048 + myseg * 2048, trow, tcol)
    }

#pragma unroll
    for (int ip = 0; ip < 4; ip++) {
#pragma unroll
        for (int sub = 0; sub < 2; sub++) {
            int ml = trow + 2 * ip + sub;
            int seg = ml >> 5, offm = ml & 31;
            if (offm >= s_cnt[seg]) continue;
            int tok = s_tok[ml];
#pragma unroll
            for (int j = 0; j < 8; j++) {
                float v = sub ? acc2[ip][j].y : acc2[ip][j].x;
                x[(size_t)tok * D_ + n0 + tcol + j] += v;
            }
        }
    }
}

// ---------------- old synchronous GEMM (attention scores / PV only) ----------
// MODE 0: C = alpha*acc      MODE 3: C[n*ldc + m] = acc  (transposed store)
template <int MODE, bool BNT>
__global__ void __launch_bounds__(256, 2)
gemm_tile(const float* __restrict__ A, const float* __restrict__ Bw,
          float* __restrict__ C,
          int M, int N, int K, int lda, int ldb, int ldc, int ZH,
          long sAb, long sAh, long sBb, long sBh, long sCb, long sCh,
          float alpha, int causalSkip, int causalK)
{
    constexpr int BM = 128, BN = 128, BK = 16;
    if (ZH > 0) {
        int z = blockIdx.z;
        int zb = z / ZH, zh = z - zb * ZH;
        A  += zb * sAb + zh * sAh;
        Bw += zb * sBb + zh * sBh;
        C  += zb * sCb + zh * sCh;
    }
    const int n0 = blockIdx.x * BN;
    const int m0 = blockIdx.y * BM;
    if (causalSkip && n0 > m0) return;
    const int kend = causalK ? min(K, m0 + BM) : K;

    __shared__ float As[BK][BM];
    __shared__ float Bs[BK][BN];

    const int tid  = threadIdx.x;
    const int trow = (tid >> 4) << 3;
    const int tcol = (tid & 15) << 3;

    GEMM_ACC_DECL

    for (int k0 = 0; k0 < kend; k0 += BK) {
#pragma unroll
        for (int it = 0; it < 2; it++) {
            int idx = tid + it * 256;
            int r = idx >> 2;
            int c4 = (idx & 3) << 2;
            float4 v = *(const float4*)(A + (long)(m0 + r) * lda + k0 + c4);
            As[c4 + 0][r] = v.x; As[c4 + 1][r] = v.y;
            As[c4 + 2][r] = v.z; As[c4 + 3][r] = v.w;
        }
        if (BNT) {
#pragma unroll
            for (int it = 0; it < 2; it++) {
                int idx = tid + it * 256;
                int r = idx >> 2;
                int c4 = (idx & 3) << 2;
                float4 v = make_float4(0.f, 0.f, 0.f, 0.f);
                if (n0 + r < N) v = *(const float4*)(Bw + (long)(n0 + r) * ldb + k0 + c4);
                Bs[c4 + 0][r] = v.x; Bs[c4 + 1][r] = v.y;
                Bs[c4 + 2][r] = v.z; Bs[c4 + 3][r] = v.w;
            }
        } else {
#pragma unroll
            for (int it = 0; it < 2; it++) {
                int idx = tid + it * 256;
                int r = idx >> 5;
                int c4 = (idx & 31) << 2;
                float4 v = make_float4(0.f, 0.f, 0.f, 0.f);
                if (n0 + c4 + 3 < N) v = *(const float4*)(Bw + (long)(k0 + r) * ldb + n0 + c4);
                *(float4*)&Bs[r][c4] = v;
            }
        }
        __syncthreads();
        GEMM_INNER(As, Bs, trow, tcol)
        __syncthreads();
    }

#pragma unroll
    for (int ip = 0; ip < 4; ip++) {
#pragma unroll
        for (int sub = 0; sub < 2; sub++) {
            int m = m0 + trow + 2 * ip + sub;
            if (m >= M) continue;
#pragma unroll
            for (int j = 0; j < 8; j++) {
                int n = n0 + tcol + j;
                if (n >= N) continue;
                float v = sub ? acc2[ip][j].y : acc2[ip][j].x;
                if (MODE == 0) C[(long)m * ldc + n] = alpha * v;
                else           C[(long)n * ldc + m] = v;          // MODE 3
            }
        }
    }
}

// ---------------- weight transpose: src[b][N][K] -> dst[b][K][N] -------------
__global__ void transpose_kernel(const float* __restrict__ src, float* __restrict__ dst,
                                 int N, int K)
{
    __shared__ float t[32][33];
    const float* s = src + (size_t)blockIdx.z * N * K;
    float* d = dst + (size_t)blockIdx.z * N * K;
    int k0 = blockIdx.x << 5, n0 = blockIdx.y << 5;
    int tx = threadIdx.x & 31, ty = threadIdx.x >> 5;
#pragma unroll
    for (int i = 0; i < 32; i += 8)
        t[ty + i][tx] = s[(size_t)(n0 + ty + i) * K + k0 + tx];
    __syncthreads();
#pragma unroll
    for (int i = 0; i < 32; i += 8)
        d[(size_t)(k0 + ty + i) * N + n0 + tx] = t[tx][ty + i];
}

// ---------------- gather hcT[k][slot] = h[slottok[slot]][k] ------------------
__global__ void gather_hcT_kernel(const float* __restrict__ h,
                                  const int* __restrict__ slottok,
                                  float* __restrict__ hcT)
{
    int slot = blockIdx.x * 8 + (threadIdx.x >> 5);
    int lane = threadIdx.x & 31;
    int tok = slottok[slot];
    const float* hr = h + (size_t)tok * D_;
    for (int k = lane; k < D_; k += 32)
        hcT[(size_t)k * NSLOT + slot] = hr[k];
}

// ================= tensor-core lm_head =================
#define LDSM4(R, addr) \
    asm volatile("ldmatrix.sync.aligned.m8n8.x4.shared.b16 {%0,%1,%2,%3}, [%4];" \
        : "=r"((R)[0]), "=r"((R)[1]), "=r"((R)[2]), "=r"((R)[3]) : "r"(addr))
__device__ __forceinline__ void mma16816(float* c, const uint32_t* a, uint32_t b0, uint32_t b1) {
    asm volatile("mma.sync.aligned.m16n8k16.row.col.f32.bf16.bf16.f32 "
                 "{%0,%1,%2,%3}, {%4,%5,%6,%7}, {%8,%9}, {%0,%1,%2,%3};"
                 : "+f"(c[0]), "+f"(c[1]), "+f"(c[2]), "+f"(c[3])
                 : "r"(a[0]), "r"(a[1]), "r"(a[2]), "r"(a[3]), "r"(b0), "r"(b1));
}
__device__ __forceinline__ void split3(float v, bf& h, bf& m, bf& l) {
    h = __float2bfloat16(v);
    float r = v - __bfloat162float(h);
    m = __float2bfloat16(r);
    l = __float2bfloat16(r - __bfloat162float(m));
}

constexpr int ROWB = 80;
constexpr int A_BYTES = 128 * ROWB;
constexpr int STAGE_BYTES = A_BYTES * 2;
constexpr int TNST = 3;
constexpr int TC_SMEM = TNST * STAGE_BYTES;

__global__ void __launch_bounds__(256)
tc_lmhead(const bf* __restrict__ Ah, const bf* __restrict__ Am, const bf* __restrict__ Al,
          const bf* __restrict__ Bh, const bf* __restrict__ Bm, const bf* __restrict__ Bl,
          float* __restrict__ Cf)
{
    extern __shared__ __align__(128) char smemc[];
    const uint32_t sbase = smem_u32(smemc);
    const int tid  = threadIdx.x;
    const int lane = tid & 31;
    const int wid  = tid >> 5;
    const int wm   = wid & 1;
    const int wn   = wid >> 1;
    const int m0 = blockIdx.y * 128;
    const int n0 = blockIdx.x * 128;

    constexpr int KC = D_ / 32;
    constexpr int C3 = 3 * KC;

    const int lr = tid >> 2;
    const int lq = (tid & 3) << 4;

    auto load_chunk = [&](int c, int s) {
        int p = c / KC;
        int kabs = (c - p * KC) << 5;
        const bf* Ap = Ah;
        const bf* Bp = Bh;
        if (p == 1) { Bp = Bm; }
        if (p == 2) { Ap = Am; }
        uint32_t sA = sbase + (uint32_t)s * STAGE_BYTES;
        uint32_t sB = sA + A_BYTES;
#pragma unroll
        for (int i = 0; i < 2; i++) {
            int r = lr + (i << 6);
            cpa16(sA + r * ROWB + lq, Ap + (size_t)(m0 + r) * D_ + kabs + (lq >> 1));
        }
#pragma unroll
        for (int i = 0; i < 2; i++) {
            int r = lr + (i << 6);
            cpa16(sB + r * ROWB + lq, Bp + (size_t)(n0 + r) * D_ + kabs + (lq >> 1));
        }
        cpa_commit();
    };

    float acc[4][4][4];
#pragma unroll
    for (int i = 0; i < 4; i++)
#pragma unroll
        for (int j = 0; j < 4; j++)
#pragma unroll
            for (int qq = 0; qq < 4; qq++) acc[i][j][qq] = 0.f;

    const int arow = (lane & 7) + ((lane >> 3) & 1) * 8;
    const int akh  = (lane >> 4) & 1;
    const int brow = (lane & 7) + ((lane >> 4) & 1) * 8;
    const int bkh  = (lane >> 3) & 1;

    load_chunk(0, 0);
    load_chunk(1, 1);

    for (int c = 0; c < C3; ++c) {
        int s = c % TNST;
        if (c + 1 < C3) cpa_wait<1>(); else cpa_wait<0>();
        __syncthreads();
        if (c + 2 < C3) load_chunk(c + 2, (c + 2) % TNST);

        uint32_t sA = sbase + (uint32_t)s * STAGE_BYTES;
        uint32_t sB = sA + A_BYTES;
        uint32_t aAddr = sA + (wm * 64 + arow) * ROWB + akh * 16;
        uint32_t bAddr = sB + (wn * 32 + brow) * ROWB + bkh * 16;

#pragma unroll
        for (int kc = 0; kc < 2; kc++) {
            uint32_t af[4][4], bfm[2][4];
#pragma unroll
            for (int ms = 0; ms < 4; ms++) LDSM4(af[ms], aAddr + ms * (16 * ROWB) + kc * 32);
#pragma unroll
            for (int np = 0; np < 2; np++) LDSM4(bfm[np], bAddr + np * (16 * ROWB) + kc * 32);
#pragma unroll
            for (int i = 0; i < 4; i++)
#pragma unroll
                for (int j = 0; j < 4; j++)
                    mma16816(acc[i][j], af[i], bfm[j >> 1][(j & 1) * 2], bfm[j >> 1][(j & 1) * 2 + 1]);
        }
    }

    const int tg  = lane >> 2;
    const int tc2 = (lane & 3) << 1;
#pragma unroll
    for (int i = 0; i < 4; i++) {
        int r0 = m0 + wm * 64 + i * 16 + tg;
        int r1 = r0 + 8;
#pragma unroll
        for (int j = 0; j < 4; j++) {
            int cb = n0 + wn * 32 + j * 8 + tc2;
            float* a4 = acc[i][j];
            *(float2*)(Cf + (size_t)r0 * V_ + cb) = make_float2(a4[0], a4[1]);
            *(float2*)(Cf + (size_t)r1 * V_ + cb) = make_float2(a4[2], a4[3]);
        }
    }
}

// ---------------- fp32 -> 3x bf16 planes ----------------
__global__ void cvt_split3(const float* __restrict__ x, bf* __restrict__ hi,
                           bf* __restrict__ mi, bf* __restrict__ lo, size_t n4)
{
    size_t i = (size_t)blockIdx.x * blockDim.x + threadIdx.x;
    size_t stride = (size_t)gridDim.x * blockDim.x;
    for (; i < n4; i += stride) {
        float4 v = ((const float4*)x)[i];
        bf h[4], m[4], l[4];
        split3(v.x, h[0], m[0], l[0]); split3(v.y, h[1], m[1], l[1]);
        split3(v.z, h[2], m[2], l[2]); split3(v.w, h[3], m[3], l[3]);
        ((__nv_bfloat162*)hi)[i * 2 + 0] = __halves2bfloat162(h[0], h[1]);
        ((__nv_bfloat162*)hi)[i * 2 + 1] = __halves2bfloat162(h[2], h[3]);
        ((__nv_bfloat162*)mi)[i * 2 + 0] = __halves2bfloat162(m[0], m[1]);
        ((__nv_bfloat162*)mi)[i * 2 + 1] = __halves2bfloat162(m[2], m[3]);
        ((__nv_bfloat162*)lo)[i * 2 + 0] = __halves2bfloat162(l[0], l[1]);
        ((__nv_bfloat162*)lo)[i * 2 + 1] = __halves2bfloat162(l[2], l[3]);
    }
}

// ---------------- embedding + LN0 ----------------
__global__ void embed_ln_kernel(const int* __restrict__ tokens,
                                const float* __restrict__ wte, const float* __restrict__ wpe,
                                const float* __restrict__ g, const float* __restrict__ b,
                                float* __restrict__ y)
{
    __shared__ float sred[8];
    long row = blockIdx.x;
    int t = (int)(row % T_);
    int tok = tokens[row];
    const float* we = wte + (long)tok * D_;
    const float* pe = wpe + (long)t * D_;
    float* yr = y + row * D_;
    int tid = threadIdx.x;
    float v[3], s = 0.f;
#pragma unroll
    for (int i = 0; i < 3; i++) { int c = tid + i * 256; v[i] = we[c] + pe[c]; s += v[i]; }
    s = bsum(s, sred);
    float mu = s * (1.f / D_);
    float q = 0.f;
#pragma unroll
    for (int i = 0; i < 3; i++) { float d = v[i] - mu; q += d * d; }
    q = bsum(q, sred);
    float rstd = rsqrtf(q * (1.f / D_) + 1e-5f);
#pragma unroll
    for (int i = 0; i < 3; i++) { int c = tid + i * 256; yr[c] = (v[i] - mu) * rstd * g[c] + b[c]; }
}

// ---------------- LayerNorm (+ optional transposed copy) ----------------
__global__ void ln_kernel(const float* __restrict__ x, float* __restrict__ y,
                          float* __restrict__ yT,
                          const float* __restrict__ g, const float* __restrict__ b)
{
    __shared__ float sred[8];
    long row = blockIdx.x;
    const float* xr = x + row * D_;
    int tid = threadIdx.x;
    float v[3], s = 0.f;
#pragma unroll
    for (int i = 0; i < 3; i++) { v[i] = xr[tid + i * 256]; s += v[i]; }
    s = bsum(s, sred);
    float mu = s * (1.f / D_);
    float q = 0.f;
#pragma unroll
    for (int i = 0; i < 3; i++) { float d = v[i] - mu; q += d * d; }
    q = bsum(q, sred);
    float rstd = rsqrtf(q * (1.f / D_) + 1e-5f);
#pragma unroll
    for (int i = 0; i < 3; i++) {
        int c = tid + i * 256;
        float o = (v[i] - mu) * rstd * g[c] + b[c];
        y[row * D_ + c] = o;
        if (yT) yT[(size_t)c * M_ + row] = o;
    }
}

// ---------------- causal softmax ----------------
__global__ void softmax_kernel(float* __restrict__ sc)
{
    __shared__ float sred[8];
    long row = blockIdx.x;
    int i = (int)(row & (T_ - 1));
    float* r = sc + row * (long)T_;
    int tid = threadIdx.x;
    int n = i + 1;
    float rv[4];
    float mx = -3.402823e38f;
#pragma unroll
    for (int p = 0; p < 4; p++) { int j = tid + p * 256; if (j < n) { rv[p] = r[j]; mx = fmaxf(mx, rv[p]); } }
    mx = bmax(mx, sred);
    float s = 0.f;
#pragma unroll
    for (int p = 0; p < 4; p++) { int j = tid + p * 256; if (j < n) { rv[p] = __expf(rv[p] - mx); s += rv[p]; } }
    s = bsum(s, sred);
    float inv = 1.f / s;
    int zend = ((i >> 7) + 1) << 7;
#pragma unroll
    for (int p = 0; p < 4; p++) {
        int j = tid + p * 256;
        if (j < n) r[j] = rv[p] * inv;
        else if (j < zend) r[j] = 0.f;
    }
}

// ---------------- router + binning ----------------
__global__ void zero_cnt_kernel(int* cnt) { if (threadIdx.x < NPAIR) cnt[threadIdx.x] = 0; }

__global__ void router_kernel(const float* __restrict__ h, const float* __restrict__ rw,
                              float* __restrict__ mp, int* __restrict__ pairid,
                              int* __restrict__ cnt)
{
    __shared__ float sc[E_];
    long tok = blockIdx.x;
    int tid = threadIdx.x;
    int w = tid >> 5, lane = tid & 31;
    const float* hr = h + tok * D_;
    const float* we = rw + (long)w * D_;
    float s = 0.f;
    for (int k = lane; k < D_; k += 32) s += hr[k] * we[k];
#pragma unroll
    for (int o = 16; o; o >>= 1) s += __shfl_xor_sync(0xffffffffu, s, o);
    if (lane == 0) sc[w] = s;
    __syncthreads();
    if (tid == 0) {
        float mx = sc[0];
#pragma unroll
        for (int e = 1; e < E_; e++) mx = fmaxf(mx, sc[e]);
        float p[E_], sum = 0.f;
#pragma unroll
        for (int e = 0; e < E_; e++) { p[e] = __expf(sc[e] - mx); sum += p[e]; }
        int i1 = 0;
#pragma unroll
        for (int e = 1; e < E_; e++) if (sc[e] > sc[i1]) i1 = e;
        int i2 = -1;
#pragma unroll
        for (int e = 0; e < E_; e++) if (e != i1 && (i2 < 0 || sc[e] > sc[i2])) i2 = e;
        float p1 = p[i1] / sum, p2 = p[i2] / sum;
        float inv = 1.f / (p1 + p2 + 1e-8f);
#pragma unroll
        for (int e = 0; e < E_; e++) mp[tok * E_ + e] = 0.f;
        mp[tok * E_ + i1] = p1 * inv;
        mp[tok * E_ + i2] = p2 * inv;
        int a = i1 < i2 ? i1 : i2;
        int bx = i1 < i2 ? i2 : i1;
        int pid = a * E_ - a * (a + 1) / 2 + (bx - a - 1);
        pairid[tok] = pid;
        atomicAdd(&cnt[pid], 1);
    }
}

__global__ void prefix_kernel(const int* __restrict__ cnt, int* __restrict__ baseo,
                              int* __restrict__ pos, int* __restrict__ segp,
                              int* __restrict__ segrow, int* __restrict__ segcnt)
{
    if (threadIdx.x == 0) {
        int s = 0;
        for (int p = 0; p < NPAIR; p++) { baseo[p] = s; pos[p] = s; s += cnt[p]; }
        int ns = 0;
        for (int p = 0; p < NPAIR; p++) {
            int c = cnt[p];
            for (int o = 0; o < c; o += 32) {
                segp[ns] = p; segrow[ns] = baseo[p] + o;
                segcnt[ns] = (c - o < 32) ? (c - o) : 32;
                ns++;
            }
        }
        for (; ns < NSEG; ns++) { segp[ns] = 0; segrow[ns] = 0; segcnt[ns] = 0; }
    }
}

__global__ void scatter_kernel(const int* __restrict__ pairid, int* __restrict__ pos,
                               int* __restrict__ idxv)
{
    int t = blockIdx.x * 256 + threadIdx.x;
    if (t < M_) {
        int p = pairid[t];
        int slot = atomicAdd(&pos[p], 1);
        idxv[slot] = t;
    }
}

__global__ void slotmap_kernel(const int* __restrict__ segrow, const int* __restrict__ segcnt,
                               const int* __restrict__ idxv, int* __restrict__ slottok)
{
    int slot = blockIdx.x * 256 + threadIdx.x;
    if (slot >= NSLOT) return;
    int s = slot >> 5, o = slot & 31, c = segcnt[s];
    int oo = (o < c) ? o : (c > 0 ? c - 1 : 0);
    slottok[slot] = (c > 0) ? idxv[segrow[s] + oo] : 0;
}

// ---------------- host side ----------------
template <class T>
static T* sym(const void* s) { void* p = nullptr; cudaGetSymbolAddress(&p, s); return (T*)p; }

extern "C" void kernel_launch(void* const* d_in, const int* in_sizes, int n_in,
                              void* d_out, int out_size)
{
    const int*   tokens  = (const int*)d_in[0];
    const float* wte     = (const float*)d_in[1];
    const float* wpe     = (const float*)d_in[2];
    const float* n0g     = (const float*)d_in[3];
    const float* n0b     = (const float*)d_in[4];
    const float* n1g     = (const float*)d_in[5];
    const float* n1b     = (const float*)d_in[6];
    const float* n2g     = (const float*)d_in[7];
    const float* n2b     = (const float*)d_in[8];
    const float* qkvw    = (const float*)d_in[9];
    const float* projw   = (const float*)d_in[10];
    const float* routerw = (const float*)d_in[11];
    const float* fc1     = (const float*)d_in[12];
    const float* fc2     = (const float*)d_in[13];
    const float* lmw     = (const float*)d_in[14];
    float* out = (float*)d_out;

    float* x     = sym<float>(g_x);
    float* h     = sym<float>(g_h);
    float* hT    = sym<float>(g_hT);
    float* atT   = sym<float>(g_atT);
    float* qkv   = sym<float>(g_qkv);
    float* scs   = sym<float>(g_scores);
    float* hcT   = sym<float>(g_hcT);
    float* hidcT = sym<float>(g_hidcT);
    float* mp    = sym<float>(g_mp);
    int* cnt    = sym<int>(g_cnt);
    int* baseo  = sym<int>(g_baseo);
    int* pos    = sym<int>(g_pos);
    int* pairid = sym<int>(g_pairid);
    int* idxv   = sym<int>(g_idx);
    int* segp   = sym<int>(g_segp);
    int* segrow = sym<int>(g_segrow);
    int* segcnt = sym<int>(g_segcnt);
    int* slottok = sym<int>(g_slottok);
    float* qkvT = sym<float>(w_qkvT);
    float* prT  = sym<float>(w_prT);
    float* f1T  = sym<float>(w_f1T);
    float* f2T  = sym<float>(w_f2T);
    bf* xp_h = sym<bf>(g_xp_h); bf* xp_m = sym<bf>(g_xp_m); bf* xp_l = sym<bf>(g_xp_l);
    bf* lm_h = sym<bf>(w_lm_h); bf* lm_m = sym<bf>(w_lm_m); bf* lm_l = sym<bf>(w_lm_l);

    cudaFuncSetAttribute(gemm_pipe<0>, cudaFuncAttributeMaxDynamicSharedMemorySize, 49152);
    cudaFuncSetAttribute(gemm_pipe<2>, cudaFuncAttributeMaxDynamicSharedMemorySize, 49152);
    cudaFuncSetAttribute(fc1_pipe, cudaFuncAttributeMaxDynamicSharedMemorySize, 81920);
    cudaFuncSetAttribute(fc2_pipe, cudaFuncAttributeMaxDynamicSharedMemorySize, 81920);
    cudaFuncSetAttribute(tc_lmhead, cudaFuncAttributeMaxDynamicSharedMemorySize, TC_SMEM);

    // ---- once-per-launch weight prep ----
    transpose_kernel<<<dim3(D_ / 32, D3_ / 32, L_), 256>>>(qkvw, qkvT, D3_, D_);
    transpose_kernel<<<dim3(D_ / 32, D_ / 32, L_), 256>>>(projw, prT, D_, D_);
    transpose_kernel<<<dim3(D_ / 32, DFF_ / 32, L_ * E_), 256>>>(fc1, f1T, DFF_, D_);
    transpose_kernel<<<dim3(DFF_ / 32, D_ / 32, L_ * E_), 256>>>(fc2, f2T, D_, DFF_);
    cvt_split3<<<2048, 256>>>(lmw, lm_h, lm_m, lm_l, (size_t)V_ * D_ / 4);

    embed_ln_kernel<<<M_, 256>>>(tokens, wte, wpe, n0g, n0b, x);

    for (int l = 0; l < L_; l++) {
        ln_kernel<<<M_, 256>>>(x, h, hT, n1g + l * D_, n1b + l * D_);
        // QKV (pipelined)
        gemm_pipe<0><<<dim3(D3_ / 128, M_ / 128), 256, 49152>>>(
            hT, qkvT + (size_t)l * D_ * D3_, qkv, M_, D3_, D_, M_, D3_, D3_);
        // scores (causal skip)
        {
            dim3 grid(T_ / 128, T_ / 128, B_ * H_);
            gemm_tile<0, true><<<grid, 256>>>(
                qkv, qkv + D_, scs,
                T_, T_, HEAD_, D3_, D3_, T_, H_,
                (long)T_ * D3_, HEAD_, (long)T_ * D3_, HEAD_,
                (long)H_ * T_ * T_, (long)T_ * T_,
                0.125f, 1, 0);
        }
        softmax_kernel<<<B_ * H_ * T_, 256>>>(scs);
        // PV -> atT (transposed store), K truncated at causal tile boundary
        {
            dim3 grid(1, T_ / 128, B_ * H_);
            gemm_tile<3, false><<<grid, 256>>>(
                scs, qkv + 2 * D_, atT,
                T_, HEAD_, T_, T_, D3_, M_, H_,
                (long)H_ * T_ * T_, (long)T_ * T_, (long)T_ * D3_, HEAD_,
                (long)T_, (long)HEAD_ * M_,
                1.f, 0, 1);
        }
        // x += attn @ proj^T (pipelined)
        gemm_pipe<2><<<dim3(D_ / 128, M_ / 128), 256, 49152>>>(
            atT, prT + (size_t)l * D_ * D_, x, M_, D_, D_, M_, D_, D_);
        // LN2 (row-major only)
        ln_kernel<<<M_, 256>>>(x, h, nullptr, n2g + l * D_, n2b + l * D_);
        // router + binning + slot build + gather
        zero_cnt_kernel<<<1, 32>>>(cnt);
        router_kernel<<<M_, 256>>>(h, routerw + (long)l * E_ * D_, mp, pairid, cnt);
        prefix_kernel<<<1, 32>>>(cnt, baseo, pos, segp, segrow, segcnt);
        scatter_kernel<<<M_ / 256, 256>>>(pairid, pos, idxv);
        slotmap_kernel<<<NSLOT / 256, 256>>>(segrow, segcnt, idxv, slottok);
        gather_hcT_kernel<<<NSLOT / 8, 256>>>(h, slottok, hcT);
        // fc1 (pipelined, quantum-32)
        fc1_pipe<<<dim3(D2FF / 128, NSEG / 4), 256, 81920>>>(
            hcT, f1T + (size_t)l * E_ * D_ * DFF_, hidcT, mp, slottok, segp, segcnt);
        // fc2 (pipelined)
        fc2_pipe<<<dim3(D_ / 128, NSEG / 4), 256, 81920>>>(
            hidcT, f2T + (size_t)l * E_ * DFF_ * D_, x, slottok, segp, segcnt);
    }
    // lm_head (tensor cores, 3-pass)
    cvt_split3<<<512, 256>>>(x, xp_h, xp_m, xp_l, (size_t)M_ * D_ / 4);
    tc_lmhead<<<dim3(V_ / 128, M_ / 128), 256, TC_SMEM>>>(
        xp_h, xp_m, xp_l, lm_h, lm_m, lm_l, out);
}

// round 13
// speedup vs baseline: 7.7708x; 1.0442x over previous
#include <cuda_runtime.h>
#include <cuda_bf16.h>
#include <math.h>
#include <stdint.h>

typedef __nv_bfloat16 bf;

// ---------------- problem constants ----------------
constexpr int B_ = 2, T_ = 1024, D_ = 768, H_ = 12, L_ = 4, E_ = 8, DFF_ = 3072, V_ = 32000;
constexpr int HEAD_ = D_ / H_;       // 64
constexpr int D3_ = 3 * D_;          // 2304
constexpr int M_ = B_ * T_;          // 2048
constexpr int NPAIR = 28;
constexpr int D2FF = 2 * DFF_;       // 6144
constexpr int NSEG = 96;
constexpr int NSLOT = NSEG * 32;     // 3072
constexpr int ZH_ = B_ * H_;         // 24

// ---------------- scratch (static device, allocation-free) ----------------
__device__ __align__(128) float g_x[M_ * D_];
__device__ __align__(128) float g_h[M_ * D_];
__device__ __align__(128) float g_hT[D_ * M_];
__device__ __align__(128) float g_atT[D_ * M_];
__device__ __align__(128) float g_qkv[M_ * D3_];
__device__ __align__(128) float g_qkT[(size_t)2 * ZH_ * HEAD_ * T_];   // [part][z][k][t]
__device__ __align__(128) float g_scores[(size_t)ZH_ * T_ * T_];
__device__ __align__(128) float g_hcT[(size_t)D_ * NSLOT];
__device__ __align__(128) float g_hidcT[(size_t)D2FF * NSLOT];
__device__ __align__(128) float g_mp[M_ * E_];
__device__ int g_cnt[NPAIR], g_baseo[NPAIR], g_pos[NPAIR];
__device__ int g_pairid[M_], g_idx[M_];
__device__ int g_segp[NSEG], g_segrow[NSEG], g_segcnt[NSEG], g_slottok[NSLOT];

// transposed weights ([K][N] per layer/expert)
__device__ __align__(128) float w_qkvT[(size_t)L_ * D_ * D3_];
__device__ __align__(128) float w_prT[(size_t)L_ * D_ * D_];
__device__ __align__(128) float w_f1T[(size_t)L_ * E_ * D_ * DFF_];
__device__ __align__(128) float w_f2T[(size_t)L_ * E_ * DFF_ * D_];

// bf16 planes for tensor-core lm_head
__device__ __align__(128) bf g_xp_h[M_ * D_], g_xp_m[M_ * D_], g_xp_l[M_ * D_];
__device__ __align__(128) bf w_lm_h[(size_t)V_ * D_], w_lm_m[(size_t)V_ * D_], w_lm_l[(size_t)V_ * D_];

__constant__ int c_pe1[NPAIR] = {0,0,0,0,0,0,0, 1,1,1,1,1,1, 2,2,2,2,2, 3,3,3,3, 4,4,4, 5,5, 6};
__constant__ int c_pe2[NPAIR] = {1,2,3,4,5,6,7, 2,3,4,5,6,7, 3,4,5,6,7, 4,5,6,7, 5,6,7, 6,7, 7};

// ---------------- packed f32x2 FMA (bit-exact lanes) ----------------
__device__ __forceinline__ float2 ffma2(float2 a, float2 b, float2 c) {
    unsigned long long au, bu, cu, du;
    au = *reinterpret_cast<unsigned long long*>(&a);
    bu = *reinterpret_cast<unsigned long long*>(&b);
    cu = *reinterpret_cast<unsigned long long*>(&c);
    asm("fma.rn.f32x2 %0, %1, %2, %3;" : "=l"(du) : "l"(au), "l"(bu), "l"(cu));
    return *reinterpret_cast<float2*>(&du);
}

// ---------------- PTX helpers ----------------
__device__ __forceinline__ uint32_t smem_u32(const void* p) {
    uint32_t a;
    asm("{ .reg .u64 t; cvta.to.shared.u64 t, %1; cvt.u32.u64 %0, t; }" : "=r"(a) : "l"(p));
    return a;
}
__device__ __forceinline__ void cpa16(uint32_t dst, const void* src) {
    asm volatile("cp.async.cg.shared.global [%0], [%1], 16;" :: "r"(dst), "l"(src) : "memory");
}
__device__ __forceinline__ void cpa_commit() { asm volatile("cp.async.commit_group;" ::: "memory"); }
template <int N> __device__ __forceinline__ void cpa_wait() {
    asm volatile("cp.async.wait_group %0;" :: "n"(N) : "memory");
}

// ---------------- reductions ----------------
__device__ __forceinline__ float bsum(float v, float* sred) {
#pragma unroll
    for (int o = 16; o; o >>= 1) v += __shfl_xor_sync(0xffffffffu, v, o);
    if ((threadIdx.x & 31) == 0) sred[threadIdx.x >> 5] = v;
    __syncthreads();
    float r = 0.f;
#pragma unroll
    for (int i = 0; i < 8; i++) r += sred[i];
    __syncthreads();
    return r;
}
__device__ __forceinline__ float bmax(float v, float* sred) {
#pragma unroll
    for (int o = 16; o; o >>= 1) v = fmaxf(v, __shfl_xor_sync(0xffffffffu, v, o));
    if ((threadIdx.x & 31) == 0) sred[threadIdx.x >> 5] = v;
    __syncthreads();
    float r = -3.402823e38f;
#pragma unroll
    for (int i = 0; i < 8; i++) r = fmaxf(r, sred[i]);
    __syncthreads();
    return r;
}

// ---------------- FFMA2 accumulator + inner bodies ----------------
#define GEMM_ACC_DECL                                   \
    float2 acc2[4][8];                                  \
    _Pragma("unroll")                                   \
    for (int ip = 0; ip < 4; ip++)                      \
        _Pragma("unroll")                               \
        for (int j = 0; j < 8; j++) acc2[ip][j] = make_float2(0.f, 0.f);

#define PIPE_INNER(sm, aOff, bOff, trow, tcol)                                 \
    _Pragma("unroll")                                                          \
    for (int kk = 0; kk < 16; kk++) {                                          \
        float2 a2[4];                                                          \
        _Pragma("unroll")                                                      \
        for (int ip = 0; ip < 4; ip++)                                         \
            a2[ip] = *(const float2*)&sm[(aOff) + kk * 128 + (trow) + 2 * ip]; \
        float4 b0 = *(const float4*)&sm[(bOff) + kk * 128 + (tcol)];           \
        float4 b1 = *(const float4*)&sm[(bOff) + kk * 128 + (tcol) + 4];       \
        float bsv[8] = {b0.x, b0.y, b0.z, b0.w, b1.x, b1.y, b1.z, b1.w};       \
        _Pragma("unroll")                                                      \
        for (int j = 0; j < 8; j++) {                                          \
            float2 bd = make_float2(bsv[j], bsv[j]);                           \
            _Pragma("unroll")                                                  \
            for (int ip = 0; ip < 4; ip++)                                     \
                acc2[ip][j] = ffma2(a2[ip], bd, acc2[ip][j]);                  \
        }                                                                      \
    }

// ---------------- pipelined dense GEMM: C = A@B^T via transposed operands ----
// AT [K][M] (row stride ldat), BT [K][N] (row stride ldbt). 3-stage cp.async.
// MODE 0: C = acc     MODE 2: C += acc
template <int MODE>
__global__ void __launch_bounds__(256, 2)
gemm_pipe(const float* __restrict__ AT, const float* __restrict__ BT,
          float* __restrict__ C, int M, int N, int K, int ldat, int ldbt, int ldc)
{
    extern __shared__ float sm[];
    const int tid = threadIdx.x;
    const int m0 = blockIdx.y << 7, n0 = blockIdx.x << 7;
    const int NT = K >> 4;
    const int trow = (tid >> 4) << 3, tcol = (tid & 15) << 3;
    const bool isA = tid < 128;
    const int lrow = (tid & 127) >> 3;
    const int c0 = (tid & 7) << 2;

    GEMM_ACC_DECL

    auto issue = [&](int t) {
        int s = t % 3;
        uint32_t base = smem_u32(&sm[s * 4096 + (isA ? 0 : 2048) + lrow * 128]);
        const float* src = isA ? (AT + (size_t)(t * 16 + lrow) * ldat + m0)
                               : (BT + (size_t)(t * 16 + lrow) * ldbt + n0);
#pragma unroll
        for (int i = 0; i < 4; i++) {
            int col = c0 + i * 32;
            cpa16(base + col * 4, src + col);
        }
        cpa_commit();
    };

    issue(0); issue(1);
    for (int t = 0; t < NT; t++) {
        if (t + 1 < NT) cpa_wait<1>(); else cpa_wait<0>();
        __syncthreads();
        if (t + 2 < NT) issue(t + 2);
        int sb = (t % 3) * 4096;
        PIPE_INNER(sm, sb, sb + 2048, trow, tcol)
    }

#pragma unroll
    for (int ip = 0; ip < 4; ip++) {
#pragma unroll
        for (int sub = 0; sub < 2; sub++) {
            int m = m0 + trow + 2 * ip + sub;
#pragma unroll
            for (int j = 0; j < 8; j++) {
                int n = n0 + tcol + j;
                long ci = (long)m * ldc + n;
                float v = sub ? acc2[ip][j].y : acc2[ip][j].x;
                if (MODE == 0) C[ci] = v;
                else           C[ci] += v;
            }
        }
    }
}

// ---------------- pipelined attention scores: scs = 0.125 * Q K^T ------------
// qT/kT: [z][64][T].  Causal tile-skip.
__global__ void __launch_bounds__(256, 2)
scores_pipe(const float* __restrict__ qkT, float* __restrict__ scs)
{
    extern __shared__ float sm[];
    const int z = blockIdx.z;
    const int m0 = blockIdx.y << 7, n0 = blockIdx.x << 7;
    if (n0 > m0) return;
    const float* AT = qkT + (size_t)z * HEAD_ * T_;
    const float* BT = qkT + (size_t)(ZH_ + z) * HEAD_ * T_;
    float* C = scs + (size_t)z * T_ * T_;

    const int tid = threadIdx.x;
    const int trow = (tid >> 4) << 3, tcol = (tid & 15) << 3;
    const bool isA = tid < 128;
    const int lrow = (tid & 127) >> 3;
    const int c0 = (tid & 7) << 2;

    GEMM_ACC_DECL

    auto issue = [&](int t) {
        int s = t % 3;
        uint32_t base = smem_u32(&sm[s * 4096 + (isA ? 0 : 2048) + lrow * 128]);
        const float* src = isA ? (AT + (size_t)(t * 16 + lrow) * T_ + m0)
                               : (BT + (size_t)(t * 16 + lrow) * T_ + n0);
#pragma unroll
        for (int i = 0; i < 4; i++) {
            int col = c0 + i * 32;
            cpa16(base + col * 4, src + col);
        }
        cpa_commit();
    };

    constexpr int NT = HEAD_ / 16;   // 4
    issue(0); issue(1);
    for (int t = 0; t < NT; t++) {
        if (t + 1 < NT) cpa_wait<1>(); else cpa_wait<0>();
        __syncthreads();
        if (t + 2 < NT) issue(t + 2);
        int sb = (t % 3) * 4096;
        PIPE_INNER(sm, sb, sb + 2048, trow, tcol)
    }

#pragma unroll
    for (int ip = 0; ip < 4; ip++) {
#pragma unroll
        for (int sub = 0; sub < 2; sub++) {
            int m = m0 + trow + 2 * ip + sub;
#pragma unroll
            for (int j = 0; j < 8; j++) {
                int n = n0 + tcol + j;
                float v = sub ? acc2[ip][j].y : acc2[ip][j].x;
                C[(size_t)m * T_ + n] = 0.125f * v;
            }
        }
    }
}

// ---------------- PV: 64x64 tiles, 128 threads; atT[n][m] store --------------
__global__ void __launch_bounds__(128, 4)
pv_tile(const float* __restrict__ scs, const float* __restrict__ qkv,
        float* __restrict__ atT)
{
    const int z = blockIdx.z, zb = z / H_, zh = z - zb * H_;
    const int m0 = blockIdx.y << 6;
    const float* A = scs + (size_t)z * T_ * T_;
    const float* Bv = qkv + ((size_t)zb * T_) * D3_ + 2 * D_ + zh * HEAD_;
    float* C = atT + (size_t)zh * HEAD_ * M_ + (size_t)zb * T_;
    const int kend = m0 + 64;                 // causal truncation (zeros beyond are exact no-ops)

    __shared__ float As[16][64];
    __shared__ float Bs[16][64];
    const int tid = threadIdx.x;
    const int trow = (tid >> 3) << 2;         // 0..60
    const int tcol = (tid & 7) << 3;          // 0..56

    float2 acc2[2][8];
#pragma unroll
    for (int ip = 0; ip < 2; ip++)
#pragma unroll
        for (int j = 0; j < 8; j++) acc2[ip][j] = make_float2(0.f, 0.f);

    for (int k0 = 0; k0 < kend; k0 += 16) {
#pragma unroll
        for (int it = 0; it < 2; it++) {      // A: 64 rows x 16, transpose into As[k][m]
            int idx = tid + it * 128;
            int r = idx >> 2, c4 = (idx & 3) << 2;
            float4 v = *(const float4*)(A + (size_t)(m0 + r) * T_ + k0 + c4);
            As[c4 + 0][r] = v.x; As[c4 + 1][r] = v.y;
            As[c4 + 2][r] = v.z; As[c4 + 3][r] = v.w;
        }
#pragma unroll
        for (int it = 0; it < 2; it++) {      // B: 16 rows(k) x 64 cols(n)
            int idx = tid + it * 128;
            int r = idx >> 4, c4 = (idx & 15) << 2;
            float4 v = *(const float4*)(Bv + (size_t)(k0 + r) * D3_ + c4);
            *(float4*)&Bs[r][c4] = v;
        }
        __syncthreads();
#pragma unroll
        for (int kk = 0; kk < 16; kk++) {
            float2 a2[2];
            a2[0] = *(const float2*)&As[kk][trow];
            a2[1] = *(const float2*)&As[kk][trow + 2];
            float4 b0 = *(const float4*)&Bs[kk][tcol];
            float4 b1 = *(const float4*)&Bs[kk][tcol + 4];
            float bsv[8] = {b0.x, b0.y, b0.z, b0.w, b1.x, b1.y, b1.z, b1.w};
#pragma unroll
            for (int j = 0; j < 8; j++) {
                float2 bd = make_float2(bsv[j], bsv[j]);
#pragma unroll
                for (int ip = 0; ip < 2; ip++)
                    acc2[ip][j] = ffma2(a2[ip], bd, acc2[ip][j]);
            }
        }
        __syncthreads();
    }

#pragma unroll
    for (int ip = 0; ip < 2; ip++) {
#pragma unroll
        for (int sub = 0; sub < 2; sub++) {
            int m = m0 + trow + 2 * ip + sub;
#pragma unroll
            for (int j = 0; j < 8; j++) {
                int n = tcol + j;
                float v = sub ? acc2[ip][j].y : acc2[ip][j].x;
                C[(size_t)n * M_ + m] = v;
            }
        }
    }
}

// ---------------- pipelined segmented fc1 (quantum-32 slots) -----------------
__global__ void __launch_bounds__(256, 2)
fc1_pipe(const float* __restrict__ hcT, const float* __restrict__ w1T,
         float* __restrict__ hidcT, const float* __restrict__ mp,
         const int* __restrict__ slottok, const int* __restrict__ segp,
         const int* __restrict__ segcnt)
{
    extern __shared__ float sm[];
    const int q  = blockIdx.y;
    const int n0 = blockIdx.x << 7;
    const int tid = threadIdx.x;
    if (segcnt[q*4+0] + segcnt[q*4+1] + segcnt[q*4+2] + segcnt[q*4+3] == 0) return;

    __shared__ int s_e[4];
    __shared__ int s_tok[128];
    if (tid < 128) s_tok[tid] = slottok[q * 128 + tid];
    if (tid < 4) {
        int p = segp[q * 4 + tid];
        s_e[tid] = (n0 < DFF_) ? c_pe1[p] : c_pe2[p];
    }
    __syncthreads();

    const int nw = (n0 < DFF_) ? n0 : n0 - DFF_;
    const int trow = (tid >> 4) << 3, tcol = (tid & 15) << 3;
    const int myseg = trow >> 5;

    GEMM_ACC_DECL

    auto issue = [&](int t) {
        int s = t & 1;
        int k0 = t << 4;
#pragma unroll
        for (int c = tid; c < 2560; c += 256) {
            uint32_t dst; const float* src;
            if (c < 512) {
                int row = c >> 5, col = (c & 31) << 2;
                dst = smem_u32(&sm[s * 10240 + row * 128 + col]);
                src = hcT + (size_t)(k0 + row) * NSLOT + q * 128 + col;
            } else {
                int bt = (c - 512) >> 9, cc = (c - 512) & 511;
                int row = cc >> 5, col = (cc & 31) << 2;
                dst = smem_u32(&sm[s * 10240 + 2048 + bt * 2048 + row * 128 + col]);
                src = w1T + ((size_t)s_e[bt] * D_ + k0 + row) * DFF_ + nw + col;
            }
            cpa16(dst, src);
        }
        cpa_commit();
    };

    issue(0);
    const int NT = D_ >> 4;
    for (int t = 0; t < NT; t++) {
        cpa_wait<0>();
        __syncthreads();
        if (t + 1 < NT) issue(t + 1);
        int sb = (t & 1) * 10240;
        PIPE_INNER(sm, sb, sb + 2048 + myseg * 2048, trow, tcol)
    }

#pragma unroll
    for (int ip = 0; ip < 4; ip++) {
        int ml0 = trow + 2 * ip;
        int e = s_e[ml0 >> 5];
        float sc0 = mp[(size_t)s_tok[ml0] * E_ + e];
        float sc1 = mp[(size_t)s_tok[ml0 + 1] * E_ + e];
#pragma unroll
        for (int j = 0; j < 8; j++) {
            float2 v = acc2[ip][j];
            float2 o = make_float2(sc0 * fmaxf(v.x, 0.f), sc1 * fmaxf(v.y, 0.f));
            *(float2*)&hidcT[(size_t)(n0 + tcol + j) * NSLOT + q * 128 + ml0] = o;
        }
    }
}

// ---------------- pipelined segmented fc2 ------------------------------------
__global__ void __launch_bounds__(256, 2)
fc2_pipe(const float* __restrict__ hidcT, const float* __restrict__ w2T,
         float* __restrict__ x, const int* __restrict__ slottok,
         const int* __restrict__ segp, const int* __restrict__ segcnt)
{
    extern __shared__ float sm[];
    const int q  = blockIdx.y;
    const int n0 = blockIdx.x << 7;
    const int tid = threadIdx.x;
    if (segcnt[q*4+0] + segcnt[q*4+1] + segcnt[q*4+2] + segcnt[q*4+3] == 0) return;

    __shared__ int s_e1[4], s_e2[4], s_cnt[4];
    __shared__ int s_tok[128];
    if (tid < 128) s_tok[tid] = slottok[q * 128 + tid];
    if (tid < 4) {
        int p = segp[q * 4 + tid];
        s_e1[tid] = c_pe1[p];
        s_e2[tid] = c_pe2[p];
        s_cnt[tid] = segcnt[q * 4 + tid];
    }
    __syncthreads();

    const int trow = (tid >> 4) << 3, tcol = (tid & 15) << 3;
    const int myseg = trow >> 5;

    GEMM_ACC_DECL

    auto issue = [&](int t) {
        int s = t & 1;
        int k0 = t << 4;
        int eb = (k0 >= DFF_);
        int kb = k0 - (eb ? DFF_ : 0);
#pragma unroll
        for (int c = tid; c < 2560; c += 256) {
            uint32_t dst; const float* src;
            if (c < 512) {
                int row = c >> 5, col = (c & 31) << 2;
                dst = smem_u32(&sm[s * 10240 + row * 128 + col]);
                src = hidcT + (size_t)(k0 + row) * NSLOT + q * 128 + col;
            } else {
                int bt = (c - 512) >> 9, cc = (c - 512) & 511;
                int row = cc >> 5, col = (cc & 31) << 2;
                int e = eb ? s_e2[bt] : s_e1[bt];
                dst = smem_u32(&sm[s * 10240 + 2048 + bt * 2048 + row * 128 + col]);
                src = w2T + ((size_t)e * DFF_ + kb + row) * D_ + n0 + col;
            }
            cpa16(dst, src);
        }
        cpa_commit();
    };

    issue(0);
    const int NT = D2FF >> 4;
    for (int t = 0; t < NT; t++) {
        cpa_wait<0>();
        __syncthreads();
        if (t + 1 < NT) issue(t + 1);
        int sb = (t & 1) * 10240;
        PIPE_INNER(sm, sb, sb + 2048 + myseg * 2048, trow, tcol)
    }

#pragma unroll
    for (int ip = 0; ip < 4; ip++) {
#pragma unroll
        for (int sub = 0; sub < 2; sub++) {
            int ml = trow + 2 * ip + sub;
            int seg = ml >> 5, offm = ml & 31;
            if (offm >= s_cnt[seg]) continue;
            int tok = s_tok[ml];
#pragma unroll
            for (int j = 0; j < 8; j++) {
                float v = sub ? acc2[ip][j].y : acc2[ip][j].x;
                x[(size_t)tok * D_ + n0 + tcol + j] += v;
            }
        }
    }
}

// ---------------- weight transpose: src[b][N][K] -> dst[b][K][N] -------------
__global__ void transpose_kernel(const float* __restrict__ src, float* __restrict__ dst,
                                 int N, int K)
{
    __shared__ float t[32][33];
    const float* s = src + (size_t)blockIdx.z * N * K;
    float* d = dst + (size_t)blockIdx.z * N * K;
    int k0 = blockIdx.x << 5, n0 = blockIdx.y << 5;
    int tx = threadIdx.x & 31, ty = threadIdx.x >> 5;
#pragma unroll
    for (int i = 0; i < 32; i += 8)
        t[ty + i][tx] = s[(size_t)(n0 + ty + i) * K + k0 + tx];
    __syncthreads();
#pragma unroll
    for (int i = 0; i < 32; i += 8)
        d[(size_t)(k0 + ty + i) * N + n0 + tx] = t[tx][ty + i];
}

// ---------------- Q/K transpose: qkv -> qkT[part][z][k][t] -------------------
__global__ void qk_transpose(const float* __restrict__ qkv, float* __restrict__ qkT)
{
    __shared__ float tl[32][33];
    int gz = blockIdx.z;                 // 0..47
    int part = gz / ZH_;                 // 0 = Q, 1 = K
    int z = gz - part * ZH_;
    int zb = z / H_, zh = z - zb * H_;
    int t0 = blockIdx.x << 5;
    int k0 = blockIdx.y << 5;
    int tx = threadIdx.x & 31, ty = threadIdx.x >> 5;
#pragma unroll
    for (int i = 0; i < 32; i += 8)
        tl[ty + i][tx] = qkv[((size_t)zb * T_ + t0 + ty + i) * D3_ + part * D_ + zh * HEAD_ + k0 + tx];
    __syncthreads();
    float* dst = qkT + ((size_t)gz * HEAD_ + k0) * T_ + t0;
#pragma unroll
    for (int i = 0; i < 32; i += 8)
        dst[(size_t)(ty + i) * T_ + tx] = tl[tx][ty + i];
}

// ---------------- gather hcT[k][slot] = h[slottok[slot]][k] ------------------
__global__ void gather_hcT_kernel(const float* __restrict__ h,
                                  const int* __restrict__ slottok,
                                  float* __restrict__ hcT)
{
    int slot = blockIdx.x * 8 + (threadIdx.x >> 5);
    int lane = threadIdx.x & 31;
    int tok = slottok[slot];
    const float* hr = h + (size_t)tok * D_;
    for (int k = lane; k < D_; k += 32)
        hcT[(size_t)k * NSLOT + slot] = hr[k];
}

// ================= tensor-core lm_head =================
#define LDSM4(R, addr) \
    asm volatile("ldmatrix.sync.aligned.m8n8.x4.shared.b16 {%0,%1,%2,%3}, [%4];" \
        : "=r"((R)[0]), "=r"((R)[1]), "=r"((R)[2]), "=r"((R)[3]) : "r"(addr))
__device__ __forceinline__ void mma16816(float* c, const uint32_t* a, uint32_t b0, uint32_t b1) {
    asm volatile("mma.sync.aligned.m16n8k16.row.col.f32.bf16.bf16.f32 "
                 "{%0,%1,%2,%3}, {%4,%5,%6,%7}, {%8,%9}, {%0,%1,%2,%3};"
                 : "+f"(c[0]), "+f"(c[1]), "+f"(c[2]), "+f"(c[3])
                 : "r"(a[0]), "r"(a[1]), "r"(a[2]), "r"(a[3]), "r"(b0), "r"(b1));
}
__device__ __forceinline__ void split3(float v, bf& h, bf& m, bf& l) {
    h = __float2bfloat16(v);
    float r = v - __bfloat162float(h);
    m = __float2bfloat16(r);
    l = __float2bfloat16(r - __bfloat162float(m));
}

constexpr int ROWB = 80;
constexpr int A_BYTES = 128 * ROWB;
constexpr int STAGE_BYTES = A_BYTES * 2;
constexpr int TNST = 3;
constexpr int TC_SMEM = TNST * STAGE_BYTES;

__global__ void __launch_bounds__(256)
tc_lmhead(const bf* __restrict__ Ah, const bf* __restrict__ Am, const bf* __restrict__ Al,
          const bf* __restrict__ Bh, const bf* __restrict__ Bm, const bf* __restrict__ Bl,
          float* __restrict__ Cf)
{
    extern __shared__ __align__(128) char smemc[];
    const uint32_t sbase = smem_u32(smemc);
    const int tid  = threadIdx.x;
    const int lane = tid & 31;
    const int wid  = tid >> 5;
    const int wm   = wid & 1;
    const int wn   = wid >> 1;
    const int m0 = blockIdx.y * 128;
    const int n0 = blockIdx.x * 128;

    constexpr int KC = D_ / 32;
    constexpr int C3 = 3 * KC;

    const int lr = tid >> 2;
    const int lq = (tid & 3) << 4;

    auto load_chunk = [&](int c, int s) {
        int p = c / KC;
        int kabs = (c - p * KC) << 5;
        const bf* Ap = Ah;
        const bf* Bp = Bh;
        if (p == 1) { Bp = Bm; }
        if (p == 2) { Ap = Am; }
        uint32_t sA = sbase + (uint32_t)s * STAGE_BYTES;
        uint32_t sB = sA + A_BYTES;
#pragma unroll
        for (int i = 0; i < 2; i++) {
            int r = lr + (i << 6);
            cpa16(sA + r * ROWB + lq, Ap + (size_t)(m0 + r) * D_ + kabs + (lq >> 1));
        }
#pragma unroll
        for (int i = 0; i < 2; i++) {
            int r = lr + (i << 6);
            cpa16(sB + r * ROWB + lq, Bp + (size_t)(n0 + r) * D_ + kabs + (lq >> 1));
        }
        cpa_commit();
    };

    float acc[4][4][4];
#pragma unroll
    for (int i = 0; i < 4; i++)
#pragma unroll
        for (int j = 0; j < 4; j++)
#pragma unroll
            for (int qq = 0; qq < 4; qq++) acc[i][j][qq] = 0.f;

    const int arow = (lane & 7) + ((lane >> 3) & 1) * 8;
    const int akh  = (lane >> 4) & 1;
    const int brow = (lane & 7) + ((lane >> 4) & 1) * 8;
    const int bkh  = (lane >> 3) & 1;

    load_chunk(0, 0);
    load_chunk(1, 1);

    for (int c = 0; c < C3; ++c) {
        int s = c % TNST;
        if (c + 1 < C3) cpa_wait<1>(); else cpa_wait<0>();
        __syncthreads();
        if (c + 2 < C3) load_chunk(c + 2, (c + 2) % TNST);

        uint32_t sA = sbase + (uint32_t)s * STAGE_BYTES;
        uint32_t sB = sA + A_BYTES;
        uint32_t aAddr = sA + (wm * 64 + arow) * ROWB + akh * 16;
        uint32_t bAddr = sB + (wn * 32 + brow) * ROWB + bkh * 16;

#pragma unroll
        for (int kc = 0; kc < 2; kc++) {
            uint32_t af[4][4], bfm[2][4];
#pragma unroll
            for (int ms = 0; ms < 4; ms++) LDSM4(af[ms], aAddr + ms * (16 * ROWB) + kc * 32);
#pragma unroll
            for (int np = 0; np < 2; np++) LDSM4(bfm[np], bAddr + np * (16 * ROWB) + kc * 32);
#pragma unroll
            for (int i = 0; i < 4; i++)
#pragma unroll
                for (int j = 0; j < 4; j++)
                    mma16816(acc[i][j], af[i], bfm[j >> 1][(j & 1) * 2], bfm[j >> 1][(j & 1) * 2 + 1]);
        }
    }

    const int tg  = lane >> 2;
    const int tc2 = (lane & 3) << 1;
#pragma unroll
    for (int i = 0; i < 4; i++) {
        int r0 = m0 + wm * 64 + i * 16 + tg;
        int r1 = r0 + 8;
#pragma unroll
        for (int j = 0; j < 4; j++) {
            int cb = n0 + wn * 32 + j * 8 + tc2;
            float* a4 = acc[i][j];
            *(float2*)(Cf + (size_t)r0 * V_ + cb) = make_float2(a4[0], a4[1]);
            *(float2*)(Cf + (size_t)r1 * V_ + cb) = make_float2(a4[2], a4[3]);
        }
    }
}

// ---------------- fp32 -> 3x bf16 planes ----------------
__global__ void cvt_split3(const float* __restrict__ x, bf* __restrict__ hi,
                           bf* __restrict__ mi, bf* __restrict__ lo, size_t n4)
{
    size_t i = (size_t)blockIdx.x * blockDim.x + threadIdx.x;
    size_t stride = (size_t)gridDim.x * blockDim.x;
    for (; i < n4; i += stride) {
        float4 v = ((const float4*)x)[i];
        bf h[4], m[4], l[4];
        split3(v.x, h[0], m[0], l[0]); split3(v.y, h[1], m[1], l[1]);
        split3(v.z, h[2], m[2], l[2]); split3(v.w, h[3], m[3], l[3]);
        ((__nv_bfloat162*)hi)[i * 2 + 0] = __halves2bfloat162(h[0], h[1]);
        ((__nv_bfloat162*)hi)[i * 2 + 1] = __halves2bfloat162(h[2], h[3]);
        ((__nv_bfloat162*)mi)[i * 2 + 0] = __halves2bfloat162(m[0], m[1]);
        ((__nv_bfloat162*)mi)[i * 2 + 1] = __halves2bfloat162(m[2], m[3]);
        ((__nv_bfloat162*)lo)[i * 2 + 0] = __halves2bfloat162(l[0], l[1]);
        ((__nv_bfloat162*)lo)[i * 2 + 1] = __halves2bfloat162(l[2], l[3]);
    }
}

// ---------------- embedding + LN0 ----------------
__global__ void embed_ln_kernel(const int* __restrict__ tokens,
                                const float* __restrict__ wte, const float* __restrict__ wpe,
                                const float* __restrict__ g, const float* __restrict__ b,
                                float* __restrict__ y)
{
    __shared__ float sred[8];
    long row = blockIdx.x;
    int t = (int)(row % T_);
    int tok = tokens[row];
    const float* we = wte + (long)tok * D_;
    const float* pe = wpe + (long)t * D_;
    float* yr = y + row * D_;
    int tid = threadIdx.x;
    float v[3], s = 0.f;
#pragma unroll
    for (int i = 0; i < 3; i++) { int c = tid + i * 256; v[i] = we[c] + pe[c]; s += v[i]; }
    s = bsum(s, sred);
    float mu = s * (1.f / D_);
    float q = 0.f;
#pragma unroll
    for (int i = 0; i < 3; i++) { float d = v[i] - mu; q += d * d; }
    q = bsum(q, sred);
    float rstd = rsqrtf(q * (1.f / D_) + 1e-5f);
#pragma unroll
    for (int i = 0; i < 3; i++) { int c = tid + i * 256; yr[c] = (v[i] - mu) * rstd * g[c] + b[c]; }
}

// ---------------- LayerNorm (+ optional transposed copy) ----------------
__global__ void ln_kernel(const float* __restrict__ x, float* __restrict__ y,
                          float* __restrict__ yT,
                          const float* __restrict__ g, const float* __restrict__ b)
{
    __shared__ float sred[8];
    long row = blockIdx.x;
    const float* xr = x + row * D_;
    int tid = threadIdx.x;
    float v[3], s = 0.f;
#pragma unroll
    for (int i = 0; i < 3; i++) { v[i] = xr[tid + i * 256]; s += v[i]; }
    s = bsum(s, sred);
    float mu = s * (1.f / D_);
    float q = 0.f;
#pragma unroll
    for (int i = 0; i < 3; i++) { float d = v[i] - mu; q += d * d; }
    q = bsum(q, sred);
    float rstd = rsqrtf(q * (1.f / D_) + 1e-5f);
#pragma unroll
    for (int i = 0; i < 3; i++) {
        int c = tid + i * 256;
        float o = (v[i] - mu) * rstd * g[c] + b[c];
        y[row * D_ + c] = o;
        if (yT) yT[(size_t)c * M_ + row] = o;
    }
}

// ---------------- causal softmax ----------------
__global__ void softmax_kernel(float* __restrict__ sc)
{
    __shared__ float sred[8];
    long row = blockIdx.x;
    int i = (int)(row & (T_ - 1));
    float* r = sc + row * (long)T_;
    int tid = threadIdx.x;
    int n = i + 1;
    float rv[4];
    float mx = -3.402823e38f;
#pragma unroll
    for (int p = 0; p < 4; p++) { int j = tid + p * 256; if (j < n) { rv[p] = r[j]; mx = fmaxf(mx, rv[p]); } }
    mx = bmax(mx, sred);
    float s = 0.f;
#pragma unroll
    for (int p = 0; p < 4; p++) { int j = tid + p * 256; if (j < n) { rv[p] = __expf(rv[p] - mx); s += rv[p]; } }
    s = bsum(s, sred);
    float inv = 1.f / s;
    int zend = ((i >> 7) + 1) << 7;
#pragma unroll
    for (int p = 0; p < 4; p++) {
        int j = tid + p * 256;
        if (j < n) r[j] = rv[p] * inv;
        else if (j < zend) r[j] = 0.f;
    }
}

// ---------------- router + binning ----------------
__global__ void zero_cnt_kernel(int* cnt) { if (threadIdx.x < NPAIR) cnt[threadIdx.x] = 0; }

__global__ void router_kernel(const float* __restrict__ h, const float* __restrict__ rw,
                              float* __restrict__ mp, int* __restrict__ pairid,
                              int* __restrict__ cnt)
{
    __shared__ float sc[E_];
    long tok = blockIdx.x;
    int tid = threadIdx.x;
    int w = tid >> 5, lane = tid & 31;
    const float* hr = h + tok * D_;
    const float* we = rw + (long)w * D_;
    float s = 0.f;
    for (int k = lane; k < D_; k += 32) s += hr[k] * we[k];
#pragma unroll
    for (int o = 16; o; o >>= 1) s += __shfl_xor_sync(0xffffffffu, s, o);
    if (lane == 0) sc[w] = s;
    __syncthreads();
    if (tid == 0) {
        float mx = sc[0];
#pragma unroll
        for (int e = 1; e < E_; e++) mx = fmaxf(mx, sc[e]);
        float p[E_], sum = 0.f;
#pragma unroll
        for (int e = 0; e < E_; e++) { p[e] = __expf(sc[e] - mx); sum += p[e]; }
        int i1 = 0;
#pragma unroll
        for (int e = 1; e < E_; e++) if (sc[e] > sc[i1]) i1 = e;
        int i2 = -1;
#pragma unroll
        for (int e = 0; e < E_; e++) if (e != i1 && (i2 < 0 || sc[e] > sc[i2])) i2 = e;
        float p1 = p[i1] / sum, p2 = p[i2] / sum;
        float inv = 1.f / (p1 + p2 + 1e-8f);
#pragma unroll
        for (int e = 0; e < E_; e++) mp[tok * E_ + e] = 0.f;
        mp[tok * E_ + i1] = p1 * inv;
        mp[tok * E_ + i2] = p2 * inv;
        int a = i1 < i2 ? i1 : i2;
        int bx = i1 < i2 ? i2 : i1;
        int pid = a * E_ - a * (a + 1) / 2 + (bx - a - 1);
        pairid[tok] = pid;
        atomicAdd(&cnt[pid], 1);
    }
}

__global__ void prefix_kernel(const int* __restrict__ cnt, int* __restrict__ baseo,
                              int* __restrict__ pos, int* __restrict__ segp,
                              int* __restrict__ segrow, int* __restrict__ segcnt)
{
    if (threadIdx.x == 0) {
        int s = 0;
        for (int p = 0; p < NPAIR; p++) { baseo[p] = s; pos[p] = s; s += cnt[p]; }
        int ns = 0;
        for (int p = 0; p < NPAIR; p++) {
            int c = cnt[p];
            for (int o = 0; o < c; o += 32) {
                segp[ns] = p; segrow[ns] = baseo[p] + o;
                segcnt[ns] = (c - o < 32) ? (c - o) : 32;
                ns++;
            }
        }
        for (; ns < NSEG; ns++) { segp[ns] = 0; segrow[ns] = 0; segcnt[ns] = 0; }
    }
}

__global__ void scatter_kernel(const int* __restrict__ pairid, int* __restrict__ pos,
                               int* __restrict__ idxv)
{
    int t = blockIdx.x * 256 + threadIdx.x;
    if (t < M_) {
        int p = pairid[t];
        int slot = atomicAdd(&pos[p], 1);
        idxv[slot] = t;
    }
}

__global__ void slotmap_kernel(const int* __restrict__ segrow, const int* __restrict__ segcnt,
                               const int* __restrict__ idxv, int* __restrict__ slottok)
{
    int slot = blockIdx.x * 256 + threadIdx.x;
    if (slot >= NSLOT) return;
    int s = slot >> 5, o = slot & 31, c = segcnt[s];
    int oo = (o < c) ? o : (c > 0 ? c - 1 : 0);
    slottok[slot] = (c > 0) ? idxv[segrow[s] + oo] : 0;
}

// ---------------- host side ----------------
template <class T>
static T* sym(const void* s) { void* p = nullptr; cudaGetSymbolAddress(&p, s); return (T*)p; }

extern "C" void kernel_launch(void* const* d_in, const int* in_sizes, int n_in,
                              void* d_out, int out_size)
{
    const int*   tokens  = (const int*)d_in[0];
    const float* wte     = (const float*)d_in[1];
    const float* wpe     = (const float*)d_in[2];
    const float* n0g     = (const float*)d_in[3];
    const float* n0b     = (const float*)d_in[4];
    const float* n1g     = (const float*)d_in[5];
    const float* n1b     = (const float*)d_in[6];
    const float* n2g     = (const float*)d_in[7];
    const float* n2b     = (const float*)d_in[8];
    const float* qkvw    = (const float*)d_in[9];
    const float* projw   = (const float*)d_in[10];
    const float* routerw = (const float*)d_in[11];
    const float* fc1     = (const float*)d_in[12];
    const float* fc2     = (const float*)d_in[13];
    const float* lmw     = (const float*)d_in[14];
    float* out = (float*)d_out;

    float* x     = sym<float>(g_x);
    float* h     = sym<float>(g_h);
    float* hT    = sym<float>(g_hT);
    float* atT   = sym<float>(g_atT);
    float* qkv   = sym<float>(g_qkv);
    float* qkT   = sym<float>(g_qkT);
    float* scs   = sym<float>(g_scores);
    float* hcT   = sym<float>(g_hcT);
    float* hidcT = sym<float>(g_hidcT);
    float* mp    = sym<float>(g_mp);
    int* cnt    = sym<int>(g_cnt);
    int* baseo  = sym<int>(g_baseo);
    int* pos    = sym<int>(g_pos);
    int* pairid = sym<int>(g_pairid);
    int* idxv   = sym<int>(g_idx);
    int* segp   = sym<int>(g_segp);
    int* segrow = sym<int>(g_segrow);
    int* segcnt = sym<int>(g_segcnt);
    int* slottok = sym<int>(g_slottok);
    float* qkvT = sym<float>(w_qkvT);
    float* prT  = sym<float>(w_prT);
    float* f1T  = sym<float>(w_f1T);
    float* f2T  = sym<float>(w_f2T);
    bf* xp_h = sym<bf>(g_xp_h); bf* xp_m = sym<bf>(g_xp_m); bf* xp_l = sym<bf>(g_xp_l);
    bf* lm_h = sym<bf>(w_lm_h); bf* lm_m = sym<bf>(w_lm_m); bf* lm_l = sym<bf>(w_lm_l);

    cudaFuncSetAttribute(gemm_pipe<0>, cudaFuncAttributeMaxDynamicSharedMemorySize, 49152);
    cudaFuncSetAttribute(gemm_pipe<2>, cudaFuncAttributeMaxDynamicSharedMemorySize, 49152);
    cudaFuncSetAttribute(scores_pipe, cudaFuncAttributeMaxDynamicSharedMemorySize, 49152);
    cudaFuncSetAttribute(fc1_pipe, cudaFuncAttributeMaxDynamicSharedMemorySize, 81920);
    cudaFuncSetAttribute(fc2_pipe, cudaFuncAttributeMaxDynamicSharedMemorySize, 81920);
    cudaFuncSetAttribute(tc_lmhead, cudaFuncAttributeMaxDynamicSharedMemorySize, TC_SMEM);

    // ---- once-per-launch weight prep ----
    transpose_kernel<<<dim3(D_ / 32, D3_ / 32, L_), 256>>>(qkvw, qkvT, D3_, D_);
    transpose_kernel<<<dim3(D_ / 32, D_ / 32, L_), 256>>>(projw, prT, D_, D_);
    transpose_kernel<<<dim3(D_ / 32, DFF_ / 32, L_ * E_), 256>>>(fc1, f1T, DFF_, D_);
    transpose_kernel<<<dim3(DFF_ / 32, D_ / 32, L_ * E_), 256>>>(fc2, f2T, D_, DFF_);
    cvt_split3<<<2048, 256>>>(lmw, lm_h, lm_m, lm_l, (size_t)V_ * D_ / 4);

    embed_ln_kernel<<<M_, 256>>>(tokens, wte, wpe, n0g, n0b, x);

    for (int l = 0; l < L_; l++) {
        ln_kernel<<<M_, 256>>>(x, h, hT, n1g + l * D_, n1b + l * D_);
        // QKV (pipelined)
        gemm_pipe<0><<<dim3(D3_ / 128, M_ / 128), 256, 49152>>>(
            hT, qkvT + (size_t)l * D_ * D3_, qkv, M_, D3_, D_, M_, D3_, D3_);
        // Q/K transpose -> qkT
        qk_transpose<<<dim3(T_ / 32, HEAD_ / 32, 2 * ZH_), 256>>>(qkv, qkT);
        // scores (pipelined, causal skip)
        scores_pipe<<<dim3(T_ / 128, T_ / 128, ZH_), 256, 49152>>>(qkT, scs);
        softmax_kernel<<<ZH_ * T_, 256>>>(scs);
        // PV (64x64 tiles, causal K-truncation) -> atT
        pv_tile<<<dim3(1, T_ / 64, ZH_), 128>>>(scs, qkv, atT);
        // x += attn @ proj^T (pipelined)
        gemm_pipe<2><<<dim3(D_ / 128, M_ / 128), 256, 49152>>>(
            atT, prT + (size_t)l * D_ * D_, x, M_, D_, D_, M_, D_, D_);
        // LN2 (row-major only)
        ln_kernel<<<M_, 256>>>(x, h, nullptr, n2g + l * D_, n2b + l * D_);
        // router + binning + slot build + gather
        zero_cnt_kernel<<<1, 32>>>(cnt);
        router_kernel<<<M_, 256>>>(h, routerw + (long)l * E_ * D_, mp, pairid, cnt);
        prefix_kernel<<<1, 32>>>(cnt, baseo, pos, segp, segrow, segcnt);
        scatter_kernel<<<M_ / 256, 256>>>(pairid, pos, idxv);
        slotmap_kernel<<<NSLOT / 256, 256>>>(segrow, segcnt, idxv, slottok);
        gather_hcT_kernel<<<NSLOT / 8, 256>>>(h, slottok, hcT);
        // fc1 (pipelined, quantum-32)
        fc1_pipe<<<dim3(D2FF / 128, NSEG / 4), 256, 81920>>>(
            hcT, f1T + (size_t)l * E_ * D_ * DFF_, hidcT, mp, slottok, segp, segcnt);
        // fc2 (pipelined)
        fc2_pipe<<<dim3(D_ / 128, NSEG / 4), 256, 81920>>>(
            hidcT, f2T + (size_t)l * E_ * DFF_ * D_, x, slottok, segp, segcnt);
    }
    // lm_head (tensor cores, 3-pass)
    cvt_split3<<<512, 256>>>(x, xp_h, xp_m, xp_l, (size_t)M_ * D_ / 4);
    tc_lmhead<<<dim3(V_ / 128, M_ / 128), 256, TC_SMEM>>>(
        xp_h, xp_m, xp_l, lm_h, lm_m, lm_l, out);
}

// round 15
// speedup vs baseline: 8.2298x; 1.0591x over previous
#include <cuda_runtime.h>
#include <cuda_bf16.h>
#include <math.h>
#include <stdint.h>

typedef __nv_bfloat16 bf;

// ---------------- problem constants ----------------
constexpr int B_ = 2, T_ = 1024, D_ = 768, H_ = 12, L_ = 4, E_ = 8, DFF_ = 3072, V_ = 32000;
constexpr int HEAD_ = D_ / H_;       // 64
constexpr int D3_ = 3 * D_;          // 2304
constexpr int M_ = B_ * T_;          // 2048
constexpr int NPAIR = 28;
constexpr int D2FF = 2 * DFF_;       // 6144
constexpr int NSEG = 96;
constexpr int NSLOT = NSEG * 32;     // 3072
constexpr int ZH_ = B_ * H_;         // 24

// ---------------- scratch (static device, allocation-free) ----------------
__device__ __align__(128) float g_x[M_ * D_];
__device__ __align__(128) float g_h[M_ * D_];
__device__ __align__(128) float g_hT[D_ * M_];
__device__ __align__(128) float g_atT[D_ * M_];
__device__ __align__(128) float g_qkv[M_ * D3_];
__device__ __align__(128) float g_qkT[(size_t)2 * ZH_ * HEAD_ * T_];
__device__ __align__(128) float g_scores[(size_t)ZH_ * T_ * T_];
__device__ __align__(128) float g_hcT[(size_t)D_ * NSLOT];
__device__ __align__(128) float g_hidcT[(size_t)D2FF * NSLOT];
__device__ __align__(128) float g_mp[M_ * E_];
__device__ int g_cnt[NPAIR], g_baseo[NPAIR], g_pos[NPAIR];
__device__ int g_pairid[M_], g_idx[M_];
__device__ int g_segp[NSEG], g_segrow[NSEG], g_segcnt[NSEG], g_slottok[NSLOT];

// transposed weights ([K][N] per layer/expert) — layers 0..2 only for fc
__device__ __align__(128) float w_qkvT[(size_t)L_ * D_ * D3_];
__device__ __align__(128) float w_prT[(size_t)L_ * D_ * D_];
__device__ __align__(128) float w_f1T[(size_t)L_ * E_ * D_ * DFF_];
__device__ __align__(128) float w_f2T[(size_t)L_ * E_ * DFF_ * D_];

// bf16 planes for tensor-core lm_head
__device__ __align__(128) bf g_xp_h[M_ * D_], g_xp_m[M_ * D_], g_xp_l[M_ * D_];
__device__ __align__(128) bf w_lm_h[(size_t)V_ * D_], w_lm_m[(size_t)V_ * D_], w_lm_l[(size_t)V_ * D_];

// bf16 planes for layer-3 tensor-core MoE (router-safe)
__device__ __align__(128) bf g_hc2_h[(size_t)NSLOT * D_],  g_hc2_m[(size_t)NSLOT * D_];
__device__ __align__(128) bf g_hid2_h[(size_t)NSLOT * D2FF], g_hid2_m[(size_t)NSLOT * D2FF];
__device__ __align__(128) bf w_f1b_h[(size_t)E_ * DFF_ * D_], w_f1b_m[(size_t)E_ * DFF_ * D_];
__device__ __align__(128) bf w_f2b_h[(size_t)E_ * D_ * DFF_], w_f2b_m[(size_t)E_ * D_ * DFF_];

__constant__ int c_pe1[NPAIR] = {0,0,0,0,0,0,0, 1,1,1,1,1,1, 2,2,2,2,2, 3,3,3,3, 4,4,4, 5,5, 6};
__constant__ int c_pe2[NPAIR] = {1,2,3,4,5,6,7, 2,3,4,5,6,7, 3,4,5,6,7, 4,5,6,7, 5,6,7, 6,7, 7};

// ---------------- packed f32x2 FMA (bit-exact lanes) ----------------
__device__ __forceinline__ float2 ffma2(float2 a, float2 b, float2 c) {
    unsigned long long au, bu, cu, du;
    au = *reinterpret_cast<unsigned long long*>(&a);
    bu = *reinterpret_cast<unsigned long long*>(&b);
    cu = *reinterpret_cast<unsigned long long*>(&c);
    asm("fma.rn.f32x2 %0, %1, %2, %3;" : "=l"(du) : "l"(au), "l"(bu), "l"(cu));
    return *reinterpret_cast<float2*>(&du);
}

// ---------------- PTX helpers ----------------
__device__ __forceinline__ uint32_t smem_u32(const void* p) {
    uint32_t a;
    asm("{ .reg .u64 t; cvta.to.shared.u64 t, %1; cvt.u32.u64 %0, t; }" : "=r"(a) : "l"(p));
    return a;
}
__device__ __forceinline__ void cpa16(uint32_t dst, const void* src) {
    asm volatile("cp.async.cg.shared.global [%0], [%1], 16;" :: "r"(dst), "l"(src) : "memory");
}
__device__ __forceinline__ void cpa_commit() { asm volatile("cp.async.commit_group;" ::: "memory"); }
template <int N> __device__ __forceinline__ void cpa_wait() {
    asm volatile("cp.async.wait_group %0;" :: "n"(N) : "memory");
}

// ---------------- reductions ----------------
__device__ __forceinline__ float bsum(float v, float* sred) {
#pragma unroll
    for (int o = 16; o; o >>= 1) v += __shfl_xor_sync(0xffffffffu, v, o);
    if ((threadIdx.x & 31) == 0) sred[threadIdx.x >> 5] = v;
    __syncthreads();
    float r = 0.f;
#pragma unroll
    for (int i = 0; i < 8; i++) r += sred[i];
    __syncthreads();
    return r;
}
__device__ __forceinline__ float bmax(float v, float* sred) {
#pragma unroll
    for (int o = 16; o; o >>= 1) v = fmaxf(v, __shfl_xor_sync(0xffffffffu, v, o));
    if ((threadIdx.x & 31) == 0) sred[threadIdx.x >> 5] = v;
    __syncthreads();
    float r = -3.402823e38f;
#pragma unroll
    for (int i = 0; i < 8; i++) r = fmaxf(r, sred[i]);
    __syncthreads();
    return r;
}

// ---------------- FFMA2 accumulator + inner bodies ----------------
#define GEMM_ACC_DECL                                   \
    float2 acc2[4][8];                                  \
    _Pragma("unroll")                                   \
    for (int ip = 0; ip < 4; ip++)                      \
        _Pragma("unroll")                               \
        for (int j = 0; j < 8; j++) acc2[ip][j] = make_float2(0.f, 0.f);

#define PIPE_INNER(sm, aOff, bOff, trow, tcol)                                 \
    _Pragma("unroll")                                                          \
    for (int kk = 0; kk < 16; kk++) {                                          \
        float2 a2[4];                                                          \
        _Pragma("unroll")                                                      \
        for (int ip = 0; ip < 4; ip++)                                         \
            a2[ip] = *(const float2*)&sm[(aOff) + kk * 128 + (trow) + 2 * ip]; \
        float4 b0 = *(const float4*)&sm[(bOff) + kk * 128 + (tcol)];           \
        float4 b1 = *(const float4*)&sm[(bOff) + kk * 128 + (tcol) + 4];       \
        float bsv[8] = {b0.x, b0.y, b0.z, b0.w, b1.x, b1.y, b1.z, b1.w};       \
        _Pragma("unroll")                                                      \
        for (int j = 0; j < 8; j++) {                                          \
            float2 bd = make_float2(bsv[j], bsv[j]);                           \
            _Pragma("unroll")                                                  \
            for (int ip = 0; ip < 4; ip++)                                     \
                acc2[ip][j] = ffma2(a2[ip], bd, acc2[ip][j]);                  \
        }                                                                      \
    }

// ---------------- pipelined dense GEMM (fp32, bit-exact) ----------------
template <int MODE>
__global__ void __launch_bounds__(256, 2)
gemm_pipe(const float* __restrict__ AT, const float* __restrict__ BT,
          float* __restrict__ C, int M, int N, int K, int ldat, int ldbt, int ldc)
{
    extern __shared__ float sm[];
    const int tid = threadIdx.x;
    const int m0 = blockIdx.y << 7, n0 = blockIdx.x << 7;
    const int NT = K >> 4;
    const int trow = (tid >> 4) << 3, tcol = (tid & 15) << 3;
    const bool isA = tid < 128;
    const int lrow = (tid & 127) >> 3;
    const int c0 = (tid & 7) << 2;

    GEMM_ACC_DECL

    auto issue = [&](int t) {
        int s = t % 3;
        uint32_t base = smem_u32(&sm[s * 4096 + (isA ? 0 : 2048) + lrow * 128]);
        const float* src = isA ? (AT + (size_t)(t * 16 + lrow) * ldat + m0)
                               : (BT + (size_t)(t * 16 + lrow) * ldbt + n0);
#pragma unroll
        for (int i = 0; i < 4; i++) {
            int col = c0 + i * 32;
            cpa16(base + col * 4, src + col);
        }
        cpa_commit();
    };

    issue(0); issue(1);
    for (int t = 0; t < NT; t++) {
        if (t + 1 < NT) cpa_wait<1>(); else cpa_wait<0>();
        __syncthreads();
        if (t + 2 < NT) issue(t + 2);
        int sb = (t % 3) * 4096;
        PIPE_INNER(sm, sb, sb + 2048, trow, tcol)
    }

#pragma unroll
    for (int ip = 0; ip < 4; ip++) {
#pragma unroll
        for (int sub = 0; sub < 2; sub++) {
            int m = m0 + trow + 2 * ip + sub;
#pragma unroll
            for (int j = 0; j < 8; j++) {
                int n = n0 + tcol + j;
                long ci = (long)m * ldc + n;
                float v = sub ? acc2[ip][j].y : acc2[ip][j].x;
                if (MODE == 0) C[ci] = v;
                else           C[ci] += v;
            }
        }
    }
}

// ---------------- pipelined attention scores: scs = 0.125 * Q K^T ------------
__global__ void __launch_bounds__(256, 2)
scores_pipe(const float* __restrict__ qkT, float* __restrict__ scs)
{
    extern __shared__ float sm[];
    const int z = blockIdx.z;
    const int m0 = blockIdx.y << 7, n0 = blockIdx.x << 7;
    if (n0 > m0) return;
    const float* AT = qkT + (size_t)z * HEAD_ * T_;
    const float* BT = qkT + (size_t)(ZH_ + z) * HEAD_ * T_;
    float* C = scs + (size_t)z * T_ * T_;

    const int tid = threadIdx.x;
    const int trow = (tid >> 4) << 3, tcol = (tid & 15) << 3;
    const bool isA = tid < 128;
    const int lrow = (tid & 127) >> 3;
    const int c0 = (tid & 7) << 2;

    GEMM_ACC_DECL

    auto issue = [&](int t) {
        int s = t % 3;
        uint32_t base = smem_u32(&sm[s * 4096 + (isA ? 0 : 2048) + lrow * 128]);
        const float* src = isA ? (AT + (size_t)(t * 16 + lrow) * T_ + m0)
                               : (BT + (size_t)(t * 16 + lrow) * T_ + n0);
#pragma unroll
        for (int i = 0; i < 4; i++) {
            int col = c0 + i * 32;
            cpa16(base + col * 4, src + col);
        }
        cpa_commit();
    };

    constexpr int NT = HEAD_ / 16;
    issue(0); issue(1);
    for (int t = 0; t < NT; t++) {
        if (t + 1 < NT) cpa_wait<1>(); else cpa_wait<0>();
        __syncthreads();
        if (t + 2 < NT) issue(t + 2);
        int sb = (t % 3) * 4096;
        PIPE_INNER(sm, sb, sb + 2048, trow, tcol)
    }

#pragma unroll
    for (int ip = 0; ip < 4; ip++) {
#pragma unroll
        for (int sub = 0; sub < 2; sub++) {
            int m = m0 + trow + 2 * ip + sub;
#pragma unroll
            for (int j = 0; j < 8; j++) {
                int n = n0 + tcol + j;
                float v = sub ? acc2[ip][j].y : acc2[ip][j].x;
                C[(size_t)m * T_ + n] = 0.125f * v;
            }
        }
    }
}

// ---------------- PV: 64x64 tiles ----------------
__global__ void __launch_bounds__(128, 4)
pv_tile(const float* __restrict__ scs, const float* __restrict__ qkv,
        float* __restrict__ atT)
{
    const int z = blockIdx.z, zb = z / H_, zh = z - zb * H_;
    const int m0 = blockIdx.y << 6;
    const float* A = scs + (size_t)z * T_ * T_;
    const float* Bv = qkv + ((size_t)zb * T_) * D3_ + 2 * D_ + zh * HEAD_;
    float* C = atT + (size_t)zh * HEAD_ * M_ + (size_t)zb * T_;
    const int kend = m0 + 64;

    __shared__ float As[16][64];
    __shared__ float Bs[16][64];
    const int tid = threadIdx.x;
    const int trow = (tid >> 3) << 2;
    const int tcol = (tid & 7) << 3;

    float2 acc2[2][8];
#pragma unroll
    for (int ip = 0; ip < 2; ip++)
#pragma unroll
        for (int j = 0; j < 8; j++) acc2[ip][j] = make_float2(0.f, 0.f);

    for (int k0 = 0; k0 < kend; k0 += 16) {
#pragma unroll
        for (int it = 0; it < 2; it++) {
            int idx = tid + it * 128;
            int r = idx >> 2, c4 = (idx & 3) << 2;
            float4 v = *(const float4*)(A + (size_t)(m0 + r) * T_ + k0 + c4);
            As[c4 + 0][r] = v.x; As[c4 + 1][r] = v.y;
            As[c4 + 2][r] = v.z; As[c4 + 3][r] = v.w;
        }
#pragma unroll
        for (int it = 0; it < 2; it++) {
            int idx = tid + it * 128;
            int r = idx >> 4, c4 = (idx & 15) << 2;
            float4 v = *(const float4*)(Bv + (size_t)(k0 + r) * D3_ + c4);
            *(float4*)&Bs[r][c4] = v;
        }
        __syncthreads();
#pragma unroll
        for (int kk = 0; kk < 16; kk++) {
            float2 a2[2];
            a2[0] = *(const float2*)&As[kk][trow];
            a2[1] = *(const float2*)&As[kk][trow + 2];
            float4 b0 = *(const float4*)&Bs[kk][tcol];
            float4 b1 = *(const float4*)&Bs[kk][tcol + 4];
            float bsv[8] = {b0.x, b0.y, b0.z, b0.w, b1.x, b1.y, b1.z, b1.w};
#pragma unroll
            for (int j = 0; j < 8; j++) {
                float2 bd = make_float2(bsv[j], bsv[j]);
#pragma unroll
                for (int ip = 0; ip < 2; ip++)
                    acc2[ip][j] = ffma2(a2[ip], bd, acc2[ip][j]);
            }
        }
        __syncthreads();
    }

#pragma unroll
    for (int ip = 0; ip < 2; ip++) {
#pragma unroll
        for (int sub = 0; sub < 2; sub++) {
            int m = m0 + trow + 2 * ip + sub;
#pragma unroll
            for (int j = 0; j < 8; j++) {
                int n = tcol + j;
                float v = sub ? acc2[ip][j].y : acc2[ip][j].x;
                C[(size_t)n * M_ + m] = v;
            }
        }
    }
}

// ---------------- pipelined segmented fc1 (layers 0..2) ----------------
__global__ void __launch_bounds__(256, 2)
fc1_pipe(const float* __restrict__ hcT, const float* __restrict__ w1T,
         float* __restrict__ hidcT, const float* __restrict__ mp,
         const int* __restrict__ slottok, const int* __restrict__ segp,
         const int* __restrict__ segcnt)
{
    extern __shared__ float sm[];
    const int q  = blockIdx.y;
    const int n0 = blockIdx.x << 7;
    const int tid = threadIdx.x;
    if (segcnt[q*4+0] + segcnt[q*4+1] + segcnt[q*4+2] + segcnt[q*4+3] == 0) return;

    __shared__ int s_e[4];
    __shared__ int s_tok[128];
    if (tid < 128) s_tok[tid] = slottok[q * 128 + tid];
    if (tid < 4) {
        int p = segp[q * 4 + tid];
        s_e[tid] = (n0 < DFF_) ? c_pe1[p] : c_pe2[p];
    }
    __syncthreads();

    const int nw = (n0 < DFF_) ? n0 : n0 - DFF_;
    const int trow = (tid >> 4) << 3, tcol = (tid & 15) << 3;
    const int myseg = trow >> 5;

    GEMM_ACC_DECL

    auto issue = [&](int t) {
        int s = t & 1;
        int k0 = t << 4;
#pragma unroll
        for (int c = tid; c < 2560; c += 256) {
            uint32_t dst; const float* src;
            if (c < 512) {
                int row = c >> 5, col = (c & 31) << 2;
                dst = smem_u32(&sm[s * 10240 + row * 128 + col]);
                src = hcT + (size_t)(k0 + row) * NSLOT + q * 128 + col;
            } else {
                int bt = (c - 512) >> 9, cc = (c - 512) & 511;
                int row = cc >> 5, col = (cc & 31) << 2;
                dst = smem_u32(&sm[s * 10240 + 2048 + bt * 2048 + row * 128 + col]);
                src = w1T + ((size_t)s_e[bt] * D_ + k0 + row) * DFF_ + nw + col;
            }
            cpa16(dst, src);
        }
        cpa_commit();
    };

    issue(0);
    const int NT = D_ >> 4;
    for (int t = 0; t < NT; t++) {
        cpa_wait<0>();
        __syncthreads();
        if (t + 1 < NT) issue(t + 1);
        int sb = (t & 1) * 10240;
        PIPE_INNER(sm, sb, sb + 2048 + myseg * 2048, trow, tcol)
    }

#pragma unroll
    for (int ip = 0; ip < 4; ip++) {
        int ml0 = trow + 2 * ip;
        int e = s_e[ml0 >> 5];
        float sc0 = mp[(size_t)s_tok[ml0] * E_ + e];
        float sc1 = mp[(size_t)s_tok[ml0 + 1] * E_ + e];
#pragma unroll
        for (int j = 0; j < 8; j++) {
            float2 v = acc2[ip][j];
            float2 o = make_float2(sc0 * fmaxf(v.x, 0.f), sc1 * fmaxf(v.y, 0.f));
            *(float2*)&hidcT[(size_t)(n0 + tcol + j) * NSLOT + q * 128 + ml0] = o;
        }
    }
}

// ---------------- pipelined segmented fc2 (layers 0..2) ----------------
__global__ void __launch_bounds__(256, 2)
fc2_pipe(const float* __restrict__ hidcT, const float* __restrict__ w2T,
         float* __restrict__ x, const int* __restrict__ slottok,
         const int* __restrict__ segp, const int* __restrict__ segcnt)
{
    extern __shared__ float sm[];
    const int q  = blockIdx.y;
    const int n0 = blockIdx.x << 7;
    const int tid = threadIdx.x;
    if (segcnt[q*4+0] + segcnt[q*4+1] + segcnt[q*4+2] + segcnt[q*4+3] == 0) return;

    __shared__ int s_e1[4], s_e2[4], s_cnt[4];
    __shared__ int s_tok[128];
    if (tid < 128) s_tok[tid] = slottok[q * 128 + tid];
    if (tid < 4) {
        int p = segp[q * 4 + tid];
        s_e1[tid] = c_pe1[p];
        s_e2[tid] = c_pe2[p];
        s_cnt[tid] = segcnt[q * 4 + tid];
    }
    __syncthreads();

    const int trow = (tid >> 4) << 3, tcol = (tid & 15) << 3;
    const int myseg = trow >> 5;

    GEMM_ACC_DECL

    auto issue = [&](int t) {
        int s = t & 1;
        int k0 = t << 4;
        int eb = (k0 >= DFF_);
        int kb = k0 - (eb ? DFF_ : 0);
#pragma unroll
        for (int c = tid; c < 2560; c += 256) {
            uint32_t dst; const float* src;
            if (c < 512) {
                int row = c >> 5, col = (c & 31) << 2;
                dst = smem_u32(&sm[s * 10240 + row * 128 + col]);
                src = hidcT + (size_t)(k0 + row) * NSLOT + q * 128 + col;
            } else {
                int bt = (c - 512) >> 9, cc = (c - 512) & 511;
                int row = cc >> 5, col = (cc & 31) << 2;
                int e = eb ? s_e2[bt] : s_e1[bt];
                dst = smem_u32(&sm[s * 10240 + 2048 + bt * 2048 + row * 128 + col]);
                src = w2T + ((size_t)e * DFF_ + kb + row) * D_ + n0 + col;
            }
            cpa16(dst, src);
        }
        cpa_commit();
    };

    issue(0);
    const int NT = D2FF >> 4;
    for (int t = 0; t < NT; t++) {
        cpa_wait<0>();
        __syncthreads();
        if (t + 1 < NT) issue(t + 1);
        int sb = (t & 1) * 10240;
        PIPE_INNER(sm, sb, sb + 2048 + myseg * 2048, trow, tcol)
    }

#pragma unroll
    for (int ip = 0; ip < 4; ip++) {
#pragma unroll
        for (int sub = 0; sub < 2; sub++) {
            int ml = trow + 2 * ip + sub;
            int seg = ml >> 5, offm = ml & 31;
            if (offm >= s_cnt[seg]) continue;
            int tok = s_tok[ml];
#pragma unroll
            for (int j = 0; j < 8; j++) {
                float v = sub ? acc2[ip][j].y : acc2[ip][j].x;
                x[(size_t)tok * D_ + n0 + tcol + j] += v;
            }
        }
    }
}

// ---------------- weight transpose: src[b][N][K] -> dst[b][K][N] -------------
__global__ void transpose_kernel(const float* __restrict__ src, float* __restrict__ dst,
                                 int N, int K)
{
    __shared__ float t[32][33];
    const float* s = src + (size_t)blockIdx.z * N * K;
    float* d = dst + (size_t)blockIdx.z * N * K;
    int k0 = blockIdx.x << 5, n0 = blockIdx.y << 5;
    int tx = threadIdx.x & 31, ty = threadIdx.x >> 5;
#pragma unroll
    for (int i = 0; i < 32; i += 8)
        t[ty + i][tx] = s[(size_t)(n0 + ty + i) * K + k0 + tx];
    __syncthreads();
#pragma unroll
    for (int i = 0; i < 32; i += 8)
        d[(size_t)(k0 + ty + i) * N + n0 + tx] = t[tx][ty + i];
}

// ---------------- Q/K transpose ----------------
__global__ void qk_transpose(const float* __restrict__ qkv, float* __restrict__ qkT)
{
    __shared__ float tl[32][33];
    int gz = blockIdx.z;
    int part = gz / ZH_;
    int z = gz - part * ZH_;
    int zb = z / H_, zh = z - zb * H_;
    int t0 = blockIdx.x << 5;
    int k0 = blockIdx.y << 5;
    int tx = threadIdx.x & 31, ty = threadIdx.x >> 5;
#pragma unroll
    for (int i = 0; i < 32; i += 8)
        tl[ty + i][tx] = qkv[((size_t)zb * T_ + t0 + ty + i) * D3_ + part * D_ + zh * HEAD_ + k0 + tx];
    __syncthreads();
    float* dst = qkT + ((size_t)gz * HEAD_ + k0) * T_ + t0;
#pragma unroll
    for (int i = 0; i < 32; i += 8)
        dst[(size_t)(ty + i) * T_ + tx] = tl[tx][ty + i];
}

// ---------------- gather hcT[k][slot] (layers 0..2) ----------------
__global__ void gather_hcT_kernel(const float* __restrict__ h,
                                  const int* __restrict__ slottok,
                                  float* __restrict__ hcT)
{
    int slot = blockIdx.x * 8 + (threadIdx.x >> 5);
    int lane = threadIdx.x & 31;
    int tok = slottok[slot];
    const float* hr = h + (size_t)tok * D_;
    for (int k = lane; k < D_; k += 32)
        hcT[(size_t)k * NSLOT + slot] = hr[k];
}

// ---------------- gather hc bf16 planes (layer 3) ----------------
__global__ void gather_hc_bf(const float* __restrict__ h,
                             const int* __restrict__ slottok,
                             bf* __restrict__ hh, bf* __restrict__ hm)
{
    int slot = blockIdx.x * 8 + (threadIdx.x >> 5);
    int lane = threadIdx.x & 31;
    int tok = slottok[slot];
    const float* hr = h + (size_t)tok * D_;
    for (int k = lane; k < D_; k += 32) {
        float v = hr[k];
        bf hi = __float2bfloat16(v);
        hh[(size_t)slot * D_ + k] = hi;
        hm[(size_t)slot * D_ + k] = __float2bfloat16(v - __bfloat162float(hi));
    }
}

// ================= tensor-core helpers =================
#define LDSM4(R, addr) \
    asm volatile("ldmatrix.sync.aligned.m8n8.x4.shared.b16 {%0,%1,%2,%3}, [%4];" \
        : "=r"((R)[0]), "=r"((R)[1]), "=r"((R)[2]), "=r"((R)[3]) : "r"(addr))
__device__ __forceinline__ void mma16816(float* c, const uint32_t* a, uint32_t b0, uint32_t b1) {
    asm volatile("mma.sync.aligned.m16n8k16.row.col.f32.bf16.bf16.f32 "
                 "{%0,%1,%2,%3}, {%4,%5,%6,%7}, {%8,%9}, {%0,%1,%2,%3};"
                 : "+f"(c[0]), "+f"(c[1]), "+f"(c[2]), "+f"(c[3])
                 : "r"(a[0]), "r"(a[1]), "r"(a[2]), "r"(a[3]), "r"(b0), "r"(b1));
}
__device__ __forceinline__ void split3(float v, bf& h, bf& m, bf& l) {
    h = __float2bfloat16(v);
    float r = v - __bfloat162float(h);
    m = __float2bfloat16(r);
    l = __float2bfloat16(r - __bfloat162float(m));
}

// ---------------- tensor-core segmented fc (layer 3 only; router-safe) -------
// M=32 (one quantum-32 segment), N=128, 3-pass bf16 (hh + hm + mh).
// ISFC1: A=hc planes (K=768), B=w1 planes [E][DFF][D]; out = split2(mp*relu(acc)) -> hid planes
// else : A=hid planes (K=6144), B=w2 planes [E][D][DFF]; out: x[tok] += acc (guarded)
constexpr int FC_STAGE = 32 * 80 + 128 * 80;   // 12800
template <int ISFC1>
__global__ void __launch_bounds__(128)
tc_fc(const bf* __restrict__ Ah, const bf* __restrict__ Am,
      const bf* __restrict__ Bh, const bf* __restrict__ Bm,
      float* __restrict__ x, bf* __restrict__ Oh, bf* __restrict__ Om,
      const float* __restrict__ mp,
      const int* __restrict__ slottok, const int* __restrict__ segp,
      const int* __restrict__ segcnt)
{
    extern __shared__ __align__(128) char smemc[];
    const uint32_t sbase = smem_u32(smemc);
    const int seg = blockIdx.y;
    const int cnt = segcnt[seg];
    if (cnt == 0) return;
    const int n0 = blockIdx.x << 7;
    const int p = segp[seg];
    const int tid = threadIdx.x, lane = tid & 31, w = tid >> 5;

    const int e1 = c_pe1[p], e2 = c_pe2[p];
    const int eF = (n0 < DFF_) ? e1 : e2;          // FC1 expert
    const int nw = (n0 < DFF_) ? n0 : n0 - DFF_;   // FC1 col base within expert
    constexpr int KA = ISFC1 ? D_ : D2FF;
    constexpr int KC = KA / 32;                    // chunks per pass
    constexpr int C3 = 3 * KC;

    const int lr = tid >> 2;          // 0..31
    const int lq = (tid & 3) << 4;    // byte quarter

    auto load_chunk = [&](int c, int s) {
        int pp = c / KC;
        int kabs = (c - pp * KC) << 5;
        const bf* Ap = (pp == 2) ? Am : Ah;
        const bf* Bp = (pp == 1) ? Bm : Bh;
        uint32_t sA = sbase + (uint32_t)s * FC_STAGE;
        uint32_t sB = sA + 32 * 80;
        // A: 32 rows x 64B
        cpa16(sA + lr * 80 + lq, Ap + (size_t)(seg * 32 + lr) * KA + kabs + (lq >> 1));
        // B: 128 rows x 64B (4 per thread)
        if (ISFC1) {
            const bf* Bb = Bp + ((size_t)eF * DFF_ + nw) * D_ + kabs;
#pragma unroll
            for (int i = 0; i < 4; i++) {
                int r = lr + (i << 5);
                cpa16(sB + r * 80 + lq, Bb + (size_t)r * D_ + (lq >> 1));
            }
        } else {
            int eb = (kabs >= DFF_);
            int kk = kabs - (eb ? DFF_ : 0);
            int e = eb ? e2 : e1;
            const bf* Bb = Bp + ((size_t)e * D_ + n0) * DFF_ + kk;
#pragma unroll
            for (int i = 0; i < 4; i++) {
                int r = lr + (i << 5);
                cpa16(sB + r * 80 + lq, Bb + (size_t)r * DFF_ + (lq >> 1));
            }
        }
        cpa_commit();
    };

    float acc[2][4][4];
#pragma unroll
    for (int i = 0; i < 2; i++)
#pragma unroll
        for (int j = 0; j < 4; j++)
#pragma unroll
            for (int qq = 0; qq < 4; qq++) acc[i][j][qq] = 0.f;

    const int arow = (lane & 7) + ((lane >> 3) & 1) * 8;
    const int akh  = (lane >> 4) & 1;
    const int brow = (lane & 7) + ((lane >> 4) & 1) * 8;
    const int bkh  = (lane >> 3) & 1;

    load_chunk(0, 0);
    load_chunk(1, 1);

    for (int c = 0; c < C3; ++c) {
        int s = c % 3;
        if (c + 1 < C3) cpa_wait<1>(); else cpa_wait<0>();
        __syncthreads();
        if (c + 2 < C3) load_chunk(c + 2, (c + 2) % 3);

        uint32_t sA = sbase + (uint32_t)s * FC_STAGE;
        uint32_t sB = sA + 32 * 80;
        uint32_t aAddr = sA + arow * 80 + akh * 16;
        uint32_t bAddr = sB + (w * 32 + brow) * 80 + bkh * 16;

#pragma unroll
        for (int kc = 0; kc < 2; kc++) {
            uint32_t af[2][4], bfm[2][4];
#pragma unroll
            for (int ms = 0; ms < 2; ms++) LDSM4(af[ms], aAddr + ms * (16 * 80) + kc * 32);
#pragma unroll
            for (int np = 0; np < 2; np++) LDSM4(bfm[np], bAddr + np * (16 * 80) + kc * 32);
#pragma unroll
            for (int i = 0; i < 2; i++)
#pragma unroll
                for (int j = 0; j < 4; j++)
                    mma16816(acc[i][j], af[i], bfm[j >> 1][(j & 1) * 2], bfm[j >> 1][(j & 1) * 2 + 1]);
        }
    }

    const int tg  = lane >> 2;
    const int tc2 = (lane & 3) << 1;
#pragma unroll
    for (int i = 0; i < 2; i++) {
        int rl0 = i * 16 + tg, rl1 = rl0 + 8;
        int slot0 = seg * 32 + rl0, slot1 = seg * 32 + rl1;
        if (ISFC1) {
            float sc0 = mp[(size_t)slottok[slot0] * E_ + eF];
            float sc1 = mp[(size_t)slottok[slot1] * E_ + eF];
#pragma unroll
            for (int j = 0; j < 4; j++) {
                int col = n0 + w * 32 + j * 8 + tc2;
                float v0 = fmaxf(acc[i][j][0], 0.f) * sc0;
                float v1 = fmaxf(acc[i][j][1], 0.f) * sc0;
                float v2 = fmaxf(acc[i][j][2], 0.f) * sc1;
                float v3 = fmaxf(acc[i][j][3], 0.f) * sc1;
                bf h0 = __float2bfloat16(v0), h1 = __float2bfloat16(v1);
                bf h2 = __float2bfloat16(v2), h3 = __float2bfloat16(v3);
                *(__nv_bfloat162*)(Oh + (size_t)slot0 * D2FF + col) = __halves2bfloat162(h0, h1);
                *(__nv_bfloat162*)(Oh + (size_t)slot1 * D2FF + col) = __halves2bfloat162(h2, h3);
                *(__nv_bfloat162*)(Om + (size_t)slot0 * D2FF + col) = __halves2bfloat162(
                    __float2bfloat16(v0 - __bfloat162float(h0)), __float2bfloat16(v1 - __bfloat162float(h1)));
                *(__nv_bfloat162*)(Om + (size_t)slot1 * D2FF + col) = __halves2bfloat162(
                    __float2bfloat16(v2 - __bfloat162float(h2)), __float2bfloat16(v3 - __bfloat162float(h3)));
            }
        } else {
            int t0 = slottok[slot0], t1 = slottok[slot1];
            bool ok0 = rl0 < cnt, ok1 = rl1 < cnt;
#pragma unroll
            for (int j = 0; j < 4; j++) {
                int col = n0 + w * 32 + j * 8 + tc2;
                if (ok0) {
                    float2* px = (float2*)(x + (size_t)t0 * D_ + col);
                    float2 o = *px; o.x += acc[i][j][0]; o.y += acc[i][j][1]; *px = o;
                }
                if (ok1) {
                    float2* px = (float2*)(x + (size_t)t1 * D_ + col);
                    float2 o = *px; o.x += acc[i][j][2]; o.y += acc[i][j][3]; *px = o;
                }
            }
        }
    }
}

// ================= tensor-core lm_head =================
constexpr int ROWB = 80;
constexpr int A_BYTES = 128 * ROWB;
constexpr int STAGE_BYTES = A_BYTES * 2;
constexpr int TNST = 3;
constexpr int TC_SMEM = TNST * STAGE_BYTES;

__global__ void __launch_bounds__(256)
tc_lmhead(const bf* __restrict__ Ah, const bf* __restrict__ Am, const bf* __restrict__ Al,
          const bf* __restrict__ Bh, const bf* __restrict__ Bm, const bf* __restrict__ Bl,
          float* __restrict__ Cf)
{
    extern __shared__ __align__(128) char smemc[];
    const uint32_t sbase = smem_u32(smemc);
    const int tid  = threadIdx.x;
    const int lane = tid & 31;
    const int wid  = tid >> 5;
    const int wm   = wid & 1;
    const int wn   = wid >> 1;
    const int m0 = blockIdx.y * 128;
    const int n0 = blockIdx.x * 128;

    constexpr int KC = D_ / 32;
    constexpr int C3 = 3 * KC;

    const int lr = tid >> 2;
    const int lq = (tid & 3) << 4;

    auto load_chunk = [&](int c, int s) {
        int p = c / KC;
        int kabs = (c - p * KC) << 5;
        const bf* Ap = Ah;
        const bf* Bp = Bh;
        if (p == 1) { Bp = Bm; }
        if (p == 2) { Ap = Am; }
        uint32_t sA = sbase + (uint32_t)s * STAGE_BYTES;
        uint32_t sB = sA + A_BYTES;
#pragma unroll
        for (int i = 0; i < 2; i++) {
            int r = lr + (i << 6);
            cpa16(sA + r * ROWB + lq, Ap + (size_t)(m0 + r) * D_ + kabs + (lq >> 1));
        }
#pragma unroll
        for (int i = 0; i < 2; i++) {
            int r = lr + (i << 6);
            cpa16(sB + r * ROWB + lq, Bp + (size_t)(n0 + r) * D_ + kabs + (lq >> 1));
        }
        cpa_commit();
    };

    float acc[4][4][4];
#pragma unroll
    for (int i = 0; i < 4; i++)
#pragma unroll
        for (int j = 0; j < 4; j++)
#pragma unroll
            for (int qq = 0; qq < 4; qq++) acc[i][j][qq] = 0.f;

    const int arow = (lane & 7) + ((lane >> 3) & 1) * 8;
    const int akh  = (lane >> 4) & 1;
    const int brow = (lane & 7) + ((lane >> 4) & 1) * 8;
    const int bkh  = (lane >> 3) & 1;

    load_chunk(0, 0);
    load_chunk(1, 1);

    for (int c = 0; c < C3; ++c) {
        int s = c % TNST;
        if (c + 1 < C3) cpa_wait<1>(); else cpa_wait<0>();
        __syncthreads();
        if (c + 2 < C3) load_chunk(c + 2, (c + 2) % TNST);

        uint32_t sA = sbase + (uint32_t)s * STAGE_BYTES;
        uint32_t sB = sA + A_BYTES;
        uint32_t aAddr = sA + (wm * 64 + arow) * ROWB + akh * 16;
        uint32_t bAddr = sB + (wn * 32 + brow) * ROWB + bkh * 16;

#pragma unroll
        for (int kc = 0; kc < 2; kc++) {
            uint32_t af[4][4], bfm[2][4];
#pragma unroll
            for (int ms = 0; ms < 4; ms++) LDSM4(af[ms], aAddr + ms * (16 * ROWB) + kc * 32);
#pragma unroll
            for (int np = 0; np < 2; np++) LDSM4(bfm[np], bAddr + np * (16 * ROWB) + kc * 32);
#pragma unroll
            for (int i = 0; i < 4; i++)
#pragma unroll
                for (int j = 0; j < 4; j++)
                    mma16816(acc[i][j], af[i], bfm[j >> 1][(j & 1) * 2], bfm[j >> 1][(j & 1) * 2 + 1]);
        }
    }

    const int tg  = lane >> 2;
    const int tc2 = (lane & 3) << 1;
#pragma unroll
    for (int i = 0; i < 4; i++) {
        int r0 = m0 + wm * 64 + i * 16 + tg;
        int r1 = r0 + 8;
#pragma unroll
        for (int j = 0; j < 4; j++) {
            int cb = n0 + wn * 32 + j * 8 + tc2;
            float* a4 = acc[i][j];
            *(float2*)(Cf + (size_t)r0 * V_ + cb) = make_float2(a4[0], a4[1]);
            *(float2*)(Cf + (size_t)r1 * V_ + cb) = make_float2(a4[2], a4[3]);
        }
    }
}

// ---------------- fp32 -> bf16 plane converters ----------------
__global__ void cvt_split3(const float* __restrict__ x, bf* __restrict__ hi,
                           bf* __restrict__ mi, bf* __restrict__ lo, size_t n4)
{
    size_t i = (size_t)blockIdx.x * blockDim.x + threadIdx.x;
    size_t stride = (size_t)gridDim.x * blockDim.x;
    for (; i < n4; i += stride) {
        float4 v = ((const float4*)x)[i];
        bf h[4], m[4], l[4];
        split3(v.x, h[0], m[0], l[0]); split3(v.y, h[1], m[1], l[1]);
        split3(v.z, h[2], m[2], l[2]); split3(v.w, h[3], m[3], l[3]);
        ((__nv_bfloat162*)hi)[i * 2 + 0] = __halves2bfloat162(h[0], h[1]);
        ((__nv_bfloat162*)hi)[i * 2 + 1] = __halves2bfloat162(h[2], h[3]);
        ((__nv_bfloat162*)mi)[i * 2 + 0] = __halves2bfloat162(m[0], m[1]);
        ((__nv_bfloat162*)mi)[i * 2 + 1] = __halves2bfloat162(m[2], m[3]);
        ((__nv_bfloat162*)lo)[i * 2 + 0] = __halves2bfloat162(l[0], l[1]);
        ((__nv_bfloat162*)lo)[i * 2 + 1] = __halves2bfloat162(l[2], l[3]);
    }
}

__global__ void cvt_split2(const float* __restrict__ x, bf* __restrict__ hi,
                           bf* __restrict__ mi, size_t n4)
{
    size_t i = (size_t)blockIdx.x * blockDim.x + threadIdx.x;
    size_t stride = (size_t)gridDim.x * blockDim.x;
    for (; i < n4; i += stride) {
        float4 v = ((const float4*)x)[i];
        bf h[4], m[4];
#pragma unroll
        for (int q = 0; q < 4; q++) {
            float vv = (&v.x)[q];
            h[q] = __float2bfloat16(vv);
            m[q] = __float2bfloat16(vv - __bfloat162float(h[q]));
        }
        ((__nv_bfloat162*)hi)[i * 2 + 0] = __halves2bfloat162(h[0], h[1]);
        ((__nv_bfloat162*)hi)[i * 2 + 1] = __halves2bfloat162(h[2], h[3]);
        ((__nv_bfloat162*)mi)[i * 2 + 0] = __halves2bfloat162(m[0], m[1]);
        ((__nv_bfloat162*)mi)[i * 2 + 1] = __halves2bfloat162(m[2], m[3]);
    }
}

// ---------------- embedding + LN0 ----------------
__global__ void embed_ln_kernel(const int* __restrict__ tokens,
                                const float* __restrict__ wte, const float* __restrict__ wpe,
                                const float* __restrict__ g, const float* __restrict__ b,
                                float* __restrict__ y)
{
    __shared__ float sred[8];
    long row = blockIdx.x;
    int t = (int)(row % T_);
    int tok = tokens[row];
    const float* we = wte + (long)tok * D_;
    const float* pe = wpe + (long)t * D_;
    float* yr = y + row * D_;
    int tid = threadIdx.x;
    float v[3], s = 0.f;
#pragma unroll
    for (int i = 0; i < 3; i++) { int c = tid + i * 256; v[i] = we[c] + pe[c]; s += v[i]; }
    s = bsum(s, sred);
    float mu = s * (1.f / D_);
    float q = 0.f;
#pragma unroll
    for (int i = 0; i < 3; i++) { float d = v[i] - mu; q += d * d; }
    q = bsum(q, sred);
    float rstd = rsqrtf(q * (1.f / D_) + 1e-5f);
#pragma unroll
    for (int i = 0; i < 3; i++) { int c = tid + i * 256; yr[c] = (v[i] - mu) * rstd * g[c] + b[c]; }
}

// ---------------- LayerNorm (+ optional transposed copy) ----------------
__global__ void ln_kernel(const float* __restrict__ x, float* __restrict__ y,
                          float* __restrict__ yT,
                          const float* __restrict__ g, const float* __restrict__ b)
{
    __shared__ float sred[8];
    long row = blockIdx.x;
    const float* xr = x + row * D_;
    int tid = threadIdx.x;
    float v[3], s = 0.f;
#pragma unroll
    for (int i = 0; i < 3; i++) { v[i] = xr[tid + i * 256]; s += v[i]; }
    s = bsum(s, sred);
    float mu = s * (1.f / D_);
    float q = 0.f;
#pragma unroll
    for (int i = 0; i < 3; i++) { float d = v[i] - mu; q += d * d; }
    q = bsum(q, sred);
    float rstd = rsqrtf(q * (1.f / D_) + 1e-5f);
#pragma unroll
    for (int i = 0; i < 3; i++) {
        int c = tid + i * 256;
        float o = (v[i] - mu) * rstd * g[c] + b[c];
        y[row * D_ + c] = o;
        if (yT) yT[(size_t)c * M_ + row] = o;
    }
}

// ---------------- causal softmax ----------------
__global__ void softmax_kernel(float* __restrict__ sc)
{
    __shared__ float sred[8];
    long row = blockIdx.x;
    int i = (int)(row & (T_ - 1));
    float* r = sc + row * (long)T_;
    int tid = threadIdx.x;
    int n = i + 1;
    float rv[4];
    float mx = -3.402823e38f;
#pragma unroll
    for (int p = 0; p < 4; p++) { int j = tid + p * 256; if (j < n) { rv[p] = r[j]; mx = fmaxf(mx, rv[p]); } }
    mx = bmax(mx, sred);
    float s = 0.f;
#pragma unroll
    for (int p = 0; p < 4; p++) { int j = tid + p * 256; if (j < n) { rv[p] = __expf(rv[p] - mx); s += rv[p]; } }
    s = bsum(s, sred);
    float inv = 1.f / s;
    int zend = ((i >> 6) + 1) << 6;
#pragma unroll
    for (int p = 0; p < 4; p++) {
        int j = tid + p * 256;
        if (j < n) r[j] = rv[p] * inv;
        else if (j < zend) r[j] = 0.f;
    }
}

// ---------------- router + binning ----------------
__global__ void zero_cnt_kernel(int* cnt) { if (threadIdx.x < NPAIR) cnt[threadIdx.x] = 0; }

__global__ void router_kernel(const float* __restrict__ h, const float* __restrict__ rw,
                              float* __restrict__ mp, int* __restrict__ pairid,
                              int* __restrict__ cnt)
{
    __shared__ float sc[E_];
    long tok = blockIdx.x;
    int tid = threadIdx.x;
    int w = tid >> 5, lane = tid & 31;
    const float* hr = h + tok * D_;
    const float* we = rw + (long)w * D_;
    float s = 0.f;
    for (int k = lane; k < D_; k += 32) s += hr[k] * we[k];
#pragma unroll
    for (int o = 16; o; o >>= 1) s += __shfl_xor_sync(0xffffffffu, s, o);
    if (lane == 0) sc[w] = s;
    __syncthreads();
    if (tid == 0) {
        float mx = sc[0];
#pragma unroll
        for (int e = 1; e < E_; e++) mx = fmaxf(mx, sc[e]);
        float p[E_], sum = 0.f;
#pragma unroll
        for (int e = 0; e < E_; e++) { p[e] = __expf(sc[e] - mx); sum += p[e]; }
        int i1 = 0;
#pragma unroll
        for (int e = 1; e < E_; e++) if (sc[e] > sc[i1]) i1 = e;
        int i2 = -1;
#pragma unroll
        for (int e = 0; e < E_; e++) if (e != i1 && (i2 < 0 || sc[e] > sc[i2])) i2 = e;
        float p1 = p[i1] / sum, p2 = p[i2] / sum;
        float inv = 1.f / (p1 + p2 + 1e-8f);
#pragma unroll
        for (int e = 0; e < E_; e++) mp[tok * E_ + e] = 0.f;
        mp[tok * E_ + i1] = p1 * inv;
        mp[tok * E_ + i2] = p2 * inv;
        int a = i1 < i2 ? i1 : i2;
        int bx = i1 < i2 ? i2 : i1;
        int pid = a * E_ - a * (a + 1) / 2 + (bx - a - 1);
        pairid[tok] = pid;
        atomicAdd(&cnt[pid], 1);
    }
}

__global__ void prefix_kernel(const int* __restrict__ cnt, int* __restrict__ baseo,
                              int* __restrict__ pos, int* __restrict__ segp,
                              int* __restrict__ segrow, int* __restrict__ segcnt)
{
    if (threadIdx.x == 0) {
        int s = 0;
        for (int p = 0; p < NPAIR; p++) { baseo[p] = s; pos[p] = s; s += cnt[p]; }
        int ns = 0;
        for (int p = 0; p < NPAIR; p++) {
            int c = cnt[p];
            for (int o = 0; o < c; o += 32) {
                segp[ns] = p; segrow[ns] = baseo[p] + o;
                segcnt[ns] = (c - o < 32) ? (c - o) : 32;
                ns++;
            }
        }
        for (; ns < NSEG; ns++) { segp[ns] = 0; segrow[ns] = 0; segcnt[ns] = 0; }
    }
}

__global__ void scatter_kernel(const int* __restrict__ pairid, int* __restrict__ pos,
                               int* __restrict__ idxv)
{
    int t = blockIdx.x * 256 + threadIdx.x;
    if (t < M_) {
        int p = pairid[t];
        int slot = atomicAdd(&pos[p], 1);
        idxv[slot] = t;
    }
}

__global__ void slotmap_kernel(const int* __restrict__ segrow, const int* __restrict__ segcnt,
                               const int* __restrict__ idxv, int* __restrict__ slottok)
{
    int slot = blockIdx.x * 256 + threadIdx.x;
    if (slot >= NSLOT) return;
    int s = slot >> 5, o = slot & 31, c = segcnt[s];
    int oo = (o < c) ? o : (c > 0 ? c - 1 : 0);
    slottok[slot] = (c > 0) ? idxv[segrow[s] + oo] : 0;
}

// ---------------- host side ----------------
template <class T>
static T* sym(const void* s) { void* p = nullptr; cudaGetSymbolAddress(&p, s); return (T*)p; }

extern "C" void kernel_launch(void* const* d_in, const int* in_sizes, int n_in,
                              void* d_out, int out_size)
{
    const int*   tokens  = (const int*)d_in[0];
    const float* wte     = (const float*)d_in[1];
    const float* wpe     = (const float*)d_in[2];
    const float* n0g     = (const float*)d_in[3];
    const float* n0b     = (const float*)d_in[4];
    const float* n1g     = (const float*)d_in[5];
    const float* n1b     = (const float*)d_in[6];
    const float* n2g     = (const float*)d_in[7];
    const float* n2b     = (const float*)d_in[8];
    const float* qkvw    = (const float*)d_in[9];
    const float* projw   = (const float*)d_in[10];
    const float* routerw = (const float*)d_in[11];
    const float* fc1     = (const float*)d_in[12];
    const float* fc2     = (const float*)d_in[13];
    const float* lmw     = (const float*)d_in[14];
    float* out = (float*)d_out;

    float* x     = sym<float>(g_x);
    float* h     = sym<float>(g_h);
    float* hT    = sym<float>(g_hT);
    float* atT   = sym<float>(g_atT);
    float* qkv   = sym<float>(g_qkv);
    float* qkT   = sym<float>(g_qkT);
    float* scs   = sym<float>(g_scores);
    float* hcT   = sym<float>(g_hcT);
    float* hidcT = sym<float>(g_hidcT);
    float* mp    = sym<float>(g_mp);
    int* cnt    = sym<int>(g_cnt);
    int* baseo  = sym<int>(g_baseo);
    int* pos    = sym<int>(g_pos);
    int* pairid = sym<int>(g_pairid);
    int* idxv   = sym<int>(g_idx);
    int* segp   = sym<int>(g_segp);
    int* segrow = sym<int>(g_segrow);
    int* segcnt = sym<int>(g_segcnt);
    int* slottok = sym<int>(g_slottok);
    float* qkvT = sym<float>(w_qkvT);
    float* prT  = sym<float>(w_prT);
    float* f1T  = sym<float>(w_f1T);
    float* f2T  = sym<float>(w_f2T);
    bf* xp_h = sym<bf>(g_xp_h); bf* xp_m = sym<bf>(g_xp_m); bf* xp_l = sym<bf>(g_xp_l);
    bf* lm_h = sym<bf>(w_lm_h); bf* lm_m = sym<bf>(w_lm_m); bf* lm_l = sym<bf>(w_lm_l);
    bf* hc2h = sym<bf>(g_hc2_h); bf* hc2m = sym<bf>(g_hc2_m);
    bf* hd2h = sym<bf>(g_hid2_h); bf* hd2m = sym<bf>(g_hid2_m);
    bf* f1bh = sym<bf>(w_f1b_h); bf* f1bm = sym<bf>(w_f1b_m);
    bf* f2bh = sym<bf>(w_f2b_h); bf* f2bm = sym<bf>(w_f2b_m);

    cudaFuncSetAttribute(gemm_pipe<0>, cudaFuncAttributeMaxDynamicSharedMemorySize, 49152);
    cudaFuncSetAttribute(gemm_pipe<2>, cudaFuncAttributeMaxDynamicSharedMemorySize, 49152);
    cudaFuncSetAttribute(scores_pipe, cudaFuncAttributeMaxDynamicSharedMemorySize, 49152);
    cudaFuncSetAttribute(fc1_pipe, cudaFuncAttributeMaxDynamicSharedMemorySize, 81920);
    cudaFuncSetAttribute(fc2_pipe, cudaFuncAttributeMaxDynamicSharedMemorySize, 81920);
    cudaFuncSetAttribute(tc_lmhead, cudaFuncAttributeMaxDynamicSharedMemorySize, TC_SMEM);
    cudaFuncSetAttribute(tc_fc<1>, cudaFuncAttributeMaxDynamicSharedMemorySize, 3 * FC_STAGE);
    cudaFuncSetAttribute(tc_fc<0>, cudaFuncAttributeMaxDynamicSharedMemorySize, 3 * FC_STAGE);

    // ---- once-per-launch weight prep ----
    transpose_kernel<<<dim3(D_ / 32, D3_ / 32, L_), 256>>>(qkvw, qkvT, D3_, D_);
    transpose_kernel<<<dim3(D_ / 32, D_ / 32, L_), 256>>>(projw, prT, D_, D_);
    transpose_kernel<<<dim3(D_ / 32, DFF_ / 32, (L_ - 1) * E_), 256>>>(fc1, f1T, DFF_, D_);
    transpose_kernel<<<dim3(DFF_ / 32, D_ / 32, (L_ - 1) * E_), 256>>>(fc2, f2T, D_, DFF_);
    cvt_split3<<<2048, 256>>>(lmw, lm_h, lm_m, lm_l, (size_t)V_ * D_ / 4);
    cvt_split2<<<4096, 256>>>(fc1 + (size_t)3 * E_ * DFF_ * D_, f1bh, f1bm, (size_t)E_ * DFF_ * D_ / 4);
    cvt_split2<<<4096, 256>>>(fc2 + (size_t)3 * E_ * D_ * DFF_, f2bh, f2bm, (size_t)E_ * D_ * DFF_ / 4);

    embed_ln_kernel<<<M_, 256>>>(tokens, wte, wpe, n0g, n0b, x);

    for (int l = 0; l < L_; l++) {
        ln_kernel<<<M_, 256>>>(x, h, hT, n1g + l * D_, n1b + l * D_);
        gemm_pipe<0><<<dim3(D3_ / 128, M_ / 128), 256, 49152>>>(
            hT, qkvT + (size_t)l * D_ * D3_, qkv, M_, D3_, D_, M_, D3_, D3_);
        qk_transpose<<<dim3(T_ / 32, HEAD_ / 32, 2 * ZH_), 256>>>(qkv, qkT);
        scores_pipe<<<dim3(T_ / 128, T_ / 128, ZH_), 256, 49152>>>(qkT, scs);
        softmax_kernel<<<ZH_ * T_, 256>>>(scs);
        pv_tile<<<dim3(1, T_ / 64, ZH_), 128>>>(scs, qkv, atT);
        gemm_pipe<2><<<dim3(D_ / 128, M_ / 128), 256, 49152>>>(
            atT, prT + (size_t)l * D_ * D_, x, M_, D_, D_, M_, D_, D_);
        ln_kernel<<<M_, 256>>>(x, h, nullptr, n2g + l * D_, n2b + l * D_);
        zero_cnt_kernel<<<1, 32>>>(cnt);
        router_kernel<<<M_, 256>>>(h, routerw + (long)l * E_ * D_, mp, pairid, cnt);
        prefix_kernel<<<1, 32>>>(cnt, baseo, pos, segp, segrow, segcnt);
        scatter_kernel<<<M_ / 256, 256>>>(pairid, pos, idxv);
        slotmap_kernel<<<NSLOT / 256, 256>>>(segrow, segcnt, idxv, slottok);
        if (l < L_ - 1) {
            // bit-exact SIMT MoE (upstream of later routers)
            gather_hcT_kernel<<<NSLOT / 8, 256>>>(h, slottok, hcT);
            fc1_pipe<<<dim3(D2FF / 128, NSEG / 4), 256, 81920>>>(
                hcT, f1T + (size_t)l * E_ * D_ * DFF_, hidcT, mp, slottok, segp, segcnt);
            fc2_pipe<<<dim3(D_ / 128, NSEG / 4), 256, 81920>>>(
                hidcT, f2T + (size_t)l * E_ * DFF_ * D_, x, slottok, segp, segcnt);
        } else {
            // layer-3 MoE: router-safe -> tensor cores (3-pass bf16)
            gather_hc_bf<<<NSLOT / 8, 256>>>(h, slottok, hc2h, hc2m);
            tc_fc<1><<<dim3(D2FF / 128, NSEG), 128, 3 * FC_STAGE>>>(
                hc2h, hc2m, f1bh, f1bm, nullptr, hd2h, hd2m, mp, slottok, segp, segcnt);
            tc_fc<0><<<dim3(D_ / 128, NSEG), 128, 3 * FC_STAGE>>>(
                hd2h, hd2m, f2bh, f2bm, x, nullptr, nullptr, nullptr, slottok, segp, segcnt);
        }
    }
    // lm_head (tensor cores, 3-pass)
    cvt_split3<<<512, 256>>>(x, xp_h, xp_m, xp_l, (size_t)M_ * D_ / 4);
    tc_lmhead<<<dim3(V_ / 128, M_ / 128), 256, TC_SMEM>>>(
        xp_h, xp_m, xp_l, lm_h, lm_m, lm_l, out);
}